// round 8
// baseline (speedup 1.0000x reference)
#include <cuda_runtime.h>
#include <cuda_fp16.h>
#include <cstdint>

// Fused GAT network on mma.sync.m16n8k16 (A fp16 hi/lo, B fp16, fp32 accum).
// 4 graphs per 256-thread block: M = 64, N = 256, K = FIN. 2 blocks/SM.

#define NN 16
#define WSTR 264          // whbuf stride (floats)
#define ASTRB 528         // A row stride bytes (264 halves)
#define BSTRB 144         // B chunk row stride bytes (72 halves)

// ---- shared memory byte offsets ----
#define OFF_AH    0            // fp16 hi A tile 64 x 264 (33792 B)
#define OFF_AL    33792        // fp16 lo A tile
#define OFF_WHB   0            // fp32 whbuf 64 x 264 overlays A (67584 B)
#define OFF_B     67584        // fp16 B chunk 256 x 72 (36864 B)
#define OFF_XS    67584        // x staging (4096 B) overlays B pre-layer0
#define OFF_ALPHA 67584        // 16384 B overlays B after GEMM
#define OFF_ES    83968        // 1024 B
#define OFF_ED    84992        // 1024 B
#define OFF_G4    104448       // 4096 B
#define OFF_G     108544       // 1024 B
#define OFF_Y     109568       // 2112 B
#define OFF_RED   111680       // 128 B
#define SMEM_BYTES 111808

// transposed fp16 weights WT[n][k]: W0 16384, W1 65536, W2 65536 elems
__device__ __align__(16) __half g_WTh[147456];

typedef unsigned long long ull;

__device__ __forceinline__ uint32_t smem_u32(const void* p) {
    uint32_t a;
    asm("{ .reg .u64 t; cvta.to.shared.u64 t, %1; cvt.u32.u64 %0, t; }" : "=r"(a) : "l"(p));
    return a;
}

#define LDSM4(r, a) \
    asm volatile("ldmatrix.sync.aligned.m8n8.x4.shared.b16 {%0,%1,%2,%3}, [%4];" \
        : "=r"((r)[0]), "=r"((r)[1]), "=r"((r)[2]), "=r"((r)[3]) : "r"(a))

#define MMA16816(d, a, b0, b1) \
    asm volatile("mma.sync.aligned.m16n8k16.row.col.f32.f16.f16.f32 " \
        "{%0,%1,%2,%3}, {%4,%5,%6,%7}, {%8,%9}, {%0,%1,%2,%3};" \
        : "+f"((d)[0]), "+f"((d)[1]), "+f"((d)[2]), "+f"((d)[3]) \
        : "r"((a)[0]), "r"((a)[1]), "r"((a)[2]), "r"((a)[3]), "r"(b0), "r"(b1))

__device__ __forceinline__ ull pk(float lo, float hi) {
    ull r; asm("mov.b64 %0, {%1,%2};" : "=l"(r) : "f"(lo), "f"(hi)); return r;
}
__device__ __forceinline__ void upk(ull v, float& lo, float& hi) {
    asm("mov.b64 {%0,%1}, %2;" : "=f"(lo), "=f"(hi) : "l"(v));
}
__device__ __forceinline__ void ffma2(ull& d, ull a, ull b) {
    asm("fma.rn.f32x2 %0, %1, %2, %0;" : "+l"(d) : "l"(a), "l"(b));
}

__device__ __forceinline__ unsigned adjmask(int i) {
    int r = i >> 2, c = i & 3;
    unsigned m = 1u << i;
    if (c > 0) m |= 1u << (i - 1);
    if (c < 3) m |= 1u << (i + 1);
    if (r > 0) m |= 1u << (i - 4);
    if (r < 3) m |= 1u << (i + 4);
    return m;
}

// ---- weight prep: transpose + fp16 ----
__global__ void prep_kernel(const float* __restrict__ W0,
                            const float* __restrict__ W1,
                            const float* __restrict__ W2) {
    int i = blockIdx.x * 256 + threadIdx.x;
    if (i >= 147456) return;
    float v;
    if (i < 16384) {                       // WT0[n*64+k] = W0[k*256+n]
        int n = i >> 6, k = i & 63;
        v = W0[k * 256 + n];
    } else if (i < 81920) {                // WT1[n*256+k] = W1[k*256+n]
        int j = i - 16384; int n = j >> 8, k = j & 255;
        v = W1[k * 256 + n];
    } else {                               // WT2
        int j = i - 81920; int n = j >> 8, k = j & 255;
        v = W2[k * 256 + n];
    }
    g_WTh[i] = __float2half_rn(v);
}

// ---- one GAT layer ----
template<int FIN, bool FINAL>
__device__ void gat_layer(char* smc, uint32_t smb, int tid,
                          const __half* __restrict__ WTh,
                          const float* __restrict__ asrc,
                          const float* __restrict__ adst,
                          const float* __restrict__ bb)
{
    const int NCH = FIN / 64;
    const int wid = tid >> 5, l = tid & 31;
    const int wr = wid & 3;          // row group: rows 16wr..16wr+15
    const int cg = wid >> 2;         // col group: cols 128cg..128cg+127
    const int nb0 = cg * 128;

    // ldmatrix lane addresses for A
    uint32_t aAddrH = smb + OFF_AH + (uint32_t)((wr * 16 + (l & 15)) * ASTRB)
                    + (uint32_t)((l >> 4) * 16);
    uint32_t aAddrL = aAddrH + (OFF_AL - OFF_AH);
    // B lane-invariant offset within the chunk buffer
    int bn = (l & 7) + ((l >> 4) << 3);
    uint32_t bLane = (uint32_t)((nb0 + bn) * BSTRB) + (uint32_t)(((l >> 3) & 1) * 16);
    uint32_t bufBase = smb + OFF_B + bLane;

    // B staging: thread = one row (64 halves = 8 x uint4)
    const uint4* gsrc = (const uint4*)(WTh + tid * FIN);
    uint4* sdst = (uint4*)(smc + OFF_B + tid * BSTRB);

    float d[16][4];
    #pragma unroll
    for (int nb = 0; nb < 16; nb++)
        #pragma unroll
        for (int q = 0; q < 4; q++) d[nb][q] = 0.f;

    // prologue: stage chunk 0
    #pragma unroll
    for (int q = 0; q < 8; q++) sdst[q] = gsrc[q];
    __syncthreads();

    for (int kc = 0; kc < NCH; kc++) {
        #pragma unroll
        for (int kk = 0; kk < 4; kk++) {
            int k16 = kc * 4 + kk;
            uint32_t ah[4], al4[4];
            LDSM4(ah, aAddrH + k16 * 32);
            LDSM4(al4, aAddrL + k16 * 32);
            #pragma unroll
            for (int nc = 0; nc < 8; nc++) {
                uint32_t ba = bufBase + nc * (16 * BSTRB) + kk * 32;
                uint32_t bh4[4];
                LDSM4(bh4, ba);
                MMA16816(d[2 * nc],     ah,  bh4[0], bh4[1]);
                MMA16816(d[2 * nc],     al4, bh4[0], bh4[1]);
                MMA16816(d[2 * nc + 1], ah,  bh4[2], bh4[3]);
                MMA16816(d[2 * nc + 1], al4, bh4[2], bh4[3]);
            }
        }
        __syncthreads();         // chunk (and final A) reads complete
        if (kc + 1 < NCH) {
            const uint4* gs = gsrc + (kc + 1) * 8;
            #pragma unroll
            for (int q = 0; q < 8; q++) sdst[q] = gs[q];
            __syncthreads();
        }
    }

    // ---- spill D -> whbuf (fp32, stride WSTR) ----
    {
        float* whb = (float*)(smc + OFF_WHB);
        int drow = wr * 16 + (l >> 2);
        int dcol = nb0 + (l & 3) * 2;
        #pragma unroll
        for (int nb = 0; nb < 16; nb++) {
            int cb = dcol + nb * 8;
            *(float2*)&whb[drow * WSTR + cb]       = make_float2(d[nb][0], d[nb][1]);
            *(float2*)&whb[(drow + 8) * WSTR + cb] = make_float2(d[nb][2], d[nb][3]);
        }
    }
    __syncthreads();

    // ---- logits: one thread per (u, n, h); 4*16*4 = 256 ----
    {
        int u = tid >> 6, rem = tid & 63, n = rem & 15, hh = rem >> 4;
        const float* whr = (const float*)(smc + OFF_WHB) + (u * 16 + n) * WSTR + hh * 64;
        const float* ap_ = asrc + hh * 64;
        const float* dp_ = adst + hh * 64;
        float as = 0.f, ad = 0.f;
        #pragma unroll
        for (int c = 0; c < 64; c += 4) {
            float4 v = *(const float4*)&whr[c];
            float4 av = *(const float4*)&ap_[c];
            float4 dv = *(const float4*)&dp_[c];
            as = fmaf(v.x, av.x, fmaf(v.y, av.y, fmaf(v.z, av.z, fmaf(v.w, av.w, as))));
            ad = fmaf(v.x, dv.x, fmaf(v.y, dv.y, fmaf(v.z, dv.z, fmaf(v.w, dv.w, ad))));
        }
        ((float*)(smc + OFF_ES))[u * 64 + n * 4 + hh] = as;
        ((float*)(smc + OFF_ED))[u * 64 + n * 4 + hh] = ad;
    }
    __syncthreads();

    // ---- masked softmax: one thread per (u, i, hh) ----
    {
        int u = tid >> 6, rem = tid & 63, i = rem & 15, hh = rem >> 4;
        const float* es = (const float*)(smc + OFF_ES);
        const float* edp = (const float*)(smc + OFF_ED);
        unsigned m = adjmask(i);
        float ed = edp[u * 64 + i * 4 + hh];
        float eb[NN];
        float mx = -1e30f;
        #pragma unroll
        for (int j = 0; j < NN; j++) {
            eb[j] = -1e30f;
            if ((m >> j) & 1u) {
                float e = ed + es[u * 64 + j * 4 + hh];
                e = e > 0.f ? e : 0.2f * e;
                eb[j] = e;
                mx = fmaxf(mx, e);
            }
        }
        float ssum = 0.f;
        #pragma unroll
        for (int j = 0; j < NN; j++) {
            float a = ((m >> j) & 1u) ? __expf(eb[j] - mx) : 0.f;
            eb[j] = a;
            ssum += a;
        }
        float inv = 1.f / ssum;
        float* al = (float*)(smc + OFF_ALPHA);
        #pragma unroll
        for (int j = 0; j < NN; j++)
            al[u * 1024 + hh * 256 + j * 16 + i] = eb[j] * inv;
    }
    __syncthreads();

    // ---- aggregation: thread (ua, v) -> cols c0..c0+3, f32x2 packed ----
    int ua = tid >> 6, v = tid & 63, c0 = 4 * v, hq = v >> 4;
    ull o2[4][8];
    #pragma unroll
    for (int c = 0; c < 4; c++)
        #pragma unroll
        for (int p = 0; p < 8; p++) o2[c][p] = 0ull;
    {
        const float* au = (const float*)(smc + OFF_ALPHA) + ua * 1024 + hq * 256;
        const float* whu = (const float*)(smc + OFF_WHB) + ua * 16 * WSTR;
        #pragma unroll
        for (int j = 0; j < NN; j++) {
            float4 wv = *(const float4*)&whu[j * WSTR + c0];
            float4 a0 = *(const float4*)&au[j * 16 + 0];
            float4 a1 = *(const float4*)&au[j * 16 + 4];
            float4 a2 = *(const float4*)&au[j * 16 + 8];
            float4 a3 = *(const float4*)&au[j * 16 + 12];
            ull ap[8] = { pk(a0.x,a0.y), pk(a0.z,a0.w), pk(a1.x,a1.y), pk(a1.z,a1.w),
                          pk(a2.x,a2.y), pk(a2.z,a2.w), pk(a3.x,a3.y), pk(a3.z,a3.w) };
            ull wp0 = pk(wv.x, wv.x), wp1 = pk(wv.y, wv.y);
            ull wp2 = pk(wv.z, wv.z), wp3 = pk(wv.w, wv.w);
            #pragma unroll
            for (int p = 0; p < 8; p++) {
                ffma2(o2[0][p], ap[p], wp0);
                ffma2(o2[1][p], ap[p], wp1);
                ffma2(o2[2][p], ap[p], wp2);
                ffma2(o2[3][p], ap[p], wp3);
            }
        }
    }
    __syncthreads();   // whbuf/alpha reads done before overwriting A region

    if (FINAL) {
        float cs[4];
        #pragma unroll
        for (int c = 0; c < 4; c++) {
            float s = 0.f;
            #pragma unroll
            for (int p = 0; p < 8; p++) {
                float lo, hi; upk(o2[c][p], lo, hi);
                s += lo + hi;
            }
            cs[c] = s;
        }
        *(float4*)((float*)(smc + OFF_G4) + ua * 256 + hq * 64 + (c0 & 63)) =
            make_float4(cs[0], cs[1], cs[2], cs[3]);
        __syncthreads();
    } else {
        float4 b4 = *(const float4*)&bb[c0];
        float bbv[4] = { b4.x, b4.y, b4.z, b4.w };
        #pragma unroll
        for (int p = 0; p < 8; p++) {
            float va[4], vb[4];
            #pragma unroll
            for (int c = 0; c < 4; c++) {
                upk(o2[c][p], va[c], vb[c]);
                va[c] = fmaxf(va[c] + bbv[c], 0.f);
                vb[c] = fmaxf(vb[c] + bbv[c], 0.f);
            }
            #pragma unroll
            for (int hf = 0; hf < 2; hf++) {
                const float* src = hf ? vb : va;
                int rowg = ua * 16 + 2 * p + hf;
                unsigned hx[4], lx[4];
                #pragma unroll
                for (int c = 0; c < 4; c++) {
                    float vv = src[c];
                    __half bh = __float2half_rn(vv);
                    __half bl = __float2half_rn(vv - __half2float(bh));
                    hx[c] = (unsigned)__half_as_ushort(bh);
                    lx[c] = (unsigned)__half_as_ushort(bl);
                }
                uint2 ph2, pl2;
                ph2.x = (hx[1] << 16) | hx[0];  ph2.y = (hx[3] << 16) | hx[2];
                pl2.x = (lx[1] << 16) | lx[0];  pl2.y = (lx[3] << 16) | lx[2];
                *(uint2*)(smc + OFF_AH + rowg * ASTRB + c0 * 2) = ph2;
                *(uint2*)(smc + OFF_AL + rowg * ASTRB + c0 * 2) = pl2;
            }
        }
        __syncthreads();
    }
}

__global__ void __launch_bounds__(256, 2) gat_mma_kernel(
    const float* __restrict__ x,
    const float* __restrict__ w_in, const float* __restrict__ b_in,
    const float* __restrict__ as0, const float* __restrict__ ad0,
    const float* __restrict__ bb0,
    const float* __restrict__ as1, const float* __restrict__ ad1,
    const float* __restrict__ bb1,
    const float* __restrict__ as2, const float* __restrict__ ad2,
    const float* __restrict__ bb2,
    const float* __restrict__ w1, const float* __restrict__ b1,
    const float* __restrict__ lng, const float* __restrict__ lnb,
    const float* __restrict__ w2, const float* __restrict__ b2,
    float* __restrict__ out)
{
    extern __shared__ char smc[];
    uint32_t smb = smem_u32(smc);
    int tid = threadIdx.x;
    long item0 = (long)blockIdx.x * 4;

    // stage x: 4 items * 256 floats into (pre-layer0-dead) B region
    float* xs = (float*)(smc + OFF_XS);
    #pragma unroll
    for (int q = 0; q < 4; q++)
        xs[q * 256 + tid] = x[item0 * 256 + q * 256 + tid];
    __syncthreads();

    // input linear -> A (fp16 hi/lo), thread = (u = tid>>6, f = tid&63)
    {
        int u = tid >> 6, f = tid & 63;
        const float* xu = xs + u * 256;
        float acc[NN];
        #pragma unroll
        for (int nn = 0; nn < NN; nn++) acc[nn] = 0.f;
        #pragma unroll
        for (int c = 0; c < 16; c++) {
            float wv = w_in[c * 64 + f];
            #pragma unroll
            for (int nn = 0; nn < NN; nn++)
                acc[nn] = fmaf(xu[c * 16 + nn], wv, acc[nn]);
        }
        float bv = b_in[f];
        #pragma unroll
        for (int nn = 0; nn < NN; nn++) {
            float vv = fmaxf(acc[nn] + bv, 0.f);
            __half bh = __float2half_rn(vv);
            __half bl = __float2half_rn(vv - __half2float(bh));
            int row = u * 16 + nn;
            *(__half*)(smc + OFF_AH + row * ASTRB + f * 2) = bh;
            *(__half*)(smc + OFF_AL + row * ASTRB + f * 2) = bl;
        }
    }
    __syncthreads();

    gat_layer<64,  false>(smc, smb, tid, g_WTh,         as0, ad0, bb0);
    gat_layer<256, false>(smc, smb, tid, g_WTh + 16384, as1, ad1, bb1);
    gat_layer<256, true >(smc, smb, tid, g_WTh + 81920, as2, ad2, bb2);

    // pooled g[c] = mean over nodes+heads + bb2; thread = (u, c)
    {
        int u = tid >> 6, cc = tid & 63;
        const float* g4 = (const float*)(smc + OFF_G4) + u * 256;
        float sg = g4[cc] + g4[64 + cc] + g4[128 + cc] + g4[192 + cc];
        ((float*)(smc + OFF_G))[u * 64 + cc] = sg * (1.0f / 64.0f) + bb2[cc];
    }
    __syncthreads();

    // MLP1 (64->128) + LN + relu; thread covers items up, up+2
    {
        int fy = tid & 127, up = tid >> 7;
        int ua = up, ub = up + 2;
        const float* ga_ = (const float*)(smc + OFF_G) + ua * 64;
        const float* gb_ = (const float*)(smc + OFF_G) + ub * 64;
        float va = b1[fy], vb = va;
        #pragma unroll 4
        for (int c = 0; c < 64; c += 4) {
            float4 ga = *(const float4*)&ga_[c];
            float4 gb = *(const float4*)&gb_[c];
            float w0 = w1[(c + 0) * 128 + fy];
            float wA = w1[(c + 1) * 128 + fy];
            float wB = w1[(c + 2) * 128 + fy];
            float wC = w1[(c + 3) * 128 + fy];
            va = fmaf(ga.x, w0, fmaf(ga.y, wA, fmaf(ga.z, wB, fmaf(ga.w, wC, va))));
            vb = fmaf(gb.x, w0, fmaf(gb.y, wA, fmaf(gb.z, wB, fmaf(gb.w, wC, vb))));
        }
        float* red = (float*)(smc + OFF_RED);
        float sa = va, sb = vb;
        #pragma unroll
        for (int off = 16; off; off >>= 1) {
            sa += __shfl_xor_sync(0xffffffffu, sa, off);
            sb += __shfl_xor_sync(0xffffffffu, sb, off);
        }
        int wi = (tid >> 5) & 3;
        if ((tid & 31) == 0) { red[ua * 8 + wi] = sa; red[ub * 8 + wi] = sb; }
        __syncthreads();
        float mua = (red[ua * 8] + red[ua * 8 + 1] + red[ua * 8 + 2] + red[ua * 8 + 3]) * (1.f / 128.f);
        float mub = (red[ub * 8] + red[ub * 8 + 1] + red[ub * 8 + 2] + red[ub * 8 + 3]) * (1.f / 128.f);
        float da = va - mua, db = vb - mub;
        float qa = da * da, qb = db * db;
        #pragma unroll
        for (int off = 16; off; off >>= 1) {
            qa += __shfl_xor_sync(0xffffffffu, qa, off);
            qb += __shfl_xor_sync(0xffffffffu, qb, off);
        }
        if ((tid & 31) == 0) { red[ua * 8 + 4 + wi] = qa; red[ub * 8 + 4 + wi] = qb; }
        __syncthreads();
        float vara = (red[ua * 8 + 4] + red[ua * 8 + 5] + red[ua * 8 + 6] + red[ua * 8 + 7]) * (1.f / 128.f);
        float varb = (red[ub * 8 + 4] + red[ub * 8 + 5] + red[ub * 8 + 6] + red[ub * 8 + 7]) * (1.f / 128.f);
        float gv = lng[fy], bv = lnb[fy];
        float* yv = (float*)(smc + OFF_Y);
        yv[ua * 132 + fy] = fmaxf(da * rsqrtf(vara + 1e-5f) * gv + bv, 0.f);
        yv[ub * 132 + fy] = fmaxf(db * rsqrtf(varb + 1e-5f) * gv + bv, 0.f);
    }
    __syncthreads();

    // MLP2 (128->256): thread = col, all 4 items
    {
        int col = tid;
        const float* yv = (const float*)(smc + OFF_Y);
        float a0 = b2[col], a1 = a0, a2 = a0, a3 = a0;
        #pragma unroll 4
        for (int f = 0; f < 128; f += 4) {
            float4 y0 = *(const float4*)&yv[0 * 132 + f];
            float4 y1 = *(const float4*)&yv[1 * 132 + f];
            float4 y2 = *(const float4*)&yv[2 * 132 + f];
            float4 y3 = *(const float4*)&yv[3 * 132 + f];
            float w0 = w2[(f + 0) * 256 + col];
            float wA = w2[(f + 1) * 256 + col];
            float wB = w2[(f + 2) * 256 + col];
            float wC = w2[(f + 3) * 256 + col];
            a0 = fmaf(y0.x, w0, fmaf(y0.y, wA, fmaf(y0.z, wB, fmaf(y0.w, wC, a0))));
            a1 = fmaf(y1.x, w0, fmaf(y1.y, wA, fmaf(y1.z, wB, fmaf(y1.w, wC, a1))));
            a2 = fmaf(y2.x, w0, fmaf(y2.y, wA, fmaf(y2.z, wB, fmaf(y2.w, wC, a2))));
            a3 = fmaf(y3.x, w0, fmaf(y3.y, wA, fmaf(y3.z, wB, fmaf(y3.w, wC, a3))));
        }
        out[(item0 + 0) * 256 + col] = a0;
        out[(item0 + 1) * 256 + col] = a1;
        out[(item0 + 2) * 256 + col] = a2;
        out[(item0 + 3) * 256 + col] = a3;
    }
}

extern "C" void kernel_launch(void* const* d_in, const int* in_sizes, int n_in,
                              void* d_out, int out_size)
{
    const float* x    = (const float*)d_in[0];
    const float* w_in = (const float*)d_in[1];
    const float* b_in = (const float*)d_in[2];
    const float* W0   = (const float*)d_in[3];
    const float* as0  = (const float*)d_in[4];
    const float* ad0  = (const float*)d_in[5];
    const float* bb0  = (const float*)d_in[6];
    const float* W1   = (const float*)d_in[7];
    const float* as1  = (const float*)d_in[8];
    const float* ad1  = (const float*)d_in[9];
    const float* bb1  = (const float*)d_in[10];
    const float* W2   = (const float*)d_in[11];
    const float* as2  = (const float*)d_in[12];
    const float* ad2  = (const float*)d_in[13];
    const float* bb2  = (const float*)d_in[14];
    const float* w1   = (const float*)d_in[15];
    const float* b1   = (const float*)d_in[16];
    const float* lng  = (const float*)d_in[17];
    const float* lnb  = (const float*)d_in[18];
    const float* w2   = (const float*)d_in[19];
    const float* b2   = (const float*)d_in[20];
    float* out = (float*)d_out;

    int B = out_size / 256;        // 16384
    int grid = B / 4;              // 4 graphs per block

    prep_kernel<<<576, 256>>>(W0, W1, W2);

    cudaFuncSetAttribute(gat_mma_kernel,
                         cudaFuncAttributeMaxDynamicSharedMemorySize, SMEM_BYTES);
    gat_mma_kernel<<<grid, 256, SMEM_BYTES>>>(
        x, w_in, b_in,
        as0, ad0, bb0, as1, ad1, bb1, as2, ad2, bb2,
        w1, b1, lng, lnb, w2, b2, out);
}

// round 9
// speedup vs baseline: 1.0967x; 1.0967x over previous
#include <cuda_runtime.h>
#include <cuda_fp16.h>
#include <cstdint>

// Fused GAT network on mma.sync.m16n8k16 (A fp16 hi/lo, B fp16, fp32 accum).
// 8 graphs per 1024-thread block: M = 128, N = 256, K = FIN. 32 warps/SM.

#define NN 16
#define WSTR 264          // whbuf stride (floats)
#define ASTRB 528         // A row stride bytes (264 halves)
#define BSTRB 144         // B chunk row stride bytes (72 halves)

// ---- shared memory byte offsets ----
#define OFF_AH    0            // fp16 hi A tile 128 x 264 (67584 B)
#define OFF_AL    67584        // fp16 lo A tile
#define OFF_WHB   0            // fp32 whbuf 128 x 264 overlays A (135168 B)
#define OFF_B0    135168       // fp16 B chunk buffer 0: 256 x 72 (36864 B)
#define OFF_B1    172032       // buffer 1
#define OFF_XS    135168       // x staging (8192 B) overlays B0, pre-layer0
#define OFF_ALPHA 135168       // 32768 B overlays B0 after GEMM
#define OFF_ES    167936       // 2048 B
#define OFF_ED    169984       // 2048 B
#define OFF_G4    208896       // 8192 B
#define OFF_G     217088       // 2048 B
#define OFF_Y     219136       // 4224 B
#define OFF_RED   223360       // 256 B
#define SMEM_BYTES 223616

// transposed fp16 weights WT[n][k]: W0 16384, W1 65536, W2 65536 elems
__device__ __align__(16) __half g_WTh[147456];

typedef unsigned long long ull;

__device__ __forceinline__ uint32_t smem_u32(const void* p) {
    uint32_t a;
    asm("{ .reg .u64 t; cvta.to.shared.u64 t, %1; cvt.u32.u64 %0, t; }" : "=r"(a) : "l"(p));
    return a;
}

#define LDSM4(r, a) \
    asm volatile("ldmatrix.sync.aligned.m8n8.x4.shared.b16 {%0,%1,%2,%3}, [%4];" \
        : "=r"((r)[0]), "=r"((r)[1]), "=r"((r)[2]), "=r"((r)[3]) : "r"(a))

#define MMA16816(d, a, b0, b1) \
    asm volatile("mma.sync.aligned.m16n8k16.row.col.f32.f16.f16.f32 " \
        "{%0,%1,%2,%3}, {%4,%5,%6,%7}, {%8,%9}, {%0,%1,%2,%3};" \
        : "+f"((d)[0]), "+f"((d)[1]), "+f"((d)[2]), "+f"((d)[3]) \
        : "r"((a)[0]), "r"((a)[1]), "r"((a)[2]), "r"((a)[3]), "r"(b0), "r"(b1))

__device__ __forceinline__ ull pk(float lo, float hi) {
    ull r; asm("mov.b64 %0, {%1,%2};" : "=l"(r) : "f"(lo), "f"(hi)); return r;
}
__device__ __forceinline__ void upk(ull v, float& lo, float& hi) {
    asm("mov.b64 {%0,%1}, %2;" : "=f"(lo), "=f"(hi) : "l"(v));
}
__device__ __forceinline__ void ffma2(ull& d, ull a, ull b) {
    asm("fma.rn.f32x2 %0, %1, %2, %0;" : "+l"(d) : "l"(a), "l"(b));
}

__device__ __forceinline__ unsigned adjmask(int i) {
    int r = i >> 2, c = i & 3;
    unsigned m = 1u << i;
    if (c > 0) m |= 1u << (i - 1);
    if (c < 3) m |= 1u << (i + 1);
    if (r > 0) m |= 1u << (i - 4);
    if (r < 3) m |= 1u << (i + 4);
    return m;
}

// ---- weight prep: transpose + fp16 ----
__global__ void prep_kernel(const float* __restrict__ W0,
                            const float* __restrict__ W1,
                            const float* __restrict__ W2) {
    int i = blockIdx.x * 256 + threadIdx.x;
    if (i >= 147456) return;
    float v;
    if (i < 16384) {                       // WT0[n*64+k] = W0[k*256+n]
        int n = i >> 6, k = i & 63;
        v = W0[k * 256 + n];
    } else if (i < 81920) {                // WT1[n*256+k] = W1[k*256+n]
        int j = i - 16384; int n = j >> 8, k = j & 255;
        v = W1[k * 256 + n];
    } else {                               // WT2
        int j = i - 81920; int n = j >> 8, k = j & 255;
        v = W2[k * 256 + n];
    }
    g_WTh[i] = __float2half_rn(v);
}

// ---- one GAT layer ----
template<int FIN, bool FINAL>
__device__ void gat_layer(char* smc, uint32_t smb, int tid,
                          const __half* __restrict__ WTh,
                          const float* __restrict__ asrc,
                          const float* __restrict__ adst,
                          const float* __restrict__ bb)
{
    const int NCH = FIN / 64;
    const int wid = tid >> 5, l = tid & 31;
    const int wr = wid & 7;          // row group: rows 16wr..16wr+15
    const int cg = wid >> 3;         // col group: cols 64cg..64cg+63
    const int nb0 = cg * 64;

    // ldmatrix lane addresses for A
    uint32_t aAddrH = smb + OFF_AH + (uint32_t)((wr * 16 + (l & 15)) * ASTRB)
                    + (uint32_t)((l >> 4) * 16);
    uint32_t aAddrL = aAddrH + (OFF_AL - OFF_AH);
    // B lane-invariant offset within a chunk buffer
    int bn = (l & 7) + ((l >> 4) << 3);
    uint32_t bLane = (uint32_t)((nb0 + bn) * BSTRB) + (uint32_t)(((l >> 3) & 1) * 16);

    // B staging: thread -> 32 contiguous bytes (2 x uint4)
    const int sn = tid >> 2, shf = tid & 3;
    const uint4* gsrc = (const uint4*)(WTh + sn * FIN + shf * 16);
    uint4* sdst0 = (uint4*)(smc + OFF_B0 + sn * BSTRB + shf * 32);
    uint4* sdst1 = (uint4*)(smc + OFF_B1 + sn * BSTRB + shf * 32);

    float d[8][4];
    #pragma unroll
    for (int nb = 0; nb < 8; nb++)
        #pragma unroll
        for (int q = 0; q < 4; q++) d[nb][q] = 0.f;

    // prologue: stage chunk 0 into B0
    {
        uint4 r0 = gsrc[0], r1 = gsrc[1];
        sdst0[0] = r0; sdst0[1] = r1;
    }
    __syncthreads();

    for (int kc = 0; kc < NCH; kc++) {
        uint4 rn0, rn1;
        if (kc + 1 < NCH) {
            const uint4* gs = (const uint4*)(WTh + sn * FIN + (kc + 1) * 64 + shf * 16);
            rn0 = gs[0]; rn1 = gs[1];
        }
        uint32_t bufBase = smb + ((kc & 1) ? OFF_B1 : OFF_B0) + bLane;
        #pragma unroll
        for (int kk = 0; kk < 4; kk++) {
            int k16 = kc * 4 + kk;
            uint32_t ah[4], al4[4];
            LDSM4(ah, aAddrH + k16 * 32);
            LDSM4(al4, aAddrL + k16 * 32);
            #pragma unroll
            for (int nc = 0; nc < 4; nc++) {
                uint32_t ba = bufBase + nc * (16 * BSTRB) + kk * 32;
                uint32_t bh4[4];
                LDSM4(bh4, ba);
                MMA16816(d[2 * nc],     ah,  bh4[0], bh4[1]);
                MMA16816(d[2 * nc],     al4, bh4[0], bh4[1]);
                MMA16816(d[2 * nc + 1], ah,  bh4[2], bh4[3]);
                MMA16816(d[2 * nc + 1], al4, bh4[2], bh4[3]);
            }
        }
        if (kc + 1 < NCH) {
            uint4* sd = (kc & 1) ? sdst0 : sdst1;
            sd[0] = rn0; sd[1] = rn1;
        }
        __syncthreads();
    }

    // ---- spill D -> whbuf (fp32, stride WSTR) ----
    {
        float* whb = (float*)(smc + OFF_WHB);
        int drow = wr * 16 + (l >> 2);
        int dcol = nb0 + (l & 3) * 2;
        #pragma unroll
        for (int nb = 0; nb < 8; nb++) {
            int cb = dcol + nb * 8;
            *(float2*)&whb[drow * WSTR + cb]       = make_float2(d[nb][0], d[nb][1]);
            *(float2*)&whb[(drow + 8) * WSTR + cb] = make_float2(d[nb][2], d[nb][3]);
        }
    }
    __syncthreads();

    // ---- logits: two threads per (u, n, h), col halves combined via shfl ----
    {
        int u = tid >> 7, rem = tid & 127;
        int half = rem & 1, n = (rem >> 1) & 15, hh = rem >> 5;
        const float* whr = (const float*)(smc + OFF_WHB) + (u * 16 + n) * WSTR
                         + hh * 64 + half * 32;
        const float* ap_ = asrc + hh * 64 + half * 32;
        const float* dp_ = adst + hh * 64 + half * 32;
        float as = 0.f, ad = 0.f;
        #pragma unroll
        for (int c = 0; c < 32; c += 4) {
            float4 v = *(const float4*)&whr[c];
            float4 av = *(const float4*)&ap_[c];
            float4 dv = *(const float4*)&dp_[c];
            as = fmaf(v.x, av.x, fmaf(v.y, av.y, fmaf(v.z, av.z, fmaf(v.w, av.w, as))));
            ad = fmaf(v.x, dv.x, fmaf(v.y, dv.y, fmaf(v.z, dv.z, fmaf(v.w, dv.w, ad))));
        }
        as += __shfl_xor_sync(0xffffffffu, as, 1);
        ad += __shfl_xor_sync(0xffffffffu, ad, 1);
        if (half == 0) {
            ((float*)(smc + OFF_ES))[u * 64 + n * 4 + hh] = as;
            ((float*)(smc + OFF_ED))[u * 64 + n * 4 + hh] = ad;
        }
    }
    __syncthreads();

    // ---- masked softmax: one thread per (u, i, hh), tid < 512 ----
    if (tid < 512) {
        int u = tid >> 6, rem = tid & 63, i = rem & 15, hh = rem >> 4;
        const float* es = (const float*)(smc + OFF_ES);
        const float* edp = (const float*)(smc + OFF_ED);
        unsigned m = adjmask(i);
        float ed = edp[u * 64 + i * 4 + hh];
        float eb[NN];
        float mx = -1e30f;
        #pragma unroll
        for (int j = 0; j < NN; j++) {
            eb[j] = -1e30f;
            if ((m >> j) & 1u) {
                float e = ed + es[u * 64 + j * 4 + hh];
                e = e > 0.f ? e : 0.2f * e;
                eb[j] = e;
                mx = fmaxf(mx, e);
            }
        }
        float ssum = 0.f;
        #pragma unroll
        for (int j = 0; j < NN; j++) {
            float a = ((m >> j) & 1u) ? __expf(eb[j] - mx) : 0.f;
            eb[j] = a;
            ssum += a;
        }
        float inv = 1.f / ssum;
        float* al = (float*)(smc + OFF_ALPHA);
        #pragma unroll
        for (int j = 0; j < NN; j++)
            al[u * 1024 + hh * 256 + j * 16 + i] = eb[j] * inv;
    }
    __syncthreads();

    // ---- aggregation: thread (ua = tid>>7, v = tid&127) -> cols 2v..2v+1 ----
    int ua = tid >> 7, v = tid & 127, c0 = 2 * v, hq = v >> 5;
    ull o2[2][8];
    #pragma unroll
    for (int c = 0; c < 2; c++)
        #pragma unroll
        for (int p = 0; p < 8; p++) o2[c][p] = 0ull;
    {
        const float* au = (const float*)(smc + OFF_ALPHA) + ua * 1024 + hq * 256;
        const float* whu = (const float*)(smc + OFF_WHB) + ua * 16 * WSTR;
        #pragma unroll
        for (int j = 0; j < NN; j++) {
            float2 wv = *(const float2*)&whu[j * WSTR + c0];
            float4 a0 = *(const float4*)&au[j * 16 + 0];
            float4 a1 = *(const float4*)&au[j * 16 + 4];
            float4 a2 = *(const float4*)&au[j * 16 + 8];
            float4 a3 = *(const float4*)&au[j * 16 + 12];
            ull ap[8] = { pk(a0.x,a0.y), pk(a0.z,a0.w), pk(a1.x,a1.y), pk(a1.z,a1.w),
                          pk(a2.x,a2.y), pk(a2.z,a2.w), pk(a3.x,a3.y), pk(a3.z,a3.w) };
            ull wp0 = pk(wv.x, wv.x), wp1 = pk(wv.y, wv.y);
            #pragma unroll
            for (int p = 0; p < 8; p++) {
                ffma2(o2[0][p], ap[p], wp0);
                ffma2(o2[1][p], ap[p], wp1);
            }
        }
    }
    __syncthreads();   // whbuf/alpha reads done before overwriting A region

    if (FINAL) {
        float cs[2];
        #pragma unroll
        for (int c = 0; c < 2; c++) {
            float s = 0.f;
            #pragma unroll
            for (int p = 0; p < 8; p++) {
                float lo, hi; upk(o2[c][p], lo, hi);
                s += lo + hi;
            }
            cs[c] = s;
        }
        *(float2*)((float*)(smc + OFF_G4) + ua * 256 + hq * 64 + (c0 & 63)) =
            make_float2(cs[0], cs[1]);
        __syncthreads();
    } else {
        float2 b2v = *(const float2*)&bb[c0];
        float bbv[2] = { b2v.x, b2v.y };
        #pragma unroll
        for (int p = 0; p < 8; p++) {
            float va[2], vb[2];
            #pragma unroll
            for (int c = 0; c < 2; c++) {
                upk(o2[c][p], va[c], vb[c]);
                va[c] = fmaxf(va[c] + bbv[c], 0.f);
                vb[c] = fmaxf(vb[c] + bbv[c], 0.f);
            }
            #pragma unroll
            for (int hf = 0; hf < 2; hf++) {
                const float* src = hf ? vb : va;
                int rowg = ua * 16 + 2 * p + hf;
                unsigned hx[2], lx[2];
                #pragma unroll
                for (int c = 0; c < 2; c++) {
                    float vv = src[c];
                    __half bh = __float2half_rn(vv);
                    __half bl = __float2half_rn(vv - __half2float(bh));
                    hx[c] = (unsigned)__half_as_ushort(bh);
                    lx[c] = (unsigned)__half_as_ushort(bl);
                }
                *(uint32_t*)(smc + OFF_AH + rowg * ASTRB + c0 * 2) = (hx[1] << 16) | hx[0];
                *(uint32_t*)(smc + OFF_AL + rowg * ASTRB + c0 * 2) = (lx[1] << 16) | lx[0];
            }
        }
        __syncthreads();
    }
}

__global__ void __launch_bounds__(1024, 1) gat_mma_kernel(
    const float* __restrict__ x,
    const float* __restrict__ w_in, const float* __restrict__ b_in,
    const float* __restrict__ as0, const float* __restrict__ ad0,
    const float* __restrict__ bb0,
    const float* __restrict__ as1, const float* __restrict__ ad1,
    const float* __restrict__ bb1,
    const float* __restrict__ as2, const float* __restrict__ ad2,
    const float* __restrict__ bb2,
    const float* __restrict__ w1, const float* __restrict__ b1,
    const float* __restrict__ lng, const float* __restrict__ lnb,
    const float* __restrict__ w2, const float* __restrict__ b2,
    float* __restrict__ out)
{
    extern __shared__ char smc[];
    uint32_t smb = smem_u32(smc);
    int tid = threadIdx.x;
    long item0 = (long)blockIdx.x * 8;

    // stage x: 8 items * 256 floats into (pre-layer0-dead) B0 region
    float* xs = (float*)(smc + OFF_XS);
    #pragma unroll
    for (int q = 0; q < 2; q++)
        xs[q * 1024 + tid] = x[item0 * 256 + q * 1024 + tid];
    __syncthreads();

    // input linear -> A (fp16 hi/lo), thread = (u = tid>>6, f = tid&63), tid<512
    if (tid < 512) {
        int u = tid >> 6, f = tid & 63;
        const float* xu = xs + u * 256;
        float acc[NN];
        #pragma unroll
        for (int nn = 0; nn < NN; nn++) acc[nn] = 0.f;
        #pragma unroll
        for (int c = 0; c < 16; c++) {
            float wv = w_in[c * 64 + f];
            #pragma unroll
            for (int nn = 0; nn < NN; nn++)
                acc[nn] = fmaf(xu[c * 16 + nn], wv, acc[nn]);
        }
        float bv = b_in[f];
        #pragma unroll
        for (int nn = 0; nn < NN; nn++) {
            float vv = fmaxf(acc[nn] + bv, 0.f);
            __half bh = __float2half_rn(vv);
            __half bl = __float2half_rn(vv - __half2float(bh));
            int row = u * 16 + nn;
            *(__half*)(smc + OFF_AH + row * ASTRB + f * 2) = bh;
            *(__half*)(smc + OFF_AL + row * ASTRB + f * 2) = bl;
        }
    }
    __syncthreads();

    gat_layer<64,  false>(smc, smb, tid, g_WTh,         as0, ad0, bb0);
    gat_layer<256, false>(smc, smb, tid, g_WTh + 16384, as1, ad1, bb1);
    gat_layer<256, true >(smc, smb, tid, g_WTh + 81920, as2, ad2, bb2);

    // pooled g[c] = mean over nodes+heads + bb2; thread = (u, c), tid < 512
    if (tid < 512) {
        int u = tid >> 6, cc = tid & 63;
        const float* g4 = (const float*)(smc + OFF_G4) + u * 256;
        float sg = g4[cc] + g4[64 + cc] + g4[128 + cc] + g4[192 + cc];
        ((float*)(smc + OFF_G))[u * 64 + cc] = sg * (1.0f / 64.0f) + bb2[cc];
    }
    __syncthreads();

    // MLP1 (64->128) + LN + relu; thread = (up = tid>>7, fy = tid&127)
    {
        int fy = tid & 127, up = tid >> 7;
        const float* ga_ = (const float*)(smc + OFF_G) + up * 64;
        float va = b1[fy];
        #pragma unroll 4
        for (int c = 0; c < 64; c += 4) {
            float4 ga = *(const float4*)&ga_[c];
            float w0 = w1[(c + 0) * 128 + fy];
            float wA = w1[(c + 1) * 128 + fy];
            float wB = w1[(c + 2) * 128 + fy];
            float wC = w1[(c + 3) * 128 + fy];
            va = fmaf(ga.x, w0, fmaf(ga.y, wA, fmaf(ga.z, wB, fmaf(ga.w, wC, va))));
        }
        float* red = (float*)(smc + OFF_RED);
        float sa = va;
        #pragma unroll
        for (int off = 16; off; off >>= 1)
            sa += __shfl_xor_sync(0xffffffffu, sa, off);
        int wi = (tid >> 5) & 3;
        if ((tid & 31) == 0) red[up * 8 + wi] = sa;
        __syncthreads();
        float mua = (red[up * 8] + red[up * 8 + 1] + red[up * 8 + 2] + red[up * 8 + 3]) * (1.f / 128.f);
        float da = va - mua;
        float qa = da * da;
        #pragma unroll
        for (int off = 16; off; off >>= 1)
            qa += __shfl_xor_sync(0xffffffffu, qa, off);
        if ((tid & 31) == 0) red[up * 8 + 4 + wi] = qa;
        __syncthreads();
        float vara = (red[up * 8 + 4] + red[up * 8 + 5] + red[up * 8 + 6] + red[up * 8 + 7]) * (1.f / 128.f);
        float gv = lng[fy], bv = lnb[fy];
        float* yv = (float*)(smc + OFF_Y);
        yv[up * 132 + fy] = fmaxf(da * rsqrtf(vara + 1e-5f) * gv + bv, 0.f);
    }
    __syncthreads();

    // MLP2 (128->256): thread = (pr = tid>>8 -> items 2pr, 2pr+1, col = tid&255)
    {
        int col = tid & 255, pr = tid >> 8;
        const float* yv = (const float*)(smc + OFF_Y) + pr * 2 * 132;
        float a0 = b2[col], a1 = a0;
        #pragma unroll 4
        for (int f = 0; f < 128; f += 4) {
            float4 y0 = *(const float4*)&yv[0 * 132 + f];
            float4 y1 = *(const float4*)&yv[1 * 132 + f];
            float w0 = w2[(f + 0) * 256 + col];
            float wA = w2[(f + 1) * 256 + col];
            float wB = w2[(f + 2) * 256 + col];
            float wC = w2[(f + 3) * 256 + col];
            a0 = fmaf(y0.x, w0, fmaf(y0.y, wA, fmaf(y0.z, wB, fmaf(y0.w, wC, a0))));
            a1 = fmaf(y1.x, w0, fmaf(y1.y, wA, fmaf(y1.z, wB, fmaf(y1.w, wC, a1))));
        }
        out[(item0 + 2 * pr + 0) * 256 + col] = a0;
        out[(item0 + 2 * pr + 1) * 256 + col] = a1;
    }
}

extern "C" void kernel_launch(void* const* d_in, const int* in_sizes, int n_in,
                              void* d_out, int out_size)
{
    const float* x    = (const float*)d_in[0];
    const float* w_in = (const float*)d_in[1];
    const float* b_in = (const float*)d_in[2];
    const float* W0   = (const float*)d_in[3];
    const float* as0  = (const float*)d_in[4];
    const float* ad0  = (const float*)d_in[5];
    const float* bb0  = (const float*)d_in[6];
    const float* W1   = (const float*)d_in[7];
    const float* as1  = (const float*)d_in[8];
    const float* ad1  = (const float*)d_in[9];
    const float* bb1  = (const float*)d_in[10];
    const float* W2   = (const float*)d_in[11];
    const float* as2  = (const float*)d_in[12];
    const float* ad2  = (const float*)d_in[13];
    const float* bb2  = (const float*)d_in[14];
    const float* w1   = (const float*)d_in[15];
    const float* b1   = (const float*)d_in[16];
    const float* lng  = (const float*)d_in[17];
    const float* lnb  = (const float*)d_in[18];
    const float* w2   = (const float*)d_in[19];
    const float* b2   = (const float*)d_in[20];
    float* out = (float*)d_out;

    int B = out_size / 256;        // 16384
    int grid = B / 8;              // 8 graphs per block

    prep_kernel<<<576, 256>>>(W0, W1, W2);

    cudaFuncSetAttribute(gat_mma_kernel,
                         cudaFuncAttributeMaxDynamicSharedMemorySize, SMEM_BYTES);
    gat_mma_kernel<<<grid, 1024, SMEM_BYTES>>>(
        x, w_in, b_in,
        as0, ad0, bb0, as1, ad1, bb1, as2, ad2, bb2,
        w1, b1, lng, lnb, w2, b2, out);
}

// round 10
// speedup vs baseline: 1.2360x; 1.1270x over previous
#include <cuda_runtime.h>
#include <cuda_fp16.h>
#include <cstdint>

// Fused GAT network on mma.sync.m16n8k16 (A fp16 hi/lo, B fp16, fp32 accum).
// 8 graphs per 512-thread block: M = 128, N = 256, K = FIN.
// R10: in-register logits from D-fragments + bank-conflict-free alpha layout.

#define NN 16
#define WSTR 264          // whbuf stride (floats)
#define ASTRB 528         // A row stride bytes (264 halves)
#define BSTRB 144         // B chunk row stride bytes (72 halves)

// ---- shared memory byte offsets ----
#define OFF_AH    0            // fp16 hi A tile 128 x 264 (67584 B)
#define OFF_AL    67584        // fp16 lo A tile
#define OFF_WHB   0            // fp32 whbuf 128 x 264 overlays A (135168 B)
#define OFF_B0    135168       // fp16 B chunk buffer 0: 256 x 72 (36864 B)
#define OFF_B1    172032       // buffer 1
#define OFF_XS    135168       // x staging (8192 B) overlays B0, pre-layer0
#define OFF_ALPHA 135168       // 33280 B overlays B0 after GEMM: [u][hh] planes of 1040 B
#define OFF_ES    172032       // 2048 B (overlays B1 after GEMM)
#define OFF_ED    174080       // 2048 B
#define OFF_ASRC  208896       // 1024 B  (4 heads x 64 floats)
#define OFF_ADST  209920       // 1024 B
#define OFF_G4    210944       // 8192 B
#define OFF_G     219136       // 2048 B
#define OFF_Y     221184       // 4224 B
#define OFF_RED   225408       // 256 B
#define SMEM_BYTES 225664

// transposed fp16 weights WT[n][k]: W0 16384, W1 65536, W2 65536 elems
__device__ __align__(16) __half g_WTh[147456];

typedef unsigned long long ull;

__device__ __forceinline__ uint32_t smem_u32(const void* p) {
    uint32_t a;
    asm("{ .reg .u64 t; cvta.to.shared.u64 t, %1; cvt.u32.u64 %0, t; }" : "=r"(a) : "l"(p));
    return a;
}

#define LDSM4(r, a) \
    asm volatile("ldmatrix.sync.aligned.m8n8.x4.shared.b16 {%0,%1,%2,%3}, [%4];" \
        : "=r"((r)[0]), "=r"((r)[1]), "=r"((r)[2]), "=r"((r)[3]) : "r"(a))

#define MMA16816(d, a, b0, b1) \
    asm volatile("mma.sync.aligned.m16n8k16.row.col.f32.f16.f16.f32 " \
        "{%0,%1,%2,%3}, {%4,%5,%6,%7}, {%8,%9}, {%0,%1,%2,%3};" \
        : "+f"((d)[0]), "+f"((d)[1]), "+f"((d)[2]), "+f"((d)[3]) \
        : "r"((a)[0]), "r"((a)[1]), "r"((a)[2]), "r"((a)[3]), "r"(b0), "r"(b1))

__device__ __forceinline__ ull pk(float lo, float hi) {
    ull r; asm("mov.b64 %0, {%1,%2};" : "=l"(r) : "f"(lo), "f"(hi)); return r;
}
__device__ __forceinline__ void upk(ull v, float& lo, float& hi) {
    asm("mov.b64 {%0,%1}, %2;" : "=f"(lo), "=f"(hi) : "l"(v));
}
__device__ __forceinline__ void ffma2(ull& d, ull a, ull b) {
    asm("fma.rn.f32x2 %0, %1, %2, %0;" : "+l"(d) : "l"(a), "l"(b));
}

__device__ __forceinline__ unsigned adjmask(int i) {
    int r = i >> 2, c = i & 3;
    unsigned m = 1u << i;
    if (c > 0) m |= 1u << (i - 1);
    if (c < 3) m |= 1u << (i + 1);
    if (r > 0) m |= 1u << (i - 4);
    if (r < 3) m |= 1u << (i + 4);
    return m;
}

// ---- weight prep: transpose + fp16 ----
__global__ void prep_kernel(const float* __restrict__ W0,
                            const float* __restrict__ W1,
                            const float* __restrict__ W2) {
    int i = blockIdx.x * 256 + threadIdx.x;
    if (i >= 147456) return;
    float v;
    if (i < 16384) {                       // WT0[n*64+k] = W0[k*256+n]
        int n = i >> 6, k = i & 63;
        v = W0[k * 256 + n];
    } else if (i < 81920) {                // WT1[n*256+k] = W1[k*256+n]
        int j = i - 16384; int n = j >> 8, k = j & 255;
        v = W1[k * 256 + n];
    } else {                               // WT2
        int j = i - 81920; int n = j >> 8, k = j & 255;
        v = W2[k * 256 + n];
    }
    g_WTh[i] = __float2half_rn(v);
}

// ---- one GAT layer ----
template<int FIN, bool FINAL>
__device__ void gat_layer(char* smc, uint32_t smb, int tid,
                          const __half* __restrict__ WTh,
                          const float* __restrict__ asrc,
                          const float* __restrict__ adst,
                          const float* __restrict__ bb)
{
    const int NCH = FIN / 64;
    const int wid = tid >> 5, l = tid & 31;
    const int wr = wid & 7;          // row group = item wr (rows 16wr..16wr+15)
    const int cg = wid >> 3;         // col group: cols 128cg..128cg+127
    const int nb0 = cg * 128;

    // stage asrc/adst into smem (used post-mainloop; syncs inside loop cover it)
    if (tid < 256) ((float*)(smc + OFF_ASRC))[tid] = asrc[tid];
    else           ((float*)(smc + OFF_ADST))[tid - 256] = adst[tid - 256];

    // ldmatrix lane addresses for A
    uint32_t aAddrH = smb + OFF_AH + (uint32_t)((wr * 16 + (l & 15)) * ASTRB)
                    + (uint32_t)((l >> 4) * 16);
    uint32_t aAddrL = aAddrH + (OFF_AL - OFF_AH);
    // B lane-invariant offset within a chunk buffer
    int bn = (l & 7) + ((l >> 4) << 3);
    uint32_t bLane = (uint32_t)((nb0 + bn) * BSTRB) + (uint32_t)(((l >> 3) & 1) * 16);

    // B staging: thread -> 64 contiguous bytes (4 x uint4)
    const int sn = tid >> 1, shf = tid & 1;
    const uint4* gsrc = (const uint4*)(WTh + sn * FIN + shf * 32);
    uint4* sdst0 = (uint4*)(smc + OFF_B0 + sn * BSTRB + shf * 64);
    uint4* sdst1 = (uint4*)(smc + OFF_B1 + sn * BSTRB + shf * 64);

    float d[16][4];
    #pragma unroll
    for (int nb = 0; nb < 16; nb++)
        #pragma unroll
        for (int q = 0; q < 4; q++) d[nb][q] = 0.f;

    // prologue: stage chunk 0 into B0
    {
        uint4 r[4];
        #pragma unroll
        for (int q = 0; q < 4; q++) r[q] = gsrc[q];
        #pragma unroll
        for (int q = 0; q < 4; q++) sdst0[q] = r[q];
    }
    __syncthreads();

    for (int kc = 0; kc < NCH; kc++) {
        uint4 rnext[4];
        if (kc + 1 < NCH) {
            #pragma unroll
            for (int q = 0; q < 4; q++) rnext[q] = gsrc[(kc + 1) * 8 + q];
        }
        uint32_t bufBase = smb + ((kc & 1) ? OFF_B1 : OFF_B0) + bLane;
        #pragma unroll
        for (int kk = 0; kk < 4; kk++) {
            int k16 = kc * 4 + kk;
            uint32_t ah[4], al4[4];
            LDSM4(ah, aAddrH + k16 * 32);
            LDSM4(al4, aAddrL + k16 * 32);
            #pragma unroll
            for (int nc = 0; nc < 8; nc++) {
                uint32_t ba = bufBase + nc * (16 * BSTRB) + kk * 32;
                uint32_t bh4[4];
                LDSM4(bh4, ba);
                MMA16816(d[2 * nc],     ah,  bh4[0], bh4[1]);
                MMA16816(d[2 * nc],     al4, bh4[0], bh4[1]);
                MMA16816(d[2 * nc + 1], ah,  bh4[2], bh4[3]);
                MMA16816(d[2 * nc + 1], al4, bh4[2], bh4[3]);
            }
        }
        if (kc + 1 < NCH) {
            uint4* sd = (kc & 1) ? sdst0 : sdst1;
            #pragma unroll
            for (int q = 0; q < 4; q++) sd[q] = rnext[q];
        }
        __syncthreads();
    }

    // ---- in-register logits from D-fragments ----
    // lane holds rows n1 = l>>2, n2 = n1+8 of item wr; cols nb*8 + (l&3)*2 (+1)
    {
        float pS[2][2] = {{0.f,0.f},{0.f,0.f}};   // [head-half][row-half]
        float pD[2][2] = {{0.f,0.f},{0.f,0.f}};
        const float* as_s = (const float*)(smc + OFF_ASRC);
        const float* ad_s = (const float*)(smc + OFF_ADST);
        int cbase = (l & 3) * 2;
        #pragma unroll
        for (int nb = 0; nb < 16; nb++) {
            int hm = nb >> 3;
            int h  = 2 * cg + hm;
            int c64 = (nb & 7) * 8 + cbase;
            float2 av = *(const float2*)&as_s[h * 64 + c64];
            float2 dv = *(const float2*)&ad_s[h * 64 + c64];
            pS[hm][0] = fmaf(d[nb][0], av.x, fmaf(d[nb][1], av.y, pS[hm][0]));
            pS[hm][1] = fmaf(d[nb][2], av.x, fmaf(d[nb][3], av.y, pS[hm][1]));
            pD[hm][0] = fmaf(d[nb][0], dv.x, fmaf(d[nb][1], dv.y, pD[hm][0]));
            pD[hm][1] = fmaf(d[nb][2], dv.x, fmaf(d[nb][3], dv.y, pD[hm][1]));
        }
        #pragma unroll
        for (int off = 1; off <= 2; off <<= 1) {
            #pragma unroll
            for (int hm = 0; hm < 2; hm++) {
                #pragma unroll
                for (int rh = 0; rh < 2; rh++) {
                    pS[hm][rh] += __shfl_xor_sync(0xffffffffu, pS[hm][rh], off);
                    pD[hm][rh] += __shfl_xor_sync(0xffffffffu, pD[hm][rh], off);
                }
            }
        }
        if ((l & 3) == 0) {
            int n1 = l >> 2;
            float* ES = (float*)(smc + OFF_ES);
            float* ED = (float*)(smc + OFF_ED);
            ES[wr * 64 + n1 * 4 + 2 * cg]           = pS[0][0];
            ES[wr * 64 + n1 * 4 + 2 * cg + 1]       = pS[1][0];
            ES[wr * 64 + (n1 + 8) * 4 + 2 * cg]     = pS[0][1];
            ES[wr * 64 + (n1 + 8) * 4 + 2 * cg + 1] = pS[1][1];
            ED[wr * 64 + n1 * 4 + 2 * cg]           = pD[0][0];
            ED[wr * 64 + n1 * 4 + 2 * cg + 1]       = pD[1][0];
            ED[wr * 64 + (n1 + 8) * 4 + 2 * cg]     = pD[0][1];
            ED[wr * 64 + (n1 + 8) * 4 + 2 * cg + 1] = pD[1][1];
        }
    }

    // ---- spill D -> whbuf (fp32, stride WSTR) ----
    {
        float* whb = (float*)(smc + OFF_WHB);
        int drow = wr * 16 + (l >> 2);
        int dcol = nb0 + (l & 3) * 2;
        #pragma unroll
        for (int nb = 0; nb < 16; nb++) {
            int cb = dcol + nb * 8;
            *(float2*)&whb[drow * WSTR + cb]       = make_float2(d[nb][0], d[nb][1]);
            *(float2*)&whb[(drow + 8) * WSTR + cb] = make_float2(d[nb][2], d[nb][3]);
        }
    }
    __syncthreads();

    // ---- masked softmax: one thread per (u, i, hh); alpha in padded planes ----
    {
        int u = tid >> 6, rem = tid & 63, i = rem & 15, hh = rem >> 4;
        const float* es = (const float*)(smc + OFF_ES);
        const float* edp = (const float*)(smc + OFF_ED);
        unsigned m = adjmask(i);
        float ed = edp[u * 64 + i * 4 + hh];
        float eb[NN];
        float mx = -1e30f;
        #pragma unroll
        for (int j = 0; j < NN; j++) {
            eb[j] = -1e30f;
            if ((m >> j) & 1u) {
                float e = ed + es[u * 64 + j * 4 + hh];
                e = e > 0.f ? e : 0.2f * e;
                eb[j] = e;
                mx = fmaxf(mx, e);
            }
        }
        float ssum = 0.f;
        #pragma unroll
        for (int j = 0; j < NN; j++) {
            float a = ((m >> j) & 1u) ? __expf(eb[j] - mx) : 0.f;
            eb[j] = a;
            ssum += a;
        }
        float inv = 1.f / ssum;
        // alpha plane (u, hh): 1040 B each -> word stride 260; u stride 1040 words
        float* al = (float*)(smc + OFF_ALPHA) + u * 1040 + hh * 260 + i;
        #pragma unroll
        for (int j = 0; j < NN; j++)
            al[j * 16] = eb[j] * inv;
    }
    __syncthreads();

    // ---- aggregation: thread (ua, v) -> cols c0..c0+3, f32x2 packed ----
    int ua = tid >> 6, v = tid & 63, c0 = 4 * v, hq = v >> 4;
    ull o2[4][8];
    #pragma unroll
    for (int c = 0; c < 4; c++)
        #pragma unroll
        for (int p = 0; p < 8; p++) o2[c][p] = 0ull;
    {
        const float* au = (const float*)(smc + OFF_ALPHA) + ua * 1040 + hq * 260;
        const float* whu = (const float*)(smc + OFF_WHB) + ua * 16 * WSTR;
        #pragma unroll
        for (int j = 0; j < NN; j++) {
            float4 wv = *(const float4*)&whu[j * WSTR + c0];
            float4 a0 = *(const float4*)&au[j * 16 + 0];
            float4 a1 = *(const float4*)&au[j * 16 + 4];
            float4 a2 = *(const float4*)&au[j * 16 + 8];
            float4 a3 = *(const float4*)&au[j * 16 + 12];
            ull ap[8] = { pk(a0.x,a0.y), pk(a0.z,a0.w), pk(a1.x,a1.y), pk(a1.z,a1.w),
                          pk(a2.x,a2.y), pk(a2.z,a2.w), pk(a3.x,a3.y), pk(a3.z,a3.w) };
            ull wp0 = pk(wv.x, wv.x), wp1 = pk(wv.y, wv.y);
            ull wp2 = pk(wv.z, wv.z), wp3 = pk(wv.w, wv.w);
            #pragma unroll
            for (int p = 0; p < 8; p++) {
                ffma2(o2[0][p], ap[p], wp0);
                ffma2(o2[1][p], ap[p], wp1);
                ffma2(o2[2][p], ap[p], wp2);
                ffma2(o2[3][p], ap[p], wp3);
            }
        }
    }
    __syncthreads();   // whbuf/alpha reads done before overwriting A region

    if (FINAL) {
        float cs[4];
        #pragma unroll
        for (int c = 0; c < 4; c++) {
            float s = 0.f;
            #pragma unroll
            for (int p = 0; p < 8; p++) {
                float lo, hi; upk(o2[c][p], lo, hi);
                s += lo + hi;
            }
            cs[c] = s;
        }
        *(float4*)((float*)(smc + OFF_G4) + ua * 256 + hq * 64 + (c0 & 63)) =
            make_float4(cs[0], cs[1], cs[2], cs[3]);
        __syncthreads();
    } else {
        float4 b4 = *(const float4*)&bb[c0];
        float bbv[4] = { b4.x, b4.y, b4.z, b4.w };
        #pragma unroll
        for (int p = 0; p < 8; p++) {
            float va[4], vb[4];
            #pragma unroll
            for (int c = 0; c < 4; c++) {
                upk(o2[c][p], va[c], vb[c]);
                va[c] = fmaxf(va[c] + bbv[c], 0.f);
                vb[c] = fmaxf(vb[c] + bbv[c], 0.f);
            }
            #pragma unroll
            for (int hf = 0; hf < 2; hf++) {
                const float* src = hf ? vb : va;
                int rowg = ua * 16 + 2 * p + hf;
                unsigned hx[4], lx[4];
                #pragma unroll
                for (int c = 0; c < 4; c++) {
                    float vv = src[c];
                    __half bh = __float2half_rn(vv);
                    __half bl = __float2half_rn(vv - __half2float(bh));
                    hx[c] = (unsigned)__half_as_ushort(bh);
                    lx[c] = (unsigned)__half_as_ushort(bl);
                }
                uint2 ph2, pl2;
                ph2.x = (hx[1] << 16) | hx[0];  ph2.y = (hx[3] << 16) | hx[2];
                pl2.x = (lx[1] << 16) | lx[0];  pl2.y = (lx[3] << 16) | lx[2];
                *(uint2*)(smc + OFF_AH + rowg * ASTRB + c0 * 2) = ph2;
                *(uint2*)(smc + OFF_AL + rowg * ASTRB + c0 * 2) = pl2;
            }
        }
        __syncthreads();
    }
}

__global__ void __launch_bounds__(512, 1) gat_mma_kernel(
    const float* __restrict__ x,
    const float* __restrict__ w_in, const float* __restrict__ b_in,
    const float* __restrict__ as0, const float* __restrict__ ad0,
    const float* __restrict__ bb0,
    const float* __restrict__ as1, const float* __restrict__ ad1,
    const float* __restrict__ bb1,
    const float* __restrict__ as2, const float* __restrict__ ad2,
    const float* __restrict__ bb2,
    const float* __restrict__ w1, const float* __restrict__ b1,
    const float* __restrict__ lng, const float* __restrict__ lnb,
    const float* __restrict__ w2, const float* __restrict__ b2,
    float* __restrict__ out)
{
    extern __shared__ char smc[];
    uint32_t smb = smem_u32(smc);
    int tid = threadIdx.x;
    long item0 = (long)blockIdx.x * 8;

    // stage x: 8 items * 256 floats into (pre-layer0-dead) B0 region
    float* xs = (float*)(smc + OFF_XS);
    #pragma unroll
    for (int q = 0; q < 4; q++)
        xs[q * 512 + tid] = x[item0 * 256 + q * 512 + tid];
    __syncthreads();

    // input linear -> A (fp16 hi/lo), thread = (u = tid>>6, f = tid&63)
    {
        int u = tid >> 6, f = tid & 63;
        const float* xu = xs + u * 256;
        float acc[NN];
        #pragma unroll
        for (int nn = 0; nn < NN; nn++) acc[nn] = 0.f;
        #pragma unroll
        for (int c = 0; c < 16; c++) {
            float wv = w_in[c * 64 + f];
            #pragma unroll
            for (int nn = 0; nn < NN; nn++)
                acc[nn] = fmaf(xu[c * 16 + nn], wv, acc[nn]);
        }
        float bv = b_in[f];
        #pragma unroll
        for (int nn = 0; nn < NN; nn++) {
            float vv = fmaxf(acc[nn] + bv, 0.f);
            __half bh = __float2half_rn(vv);
            __half bl = __float2half_rn(vv - __half2float(bh));
            int row = u * 16 + nn;
            *(__half*)(smc + OFF_AH + row * ASTRB + f * 2) = bh;
            *(__half*)(smc + OFF_AL + row * ASTRB + f * 2) = bl;
        }
    }
    __syncthreads();

    gat_layer<64,  false>(smc, smb, tid, g_WTh,         as0, ad0, bb0);
    gat_layer<256, false>(smc, smb, tid, g_WTh + 16384, as1, ad1, bb1);
    gat_layer<256, true >(smc, smb, tid, g_WTh + 81920, as2, ad2, bb2);

    // pooled g[c] = mean over nodes+heads + bb2
    {
        int u = tid >> 6, cc = tid & 63;
        const float* g4 = (const float*)(smc + OFF_G4) + u * 256;
        float sg = g4[cc] + g4[64 + cc] + g4[128 + cc] + g4[192 + cc];
        ((float*)(smc + OFF_G))[u * 64 + cc] = sg * (1.0f / 64.0f) + bb2[cc];
    }
    __syncthreads();

    // MLP1 (64->128) + LN + relu; thread covers items up, up+4
    {
        int fy = tid & 127, up = tid >> 7;
        int ua = up, ub = up + 4;
        const float* ga_ = (const float*)(smc + OFF_G) + ua * 64;
        const float* gb_ = (const float*)(smc + OFF_G) + ub * 64;
        float va = b1[fy], vb = va;
        #pragma unroll 4
        for (int c = 0; c < 64; c += 4) {
            float4 ga = *(const float4*)&ga_[c];
            float4 gb = *(const float4*)&gb_[c];
            float w0 = w1[(c + 0) * 128 + fy];
            float wA = w1[(c + 1) * 128 + fy];
            float wB = w1[(c + 2) * 128 + fy];
            float wC = w1[(c + 3) * 128 + fy];
            va = fmaf(ga.x, w0, fmaf(ga.y, wA, fmaf(ga.z, wB, fmaf(ga.w, wC, va))));
            vb = fmaf(gb.x, w0, fmaf(gb.y, wA, fmaf(gb.z, wB, fmaf(gb.w, wC, vb))));
        }
        float* red = (float*)(smc + OFF_RED);
        float sa = va, sb = vb;
        #pragma unroll
        for (int off = 16; off; off >>= 1) {
            sa += __shfl_xor_sync(0xffffffffu, sa, off);
            sb += __shfl_xor_sync(0xffffffffu, sb, off);
        }
        int wi = (tid >> 5) & 3;
        if ((tid & 31) == 0) { red[ua * 8 + wi] = sa; red[ub * 8 + wi] = sb; }
        __syncthreads();
        float mua = (red[ua * 8] + red[ua * 8 + 1] + red[ua * 8 + 2] + red[ua * 8 + 3]) * (1.f / 128.f);
        float mub = (red[ub * 8] + red[ub * 8 + 1] + red[ub * 8 + 2] + red[ub * 8 + 3]) * (1.f / 128.f);
        float da = va - mua, db = vb - mub;
        float qa = da * da, qb = db * db;
        #pragma unroll
        for (int off = 16; off; off >>= 1) {
            qa += __shfl_xor_sync(0xffffffffu, qa, off);
            qb += __shfl_xor_sync(0xffffffffu, qb, off);
        }
        if ((tid & 31) == 0) { red[ua * 8 + 4 + wi] = qa; red[ub * 8 + 4 + wi] = qb; }
        __syncthreads();
        float vara = (red[ua * 8 + 4] + red[ua * 8 + 5] + red[ua * 8 + 6] + red[ua * 8 + 7]) * (1.f / 128.f);
        float varb = (red[ub * 8 + 4] + red[ub * 8 + 5] + red[ub * 8 + 6] + red[ub * 8 + 7]) * (1.f / 128.f);
        float gv = lng[fy], bv = lnb[fy];
        float* yv = (float*)(smc + OFF_Y);
        yv[ua * 132 + fy] = fmaxf(da * rsqrtf(vara + 1e-5f) * gv + bv, 0.f);
        yv[ub * 132 + fy] = fmaxf(db * rsqrtf(varb + 1e-5f) * gv + bv, 0.f);
    }
    __syncthreads();

    // MLP2 (128->256): thread = (pr = tid>>8 -> items 4pr..4pr+3, col = tid&255)
    {
        int col = tid & 255, pr = tid >> 8;
        const float* yv = (const float*)(smc + OFF_Y) + pr * 4 * 132;
        float a0 = b2[col], a1 = a0, a2 = a0, a3 = a0;
        #pragma unroll 4
        for (int f = 0; f < 128; f += 4) {
            float4 y0 = *(const float4*)&yv[0 * 132 + f];
            float4 y1 = *(const float4*)&yv[1 * 132 + f];
            float4 y2 = *(const float4*)&yv[2 * 132 + f];
            float4 y3 = *(const float4*)&yv[3 * 132 + f];
            float w0 = w2[(f + 0) * 256 + col];
            float wA = w2[(f + 1) * 256 + col];
            float wB = w2[(f + 2) * 256 + col];
            float wC = w2[(f + 3) * 256 + col];
            a0 = fmaf(y0.x, w0, fmaf(y0.y, wA, fmaf(y0.z, wB, fmaf(y0.w, wC, a0))));
            a1 = fmaf(y1.x, w0, fmaf(y1.y, wA, fmaf(y1.z, wB, fmaf(y1.w, wC, a1))));
            a2 = fmaf(y2.x, w0, fmaf(y2.y, wA, fmaf(y2.z, wB, fmaf(y2.w, wC, a2))));
            a3 = fmaf(y3.x, w0, fmaf(y3.y, wA, fmaf(y3.z, wB, fmaf(y3.w, wC, a3))));
        }
        out[(item0 + 4 * pr + 0) * 256 + col] = a0;
        out[(item0 + 4 * pr + 1) * 256 + col] = a1;
        out[(item0 + 4 * pr + 2) * 256 + col] = a2;
        out[(item0 + 4 * pr + 3) * 256 + col] = a3;
    }
}

extern "C" void kernel_launch(void* const* d_in, const int* in_sizes, int n_in,
                              void* d_out, int out_size)
{
    const float* x    = (const float*)d_in[0];
    const float* w_in = (const float*)d_in[1];
    const float* b_in = (const float*)d_in[2];
    const float* W0   = (const float*)d_in[3];
    const float* as0  = (const float*)d_in[4];
    const float* ad0  = (const float*)d_in[5];
    const float* bb0  = (const float*)d_in[6];
    const float* W1   = (const float*)d_in[7];
    const float* as1  = (const float*)d_in[8];
    const float* ad1  = (const float*)d_in[9];
    const float* bb1  = (const float*)d_in[10];
    const float* W2   = (const float*)d_in[11];
    const float* as2  = (const float*)d_in[12];
    const float* ad2  = (const float*)d_in[13];
    const float* bb2  = (const float*)d_in[14];
    const float* w1   = (const float*)d_in[15];
    const float* b1   = (const float*)d_in[16];
    const float* lng  = (const float*)d_in[17];
    const float* lnb  = (const float*)d_in[18];
    const float* w2   = (const float*)d_in[19];
    const float* b2   = (const float*)d_in[20];
    float* out = (float*)d_out;

    int B = out_size / 256;        // 16384
    int grid = B / 8;              // 8 graphs per block

    prep_kernel<<<576, 256>>>(W0, W1, W2);

    cudaFuncSetAttribute(gat_mma_kernel,
                         cudaFuncAttributeMaxDynamicSharedMemorySize, SMEM_BYTES);
    gat_mma_kernel<<<grid, 512, SMEM_BYTES>>>(
        x, w_in, b_in,
        as0, ad0, bb0, as1, ad1, bb1, as2, ad2, bb2,
        w1, b1, lng, lnb, w2, b2, out);
}

// round 11
// speedup vs baseline: 1.5110x; 1.2225x over previous
#include <cuda_runtime.h>
#include <cuda_fp16.h>
#include <cstdint>

// Fused GAT network on mma.sync.m16n8k16 (A fp16, B fp16, fp32 accum).
// 8 graphs per 512-thread block: M = 128, N = 256, K = FIN.
// R11: single-precision-split dropped on A as well (error budget allows).

#define NN 16
#define WSTR 264          // whbuf stride (floats)
#define ASTRB 528         // A row stride bytes (264 halves)
#define BSTRB 144         // B chunk row stride bytes (72 halves)

// ---- shared memory byte offsets ----
#define OFF_AH    0            // fp16 A tile 128 x 264 (67584 B)
#define OFF_WHB   0            // fp32 whbuf 128 x 264 overlays A + spare (135168 B)
#define OFF_B0    135168       // fp16 B chunk buffer 0: 256 x 72 (36864 B)
#define OFF_B1    172032       // buffer 1
#define OFF_XS    135168       // x staging (8192 B) overlays B0, pre-layer0
#define OFF_ALPHA 135168       // 33280 B overlays B0 after GEMM: [u][hh] planes
#define OFF_ES    172032       // 2048 B (overlays B1 after GEMM)
#define OFF_ED    174080       // 2048 B
#define OFF_ASRC  208896       // 1024 B
#define OFF_ADST  209920       // 1024 B
#define OFF_G4    210944       // 8192 B
#define OFF_G     219136       // 2048 B
#define OFF_Y     221184       // 4224 B
#define OFF_RED   225408       // 256 B
#define SMEM_BYTES 225664

// transposed fp16 weights WT[n][k]: W0 16384, W1 65536, W2 65536 elems
__device__ __align__(16) __half g_WTh[147456];

typedef unsigned long long ull;

__device__ __forceinline__ uint32_t smem_u32(const void* p) {
    uint32_t a;
    asm("{ .reg .u64 t; cvta.to.shared.u64 t, %1; cvt.u32.u64 %0, t; }" : "=r"(a) : "l"(p));
    return a;
}

#define LDSM4(r, a) \
    asm volatile("ldmatrix.sync.aligned.m8n8.x4.shared.b16 {%0,%1,%2,%3}, [%4];" \
        : "=r"((r)[0]), "=r"((r)[1]), "=r"((r)[2]), "=r"((r)[3]) : "r"(a))

#define MMA16816(d, a, b0, b1) \
    asm volatile("mma.sync.aligned.m16n8k16.row.col.f32.f16.f16.f32 " \
        "{%0,%1,%2,%3}, {%4,%5,%6,%7}, {%8,%9}, {%0,%1,%2,%3};" \
        : "+f"((d)[0]), "+f"((d)[1]), "+f"((d)[2]), "+f"((d)[3]) \
        : "r"((a)[0]), "r"((a)[1]), "r"((a)[2]), "r"((a)[3]), "r"(b0), "r"(b1))

__device__ __forceinline__ ull pk(float lo, float hi) {
    ull r; asm("mov.b64 %0, {%1,%2};" : "=l"(r) : "f"(lo), "f"(hi)); return r;
}
__device__ __forceinline__ void upk(ull v, float& lo, float& hi) {
    asm("mov.b64 {%0,%1}, %2;" : "=f"(lo), "=f"(hi) : "l"(v));
}
__device__ __forceinline__ void ffma2(ull& d, ull a, ull b) {
    asm("fma.rn.f32x2 %0, %1, %2, %0;" : "+l"(d) : "l"(a), "l"(b));
}

__device__ __forceinline__ unsigned adjmask(int i) {
    int r = i >> 2, c = i & 3;
    unsigned m = 1u << i;
    if (c > 0) m |= 1u << (i - 1);
    if (c < 3) m |= 1u << (i + 1);
    if (r > 0) m |= 1u << (i - 4);
    if (r < 3) m |= 1u << (i + 4);
    return m;
}

// ---- weight prep: transpose + fp16 ----
__global__ void prep_kernel(const float* __restrict__ W0,
                            const float* __restrict__ W1,
                            const float* __restrict__ W2) {
    int i = blockIdx.x * 256 + threadIdx.x;
    if (i >= 147456) return;
    float v;
    if (i < 16384) {                       // WT0[n*64+k] = W0[k*256+n]
        int n = i >> 6, k = i & 63;
        v = W0[k * 256 + n];
    } else if (i < 81920) {                // WT1[n*256+k] = W1[k*256+n]
        int j = i - 16384; int n = j >> 8, k = j & 255;
        v = W1[k * 256 + n];
    } else {                               // WT2
        int j = i - 81920; int n = j >> 8, k = j & 255;
        v = W2[k * 256 + n];
    }
    g_WTh[i] = __float2half_rn(v);
}

// ---- one GAT layer ----
template<int FIN, bool FINAL>
__device__ void gat_layer(char* smc, uint32_t smb, int tid,
                          const __half* __restrict__ WTh,
                          const float* __restrict__ asrc,
                          const float* __restrict__ adst,
                          const float* __restrict__ bb)
{
    const int NCH = FIN / 64;
    const int wid = tid >> 5, l = tid & 31;
    const int wr = wid & 7;          // row group = item wr (rows 16wr..16wr+15)
    const int cg = wid >> 3;         // col group: cols 128cg..128cg+127
    const int nb0 = cg * 128;

    // stage asrc/adst into smem (used post-mainloop; syncs inside loop cover it)
    if (tid < 256) ((float*)(smc + OFF_ASRC))[tid] = asrc[tid];
    else           ((float*)(smc + OFF_ADST))[tid - 256] = adst[tid - 256];

    // ldmatrix lane address for A
    uint32_t aAddr = smb + OFF_AH + (uint32_t)((wr * 16 + (l & 15)) * ASTRB)
                   + (uint32_t)((l >> 4) * 16);
    // B lane-invariant offset within a chunk buffer
    int bn = (l & 7) + ((l >> 4) << 3);
    uint32_t bLane = (uint32_t)((nb0 + bn) * BSTRB) + (uint32_t)(((l >> 3) & 1) * 16);

    // B staging: thread -> 64 contiguous bytes (4 x uint4)
    const int sn = tid >> 1, shf = tid & 1;
    const uint4* gsrc = (const uint4*)(WTh + sn * FIN + shf * 32);
    uint4* sdst0 = (uint4*)(smc + OFF_B0 + sn * BSTRB + shf * 64);
    uint4* sdst1 = (uint4*)(smc + OFF_B1 + sn * BSTRB + shf * 64);

    float d[16][4];
    #pragma unroll
    for (int nb = 0; nb < 16; nb++)
        #pragma unroll
        for (int q = 0; q < 4; q++) d[nb][q] = 0.f;

    // prologue: stage chunk 0 into B0
    {
        uint4 r[4];
        #pragma unroll
        for (int q = 0; q < 4; q++) r[q] = gsrc[q];
        #pragma unroll
        for (int q = 0; q < 4; q++) sdst0[q] = r[q];
    }
    __syncthreads();

    for (int kc = 0; kc < NCH; kc++) {
        uint4 rnext[4];
        if (kc + 1 < NCH) {
            #pragma unroll
            for (int q = 0; q < 4; q++) rnext[q] = gsrc[(kc + 1) * 8 + q];
        }
        uint32_t bufBase = smb + ((kc & 1) ? OFF_B1 : OFF_B0) + bLane;
        #pragma unroll
        for (int kk = 0; kk < 4; kk++) {
            int k16 = kc * 4 + kk;
            uint32_t ah[4];
            LDSM4(ah, aAddr + k16 * 32);
            #pragma unroll
            for (int nc = 0; nc < 8; nc++) {
                uint32_t ba = bufBase + nc * (16 * BSTRB) + kk * 32;
                uint32_t bh4[4];
                LDSM4(bh4, ba);
                MMA16816(d[2 * nc],     ah, bh4[0], bh4[1]);
                MMA16816(d[2 * nc + 1], ah, bh4[2], bh4[3]);
            }
        }
        if (kc + 1 < NCH) {
            uint4* sd = (kc & 1) ? sdst0 : sdst1;
            #pragma unroll
            for (int q = 0; q < 4; q++) sd[q] = rnext[q];
        }
        __syncthreads();
    }

    // ---- in-register logits from D-fragments ----
    {
        float pS[2][2] = {{0.f,0.f},{0.f,0.f}};   // [head-half][row-half]
        float pD[2][2] = {{0.f,0.f},{0.f,0.f}};
        const float* as_s = (const float*)(smc + OFF_ASRC);
        const float* ad_s = (const float*)(smc + OFF_ADST);
        int cbase = (l & 3) * 2;
        #pragma unroll
        for (int nb = 0; nb < 16; nb++) {
            int hm = nb >> 3;
            int h  = 2 * cg + hm;
            int c64 = (nb & 7) * 8 + cbase;
            float2 av = *(const float2*)&as_s[h * 64 + c64];
            float2 dv = *(const float2*)&ad_s[h * 64 + c64];
            pS[hm][0] = fmaf(d[nb][0], av.x, fmaf(d[nb][1], av.y, pS[hm][0]));
            pS[hm][1] = fmaf(d[nb][2], av.x, fmaf(d[nb][3], av.y, pS[hm][1]));
            pD[hm][0] = fmaf(d[nb][0], dv.x, fmaf(d[nb][1], dv.y, pD[hm][0]));
            pD[hm][1] = fmaf(d[nb][2], dv.x, fmaf(d[nb][3], dv.y, pD[hm][1]));
        }
        #pragma unroll
        for (int off = 1; off <= 2; off <<= 1) {
            #pragma unroll
            for (int hm = 0; hm < 2; hm++) {
                #pragma unroll
                for (int rh = 0; rh < 2; rh++) {
                    pS[hm][rh] += __shfl_xor_sync(0xffffffffu, pS[hm][rh], off);
                    pD[hm][rh] += __shfl_xor_sync(0xffffffffu, pD[hm][rh], off);
                }
            }
        }
        if ((l & 3) == 0) {
            int n1 = l >> 2;
            float* ES = (float*)(smc + OFF_ES);
            float* ED = (float*)(smc + OFF_ED);
            ES[wr * 64 + n1 * 4 + 2 * cg]           = pS[0][0];
            ES[wr * 64 + n1 * 4 + 2 * cg + 1]       = pS[1][0];
            ES[wr * 64 + (n1 + 8) * 4 + 2 * cg]     = pS[0][1];
            ES[wr * 64 + (n1 + 8) * 4 + 2 * cg + 1] = pS[1][1];
            ED[wr * 64 + n1 * 4 + 2 * cg]           = pD[0][0];
            ED[wr * 64 + n1 * 4 + 2 * cg + 1]       = pD[1][0];
            ED[wr * 64 + (n1 + 8) * 4 + 2 * cg]     = pD[0][1];
            ED[wr * 64 + (n1 + 8) * 4 + 2 * cg + 1] = pD[1][1];
        }
    }

    // ---- spill D -> whbuf (fp32, stride WSTR) ----
    {
        float* whb = (float*)(smc + OFF_WHB);
        int drow = wr * 16 + (l >> 2);
        int dcol = nb0 + (l & 3) * 2;
        #pragma unroll
        for (int nb = 0; nb < 16; nb++) {
            int cb = dcol + nb * 8;
            *(float2*)&whb[drow * WSTR + cb]       = make_float2(d[nb][0], d[nb][1]);
            *(float2*)&whb[(drow + 8) * WSTR + cb] = make_float2(d[nb][2], d[nb][3]);
        }
    }
    __syncthreads();

    // ---- masked softmax: one thread per (u, i, hh); alpha in padded planes ----
    {
        int u = tid >> 6, rem = tid & 63, i = rem & 15, hh = rem >> 4;
        const float* es = (const float*)(smc + OFF_ES);
        const float* edp = (const float*)(smc + OFF_ED);
        unsigned m = adjmask(i);
        float ed = edp[u * 64 + i * 4 + hh];
        float eb[NN];
        float mx = -1e30f;
        #pragma unroll
        for (int j = 0; j < NN; j++) {
            eb[j] = -1e30f;
            if ((m >> j) & 1u) {
                float e = ed + es[u * 64 + j * 4 + hh];
                e = e > 0.f ? e : 0.2f * e;
                eb[j] = e;
                mx = fmaxf(mx, e);
            }
        }
        float ssum = 0.f;
        #pragma unroll
        for (int j = 0; j < NN; j++) {
            float a = ((m >> j) & 1u) ? __expf(eb[j] - mx) : 0.f;
            eb[j] = a;
            ssum += a;
        }
        float inv = 1.f / ssum;
        float* al = (float*)(smc + OFF_ALPHA) + u * 1040 + hh * 260 + i;
        #pragma unroll
        for (int j = 0; j < NN; j++)
            al[j * 16] = eb[j] * inv;
    }
    __syncthreads();

    // ---- aggregation: thread (ua, v) -> cols c0..c0+3, f32x2 packed ----
    int ua = tid >> 6, v = tid & 63, c0 = 4 * v, hq = v >> 4;
    ull o2[4][8];
    #pragma unroll
    for (int c = 0; c < 4; c++)
        #pragma unroll
        for (int p = 0; p < 8; p++) o2[c][p] = 0ull;
    {
        const float* au = (const float*)(smc + OFF_ALPHA) + ua * 1040 + hq * 260;
        const float* whu = (const float*)(smc + OFF_WHB) + ua * 16 * WSTR;
        #pragma unroll
        for (int j = 0; j < NN; j++) {
            float4 wv = *(const float4*)&whu[j * WSTR + c0];
            float4 a0 = *(const float4*)&au[j * 16 + 0];
            float4 a1 = *(const float4*)&au[j * 16 + 4];
            float4 a2 = *(const float4*)&au[j * 16 + 8];
            float4 a3 = *(const float4*)&au[j * 16 + 12];
            ull ap[8] = { pk(a0.x,a0.y), pk(a0.z,a0.w), pk(a1.x,a1.y), pk(a1.z,a1.w),
                          pk(a2.x,a2.y), pk(a2.z,a2.w), pk(a3.x,a3.y), pk(a3.z,a3.w) };
            ull wp0 = pk(wv.x, wv.x), wp1 = pk(wv.y, wv.y);
            ull wp2 = pk(wv.z, wv.z), wp3 = pk(wv.w, wv.w);
            #pragma unroll
            for (int p = 0; p < 8; p++) {
                ffma2(o2[0][p], ap[p], wp0);
                ffma2(o2[1][p], ap[p], wp1);
                ffma2(o2[2][p], ap[p], wp2);
                ffma2(o2[3][p], ap[p], wp3);
            }
        }
    }
    __syncthreads();   // whbuf/alpha reads done before overwriting A region

    if (FINAL) {
        float cs[4];
        #pragma unroll
        for (int c = 0; c < 4; c++) {
            float s = 0.f;
            #pragma unroll
            for (int p = 0; p < 8; p++) {
                float lo, hi; upk(o2[c][p], lo, hi);
                s += lo + hi;
            }
            cs[c] = s;
        }
        *(float4*)((float*)(smc + OFF_G4) + ua * 256 + hq * 64 + (c0 & 63)) =
            make_float4(cs[0], cs[1], cs[2], cs[3]);
        __syncthreads();
    } else {
        float4 b4 = *(const float4*)&bb[c0];
        float bbv[4] = { b4.x, b4.y, b4.z, b4.w };
        #pragma unroll
        for (int p = 0; p < 8; p++) {
            float va[4], vb[4];
            #pragma unroll
            for (int c = 0; c < 4; c++) {
                upk(o2[c][p], va[c], vb[c]);
                va[c] = fmaxf(va[c] + bbv[c], 0.f);
                vb[c] = fmaxf(vb[c] + bbv[c], 0.f);
            }
            #pragma unroll
            for (int hf = 0; hf < 2; hf++) {
                const float* src = hf ? vb : va;
                int rowg = ua * 16 + 2 * p + hf;
                unsigned hx[4];
                #pragma unroll
                for (int c = 0; c < 4; c++)
                    hx[c] = (unsigned)__half_as_ushort(__float2half_rn(src[c]));
                uint2 ph2;
                ph2.x = (hx[1] << 16) | hx[0];  ph2.y = (hx[3] << 16) | hx[2];
                *(uint2*)(smc + OFF_AH + rowg * ASTRB + c0 * 2) = ph2;
            }
        }
        __syncthreads();
    }
}

__global__ void __launch_bounds__(512, 1) gat_mma_kernel(
    const float* __restrict__ x,
    const float* __restrict__ w_in, const float* __restrict__ b_in,
    const float* __restrict__ as0, const float* __restrict__ ad0,
    const float* __restrict__ bb0,
    const float* __restrict__ as1, const float* __restrict__ ad1,
    const float* __restrict__ bb1,
    const float* __restrict__ as2, const float* __restrict__ ad2,
    const float* __restrict__ bb2,
    const float* __restrict__ w1, const float* __restrict__ b1,
    const float* __restrict__ lng, const float* __restrict__ lnb,
    const float* __restrict__ w2, const float* __restrict__ b2,
    float* __restrict__ out)
{
    extern __shared__ char smc[];
    uint32_t smb = smem_u32(smc);
    int tid = threadIdx.x;
    long item0 = (long)blockIdx.x * 8;

    // stage x: 8 items * 256 floats into (pre-layer0-dead) B0 region
    float* xs = (float*)(smc + OFF_XS);
    #pragma unroll
    for (int q = 0; q < 4; q++)
        xs[q * 512 + tid] = x[item0 * 256 + q * 512 + tid];
    __syncthreads();

    // input linear -> A (fp16), thread = (u = tid>>6, f = tid&63)
    {
        int u = tid >> 6, f = tid & 63;
        const float* xu = xs + u * 256;
        float acc[NN];
        #pragma unroll
        for (int nn = 0; nn < NN; nn++) acc[nn] = 0.f;
        #pragma unroll
        for (int c = 0; c < 16; c++) {
            float wv = w_in[c * 64 + f];
            #pragma unroll
            for (int nn = 0; nn < NN; nn++)
                acc[nn] = fmaf(xu[c * 16 + nn], wv, acc[nn]);
        }
        float bv = b_in[f];
        #pragma unroll
        for (int nn = 0; nn < NN; nn++) {
            float vv = fmaxf(acc[nn] + bv, 0.f);
            int row = u * 16 + nn;
            *(__half*)(smc + OFF_AH + row * ASTRB + f * 2) = __float2half_rn(vv);
        }
    }
    __syncthreads();

    gat_layer<64,  false>(smc, smb, tid, g_WTh,         as0, ad0, bb0);
    gat_layer<256, false>(smc, smb, tid, g_WTh + 16384, as1, ad1, bb1);
    gat_layer<256, true >(smc, smb, tid, g_WTh + 81920, as2, ad2, bb2);

    // pooled g[c] = mean over nodes+heads + bb2
    {
        int u = tid >> 6, cc = tid & 63;
        const float* g4 = (const float*)(smc + OFF_G4) + u * 256;
        float sg = g4[cc] + g4[64 + cc] + g4[128 + cc] + g4[192 + cc];
        ((float*)(smc + OFF_G))[u * 64 + cc] = sg * (1.0f / 64.0f) + bb2[cc];
    }
    __syncthreads();

    // MLP1 (64->128) + LN + relu; thread covers items up, up+4
    {
        int fy = tid & 127, up = tid >> 7;
        int ua = up, ub = up + 4;
        const float* ga_ = (const float*)(smc + OFF_G) + ua * 64;
        const float* gb_ = (const float*)(smc + OFF_G) + ub * 64;
        float va = b1[fy], vb = va;
        #pragma unroll 4
        for (int c = 0; c < 64; c += 4) {
            float4 ga = *(const float4*)&ga_[c];
            float4 gb = *(const float4*)&gb_[c];
            float w0 = w1[(c + 0) * 128 + fy];
            float wA = w1[(c + 1) * 128 + fy];
            float wB = w1[(c + 2) * 128 + fy];
            float wC = w1[(c + 3) * 128 + fy];
            va = fmaf(ga.x, w0, fmaf(ga.y, wA, fmaf(ga.z, wB, fmaf(ga.w, wC, va))));
            vb = fmaf(gb.x, w0, fmaf(gb.y, wA, fmaf(gb.z, wB, fmaf(gb.w, wC, vb))));
        }
        float* red = (float*)(smc + OFF_RED);
        float sa = va, sb = vb;
        #pragma unroll
        for (int off = 16; off; off >>= 1) {
            sa += __shfl_xor_sync(0xffffffffu, sa, off);
            sb += __shfl_xor_sync(0xffffffffu, sb, off);
        }
        int wi = (tid >> 5) & 3;
        if ((tid & 31) == 0) { red[ua * 8 + wi] = sa; red[ub * 8 + wi] = sb; }
        __syncthreads();
        float mua = (red[ua * 8] + red[ua * 8 + 1] + red[ua * 8 + 2] + red[ua * 8 + 3]) * (1.f / 128.f);
        float mub = (red[ub * 8] + red[ub * 8 + 1] + red[ub * 8 + 2] + red[ub * 8 + 3]) * (1.f / 128.f);
        float da = va - mua, db = vb - mub;
        float qa = da * da, qb = db * db;
        #pragma unroll
        for (int off = 16; off; off >>= 1) {
            qa += __shfl_xor_sync(0xffffffffu, qa, off);
            qb += __shfl_xor_sync(0xffffffffu, qb, off);
        }
        if ((tid & 31) == 0) { red[ua * 8 + 4 + wi] = qa; red[ub * 8 + 4 + wi] = qb; }
        __syncthreads();
        float vara = (red[ua * 8 + 4] + red[ua * 8 + 5] + red[ua * 8 + 6] + red[ua * 8 + 7]) * (1.f / 128.f);
        float varb = (red[ub * 8 + 4] + red[ub * 8 + 5] + red[ub * 8 + 6] + red[ub * 8 + 7]) * (1.f / 128.f);
        float gv = lng[fy], bv = lnb[fy];
        float* yv = (float*)(smc + OFF_Y);
        yv[ua * 132 + fy] = fmaxf(da * rsqrtf(vara + 1e-5f) * gv + bv, 0.f);
        yv[ub * 132 + fy] = fmaxf(db * rsqrtf(varb + 1e-5f) * gv + bv, 0.f);
    }
    __syncthreads();

    // MLP2 (128->256): thread = (pr = tid>>8 -> items 4pr..4pr+3, col = tid&255)
    {
        int col = tid & 255, pr = tid >> 8;
        const float* yv = (const float*)(smc + OFF_Y) + pr * 4 * 132;
        float a0 = b2[col], a1 = a0, a2 = a0, a3 = a0;
        #pragma unroll 4
        for (int f = 0; f < 128; f += 4) {
            float4 y0 = *(const float4*)&yv[0 * 132 + f];
            float4 y1 = *(const float4*)&yv[1 * 132 + f];
            float4 y2 = *(const float4*)&yv[2 * 132 + f];
            float4 y3 = *(const float4*)&yv[3 * 132 + f];
            float w0 = w2[(f + 0) * 256 + col];
            float wA = w2[(f + 1) * 256 + col];
            float wB = w2[(f + 2) * 256 + col];
            float wC = w2[(f + 3) * 256 + col];
            a0 = fmaf(y0.x, w0, fmaf(y0.y, wA, fmaf(y0.z, wB, fmaf(y0.w, wC, a0))));
            a1 = fmaf(y1.x, w0, fmaf(y1.y, wA, fmaf(y1.z, wB, fmaf(y1.w, wC, a1))));
            a2 = fmaf(y2.x, w0, fmaf(y2.y, wA, fmaf(y2.z, wB, fmaf(y2.w, wC, a2))));
            a3 = fmaf(y3.x, w0, fmaf(y3.y, wA, fmaf(y3.z, wB, fmaf(y3.w, wC, a3))));
        }
        out[(item0 + 4 * pr + 0) * 256 + col] = a0;
        out[(item0 + 4 * pr + 1) * 256 + col] = a1;
        out[(item0 + 4 * pr + 2) * 256 + col] = a2;
        out[(item0 + 4 * pr + 3) * 256 + col] = a3;
    }
}

extern "C" void kernel_launch(void* const* d_in, const int* in_sizes, int n_in,
                              void* d_out, int out_size)
{
    const float* x    = (const float*)d_in[0];
    const float* w_in = (const float*)d_in[1];
    const float* b_in = (const float*)d_in[2];
    const float* W0   = (const float*)d_in[3];
    const float* as0  = (const float*)d_in[4];
    const float* ad0  = (const float*)d_in[5];
    const float* bb0  = (const float*)d_in[6];
    const float* W1   = (const float*)d_in[7];
    const float* as1  = (const float*)d_in[8];
    const float* ad1  = (const float*)d_in[9];
    const float* bb1  = (const float*)d_in[10];
    const float* W2   = (const float*)d_in[11];
    const float* as2  = (const float*)d_in[12];
    const float* ad2  = (const float*)d_in[13];
    const float* bb2  = (const float*)d_in[14];
    const float* w1   = (const float*)d_in[15];
    const float* b1   = (const float*)d_in[16];
    const float* lng  = (const float*)d_in[17];
    const float* lnb  = (const float*)d_in[18];
    const float* w2   = (const float*)d_in[19];
    const float* b2   = (const float*)d_in[20];
    float* out = (float*)d_out;

    int B = out_size / 256;        // 16384
    int grid = B / 8;              // 8 graphs per block

    prep_kernel<<<576, 256>>>(W0, W1, W2);

    cudaFuncSetAttribute(gat_mma_kernel,
                         cudaFuncAttributeMaxDynamicSharedMemorySize, SMEM_BYTES);
    gat_mma_kernel<<<grid, 512, SMEM_BYTES>>>(
        x, w_in, b_in,
        as0, ad0, bb0, as1, ad1, bb1, as2, ad2, bb2,
        w1, b1, lng, lnb, w2, b2, out);
}

// round 12
// speedup vs baseline: 1.6345x; 1.0817x over previous
#include <cuda_runtime.h>
#include <cuda_fp16.h>
#include <cstdint>

// Fused GAT network on mma.sync.m16n8k16 (A fp16, B fp16, fp32 accum).
// 8 graphs per 512-thread block: M = 128, N = 256, K = FIN.
// R12: warp tile M32xN64, cp.async B staging, fp16 whbuf.

#define NN 16
#define WSTRH 264         // whbuf stride (halves) == A stride
#define ASTRB 528         // A row stride bytes (264 halves)
#define BSTRB 144         // B chunk row stride bytes (72 halves)

// ---- shared memory byte offsets ----
#define OFF_A     0            // fp16 A tile 128 x 264 (67584 B); whbuf overlays
#define OFF_WHB   0
#define OFF_B0    67584        // fp16 B chunk buffer 0: 256 x 72 (36864 B)
#define OFF_B1    104448       // buffer 1
#define OFF_XS    67584        // x staging (8192 B) overlays B0, pre-layer0
#define OFF_ALPHA 67584        // 33280 B overlays B0 after GEMM: [u][hh] planes
#define OFF_ES    104448       // 2048 B (overlays B1 after GEMM)
#define OFF_ED    106496       // 2048 B
#define OFF_ASRC  141312       // 1024 B
#define OFF_ADST  142336       // 1024 B
#define OFF_G4    143360       // 8192 B
#define OFF_G     151552       // 2048 B
#define OFF_Y     153600       // 4224 B
#define OFF_RED   157824       // 256 B
#define SMEM_BYTES 158080

// transposed fp16 weights WT[n][k]: W0 16384, W1 65536, W2 65536 elems
__device__ __align__(16) __half g_WTh[147456];

typedef unsigned long long ull;

__device__ __forceinline__ uint32_t smem_u32(const void* p) {
    uint32_t a;
    asm("{ .reg .u64 t; cvta.to.shared.u64 t, %1; cvt.u32.u64 %0, t; }" : "=r"(a) : "l"(p));
    return a;
}

#define LDSM4(r, a) \
    asm volatile("ldmatrix.sync.aligned.m8n8.x4.shared.b16 {%0,%1,%2,%3}, [%4];" \
        : "=r"((r)[0]), "=r"((r)[1]), "=r"((r)[2]), "=r"((r)[3]) : "r"(a))

#define MMA16816(d, a0, a1, b0, b1) \
    asm volatile("mma.sync.aligned.m16n8k16.row.col.f32.f16.f16.f32 " \
        "{%0,%1,%2,%3}, {%4,%5,%6,%7}, {%8,%9}, {%0,%1,%2,%3};" \
        : "+f"((d)[0]), "+f"((d)[1]), "+f"((d)[2]), "+f"((d)[3]) \
        : "r"(a0), "r"(a1), "r"((a)[2]), "r"((a)[3]), "r"(b0), "r"(b1))

#define MMA16816F(d, a, b0, b1) \
    asm volatile("mma.sync.aligned.m16n8k16.row.col.f32.f16.f16.f32 " \
        "{%0,%1,%2,%3}, {%4,%5,%6,%7}, {%8,%9}, {%0,%1,%2,%3};" \
        : "+f"((d)[0]), "+f"((d)[1]), "+f"((d)[2]), "+f"((d)[3]) \
        : "r"((a)[0]), "r"((a)[1]), "r"((a)[2]), "r"((a)[3]), "r"(b0), "r"(b1))

#define CP_ASYNC16(dst, src) \
    asm volatile("cp.async.cg.shared.global [%0], [%1], 16;" :: "r"(dst), "l"(src))
#define CP_COMMIT() asm volatile("cp.async.commit_group;" ::: "memory")
#define CP_WAIT0()  asm volatile("cp.async.wait_group 0;" ::: "memory")

__device__ __forceinline__ ull pk(float lo, float hi) {
    ull r; asm("mov.b64 %0, {%1,%2};" : "=l"(r) : "f"(lo), "f"(hi)); return r;
}
__device__ __forceinline__ void upk(ull v, float& lo, float& hi) {
    asm("mov.b64 {%0,%1}, %2;" : "=f"(lo), "=f"(hi) : "l"(v));
}
__device__ __forceinline__ void ffma2(ull& d, ull a, ull b) {
    asm("fma.rn.f32x2 %0, %1, %2, %0;" : "+l"(d) : "l"(a), "l"(b));
}

__device__ __forceinline__ unsigned adjmask(int i) {
    int r = i >> 2, c = i & 3;
    unsigned m = 1u << i;
    if (c > 0) m |= 1u << (i - 1);
    if (c < 3) m |= 1u << (i + 1);
    if (r > 0) m |= 1u << (i - 4);
    if (r < 3) m |= 1u << (i + 4);
    return m;
}

// ---- weight prep: transpose + fp16 ----
__global__ void prep_kernel(const float* __restrict__ W0,
                            const float* __restrict__ W1,
                            const float* __restrict__ W2) {
    int i = blockIdx.x * 256 + threadIdx.x;
    if (i >= 147456) return;
    float v;
    if (i < 16384) {                       // WT0[n*64+k] = W0[k*256+n]
        int n = i >> 6, k = i & 63;
        v = W0[k * 256 + n];
    } else if (i < 81920) {                // WT1[n*256+k] = W1[k*256+n]
        int j = i - 16384; int n = j >> 8, k = j & 255;
        v = W1[k * 256 + n];
    } else {                               // WT2
        int j = i - 81920; int n = j >> 8, k = j & 255;
        v = W2[k * 256 + n];
    }
    g_WTh[i] = __float2half_rn(v);
}

// ---- one GAT layer ----
template<int FIN, bool FINAL>
__device__ void gat_layer(char* smc, uint32_t smb, int tid,
                          const __half* __restrict__ WTh,
                          const float* __restrict__ asrc,
                          const float* __restrict__ adst,
                          const float* __restrict__ bb)
{
    const int NCH = FIN / 64;
    const int wid = tid >> 5, l = tid & 31;
    const int wr2 = wid & 3;         // row block: rows 32*wr2 .. +31 (items 2wr2, 2wr2+1)
    const int cg4 = wid >> 2;        // head / col group: cols 64*cg4 .. +63
    const int nb0 = cg4 * 64;

    // stage asrc/adst into smem (read post-mainloop; covered by loop syncs)
    if (tid < 256) ((float*)(smc + OFF_ASRC))[tid] = asrc[tid];
    else           ((float*)(smc + OFF_ADST))[tid - 256] = adst[tid - 256];

    // ldmatrix lane addresses for A (two 16-row groups)
    uint32_t aAddr0 = smb + OFF_A + (uint32_t)((wr2 * 32 + (l & 15)) * ASTRB)
                    + (uint32_t)((l >> 4) * 16);
    uint32_t aAddr1 = aAddr0 + 16 * ASTRB;
    // B lane-invariant offset within a chunk buffer
    int bn = (l & 7) + ((l >> 4) << 3);
    uint32_t bLane = (uint32_t)((nb0 + bn) * BSTRB) + (uint32_t)(((l >> 3) & 1) * 16);

    // B staging: thread -> 64 contiguous bytes per chunk (4 x cp.async 16B)
    const int sn = tid >> 1, shf = tid & 1;
    uint32_t sdst0 = smb + OFF_B0 + (uint32_t)(sn * BSTRB + shf * 64);
    uint32_t sdst1 = smb + OFF_B1 + (uint32_t)(sn * BSTRB + shf * 64);
    const char* gbase = (const char*)(WTh + sn * FIN + shf * 32);

    float d[2][8][4];
    #pragma unroll
    for (int rg = 0; rg < 2; rg++)
        #pragma unroll
        for (int nb = 0; nb < 8; nb++)
            #pragma unroll
            for (int q = 0; q < 4; q++) d[rg][nb][q] = 0.f;

    // prologue: stage chunk 0 into B0
    #pragma unroll
    for (int q = 0; q < 4; q++) CP_ASYNC16(sdst0 + q * 16, gbase + q * 16);
    CP_COMMIT();
    CP_WAIT0();
    __syncthreads();

    for (int kc = 0; kc < NCH; kc++) {
        if (kc + 1 < NCH) {
            uint32_t sd = (kc & 1) ? sdst0 : sdst1;
            const char* gs = gbase + (kc + 1) * 128;
            #pragma unroll
            for (int q = 0; q < 4; q++) CP_ASYNC16(sd + q * 16, gs + q * 16);
            CP_COMMIT();
        }
        uint32_t bufBase = smb + ((kc & 1) ? OFF_B1 : OFF_B0) + bLane;
        #pragma unroll
        for (int kk = 0; kk < 4; kk++) {
            int k16 = kc * 4 + kk;
            uint32_t a0[4], a1[4];
            LDSM4(a0, aAddr0 + k16 * 32);
            LDSM4(a1, aAddr1 + k16 * 32);
            #pragma unroll
            for (int nt = 0; nt < 4; nt++) {
                uint32_t ba = bufBase + nt * (16 * BSTRB) + kk * 32;
                uint32_t bh4[4];
                LDSM4(bh4, ba);
                MMA16816F(d[0][2 * nt],     a0, bh4[0], bh4[1]);
                MMA16816F(d[0][2 * nt + 1], a0, bh4[2], bh4[3]);
                MMA16816F(d[1][2 * nt],     a1, bh4[0], bh4[1]);
                MMA16816F(d[1][2 * nt + 1], a1, bh4[2], bh4[3]);
            }
        }
        if (kc + 1 < NCH) CP_WAIT0();
        __syncthreads();
    }

    // ---- in-register logits from D-fragments (head = cg4) ----
    {
        float pS[2][2] = {{0.f,0.f},{0.f,0.f}};   // [row-group][row-half]
        float pD[2][2] = {{0.f,0.f},{0.f,0.f}};
        const float* as_s = (const float*)(smc + OFF_ASRC) + cg4 * 64;
        const float* ad_s = (const float*)(smc + OFF_ADST) + cg4 * 64;
        int cbase = (l & 3) * 2;
        #pragma unroll
        for (int nb = 0; nb < 8; nb++) {
            int c64 = nb * 8 + cbase;
            float2 av = *(const float2*)&as_s[c64];
            float2 dv = *(const float2*)&ad_s[c64];
            #pragma unroll
            for (int rg = 0; rg < 2; rg++) {
                pS[rg][0] = fmaf(d[rg][nb][0], av.x, fmaf(d[rg][nb][1], av.y, pS[rg][0]));
                pS[rg][1] = fmaf(d[rg][nb][2], av.x, fmaf(d[rg][nb][3], av.y, pS[rg][1]));
                pD[rg][0] = fmaf(d[rg][nb][0], dv.x, fmaf(d[rg][nb][1], dv.y, pD[rg][0]));
                pD[rg][1] = fmaf(d[rg][nb][2], dv.x, fmaf(d[rg][nb][3], dv.y, pD[rg][1]));
            }
        }
        #pragma unroll
        for (int off = 1; off <= 2; off <<= 1) {
            #pragma unroll
            for (int rg = 0; rg < 2; rg++) {
                #pragma unroll
                for (int rh = 0; rh < 2; rh++) {
                    pS[rg][rh] += __shfl_xor_sync(0xffffffffu, pS[rg][rh], off);
                    pD[rg][rh] += __shfl_xor_sync(0xffffffffu, pD[rg][rh], off);
                }
            }
        }
        if ((l & 3) == 0) {
            int n1 = l >> 2;
            float* ES = (float*)(smc + OFF_ES);
            float* ED = (float*)(smc + OFF_ED);
            #pragma unroll
            for (int rg = 0; rg < 2; rg++) {
                int u = wr2 * 2 + rg;
                ES[u * 64 + n1 * 4 + cg4]       = pS[rg][0];
                ES[u * 64 + (n1 + 8) * 4 + cg4] = pS[rg][1];
                ED[u * 64 + n1 * 4 + cg4]       = pD[rg][0];
                ED[u * 64 + (n1 + 8) * 4 + cg4] = pD[rg][1];
            }
        }
    }

    // ---- spill D -> whbuf (fp16 half2, stride WSTRH halves) ----
    {
        __half* whb = (__half*)(smc + OFF_WHB);
        int baseRow = wr2 * 32 + (l >> 2);
        int col = nb0 + (l & 3) * 2;
        #pragma unroll
        for (int rg = 0; rg < 2; rg++) {
            int r0 = baseRow + rg * 16;
            #pragma unroll
            for (int nb = 0; nb < 8; nb++) {
                int cc = col + nb * 8;
                *(__half2*)&whb[r0 * WSTRH + cc] =
                    __floats2half2_rn(d[rg][nb][0], d[rg][nb][1]);
                *(__half2*)&whb[(r0 + 8) * WSTRH + cc] =
                    __floats2half2_rn(d[rg][nb][2], d[rg][nb][3]);
            }
        }
    }
    __syncthreads();

    // ---- masked softmax: one thread per (u, i, hh); alpha in padded planes ----
    {
        int u = tid >> 6, rem = tid & 63, i = rem & 15, hh = rem >> 4;
        const float* es = (const float*)(smc + OFF_ES);
        const float* edp = (const float*)(smc + OFF_ED);
        unsigned m = adjmask(i);
        float ed = edp[u * 64 + i * 4 + hh];
        float eb[NN];
        float mx = -1e30f;
        #pragma unroll
        for (int j = 0; j < NN; j++) {
            eb[j] = -1e30f;
            if ((m >> j) & 1u) {
                float e = ed + es[u * 64 + j * 4 + hh];
                e = e > 0.f ? e : 0.2f * e;
                eb[j] = e;
                mx = fmaxf(mx, e);
            }
        }
        float ssum = 0.f;
        #pragma unroll
        for (int j = 0; j < NN; j++) {
            float a = ((m >> j) & 1u) ? __expf(eb[j] - mx) : 0.f;
            eb[j] = a;
            ssum += a;
        }
        float inv = 1.f / ssum;
        float* al = (float*)(smc + OFF_ALPHA) + u * 1040 + hh * 260 + i;
        #pragma unroll
        for (int j = 0; j < NN; j++)
            al[j * 16] = eb[j] * inv;
    }
    __syncthreads();

    // ---- aggregation: thread (ua, v) -> cols c0..c0+3, f32x2 packed ----
    int ua = tid >> 6, v = tid & 63, c0 = 4 * v, hq = v >> 4;
    ull o2[4][8];
    #pragma unroll
    for (int c = 0; c < 4; c++)
        #pragma unroll
        for (int p = 0; p < 8; p++) o2[c][p] = 0ull;
    {
        const float* au = (const float*)(smc + OFF_ALPHA) + ua * 1040 + hq * 260;
        const __half* whu = (const __half*)(smc + OFF_WHB) + ua * 16 * WSTRH;
        #pragma unroll
        for (int j = 0; j < NN; j++) {
            uint2 hv = *(const uint2*)&whu[j * WSTRH + c0];
            float2 w01 = __half22float2(*(const __half2*)&hv.x);
            float2 w23 = __half22float2(*(const __half2*)&hv.y);
            float4 a0 = *(const float4*)&au[j * 16 + 0];
            float4 a1 = *(const float4*)&au[j * 16 + 4];
            float4 a2 = *(const float4*)&au[j * 16 + 8];
            float4 a3 = *(const float4*)&au[j * 16 + 12];
            ull ap[8] = { pk(a0.x,a0.y), pk(a0.z,a0.w), pk(a1.x,a1.y), pk(a1.z,a1.w),
                          pk(a2.x,a2.y), pk(a2.z,a2.w), pk(a3.x,a3.y), pk(a3.z,a3.w) };
            ull wp0 = pk(w01.x, w01.x), wp1 = pk(w01.y, w01.y);
            ull wp2 = pk(w23.x, w23.x), wp3 = pk(w23.y, w23.y);
            #pragma unroll
            for (int p = 0; p < 8; p++) {
                ffma2(o2[0][p], ap[p], wp0);
                ffma2(o2[1][p], ap[p], wp1);
                ffma2(o2[2][p], ap[p], wp2);
                ffma2(o2[3][p], ap[p], wp3);
            }
        }
    }
    __syncthreads();   // whbuf/alpha reads done before overwriting A region

    if (FINAL) {
        float cs[4];
        #pragma unroll
        for (int c = 0; c < 4; c++) {
            float s = 0.f;
            #pragma unroll
            for (int p = 0; p < 8; p++) {
                float lo, hi; upk(o2[c][p], lo, hi);
                s += lo + hi;
            }
            cs[c] = s;
        }
        *(float4*)((float*)(smc + OFF_G4) + ua * 256 + hq * 64 + (c0 & 63)) =
            make_float4(cs[0], cs[1], cs[2], cs[3]);
        __syncthreads();
    } else {
        float4 b4 = *(const float4*)&bb[c0];
        float bbv[4] = { b4.x, b4.y, b4.z, b4.w };
        __half* ab = (__half*)(smc + OFF_A);
        #pragma unroll
        for (int p = 0; p < 8; p++) {
            float va[4], vb[4];
            #pragma unroll
            for (int c = 0; c < 4; c++) {
                upk(o2[c][p], va[c], vb[c]);
                va[c] = fmaxf(va[c] + bbv[c], 0.f);
                vb[c] = fmaxf(vb[c] + bbv[c], 0.f);
            }
            #pragma unroll
            for (int hf = 0; hf < 2; hf++) {
                const float* src = hf ? vb : va;
                int rowg = ua * 16 + 2 * p + hf;
                __half2 h01 = __floats2half2_rn(src[0], src[1]);
                __half2 h23 = __floats2half2_rn(src[2], src[3]);
                uint2 pack;
                pack.x = *(uint32_t*)&h01;
                pack.y = *(uint32_t*)&h23;
                *(uint2*)&ab[rowg * WSTRH + c0] = pack;
            }
        }
        __syncthreads();
    }
}

__global__ void __launch_bounds__(512, 1) gat_mma_kernel(
    const float* __restrict__ x,
    const float* __restrict__ w_in, const float* __restrict__ b_in,
    const float* __restrict__ as0, const float* __restrict__ ad0,
    const float* __restrict__ bb0,
    const float* __restrict__ as1, const float* __restrict__ ad1,
    const float* __restrict__ bb1,
    const float* __restrict__ as2, const float* __restrict__ ad2,
    const float* __restrict__ bb2,
    const float* __restrict__ w1, const float* __restrict__ b1,
    const float* __restrict__ lng, const float* __restrict__ lnb,
    const float* __restrict__ w2, const float* __restrict__ b2,
    float* __restrict__ out)
{
    extern __shared__ char smc[];
    uint32_t smb = smem_u32(smc);
    int tid = threadIdx.x;
    long item0 = (long)blockIdx.x * 8;

    // stage x: 8 items * 256 floats into (pre-layer0-dead) B0 region
    float* xs = (float*)(smc + OFF_XS);
    #pragma unroll
    for (int q = 0; q < 4; q++)
        xs[q * 512 + tid] = x[item0 * 256 + q * 512 + tid];
    __syncthreads();

    // input linear -> A (fp16), thread = (u = tid>>6, f = tid&63)
    {
        int u = tid >> 6, f = tid & 63;
        const float* xu = xs + u * 256;
        float acc[NN];
        #pragma unroll
        for (int nn = 0; nn < NN; nn++) acc[nn] = 0.f;
        #pragma unroll
        for (int c = 0; c < 16; c++) {
            float wv = w_in[c * 64 + f];
            #pragma unroll
            for (int nn = 0; nn < NN; nn++)
                acc[nn] = fmaf(xu[c * 16 + nn], wv, acc[nn]);
        }
        float bv = b_in[f];
        __half* ab = (__half*)(smc + OFF_A);
        #pragma unroll
        for (int nn = 0; nn < NN; nn++) {
            float vv = fmaxf(acc[nn] + bv, 0.f);
            ab[(u * 16 + nn) * WSTRH + f] = __float2half_rn(vv);
        }
    }
    __syncthreads();

    gat_layer<64,  false>(smc, smb, tid, g_WTh,         as0, ad0, bb0);
    gat_layer<256, false>(smc, smb, tid, g_WTh + 16384, as1, ad1, bb1);
    gat_layer<256, true >(smc, smb, tid, g_WTh + 81920, as2, ad2, bb2);

    // pooled g[c] = mean over nodes+heads + bb2
    {
        int u = tid >> 6, cc = tid & 63;
        const float* g4 = (const float*)(smc + OFF_G4) + u * 256;
        float sg = g4[cc] + g4[64 + cc] + g4[128 + cc] + g4[192 + cc];
        ((float*)(smc + OFF_G))[u * 64 + cc] = sg * (1.0f / 64.0f) + bb2[cc];
    }
    __syncthreads();

    // MLP1 (64->128) + LN + relu; thread covers items up, up+4
    {
        int fy = tid & 127, up = tid >> 7;
        int ua = up, ub = up + 4;
        const float* ga_ = (const float*)(smc + OFF_G) + ua * 64;
        const float* gb_ = (const float*)(smc + OFF_G) + ub * 64;
        float va = b1[fy], vb = va;
        #pragma unroll 4
        for (int c = 0; c < 64; c += 4) {
            float4 ga = *(const float4*)&ga_[c];
            float4 gb = *(const float4*)&gb_[c];
            float w0 = w1[(c + 0) * 128 + fy];
            float wA = w1[(c + 1) * 128 + fy];
            float wB = w1[(c + 2) * 128 + fy];
            float wC = w1[(c + 3) * 128 + fy];
            va = fmaf(ga.x, w0, fmaf(ga.y, wA, fmaf(ga.z, wB, fmaf(ga.w, wC, va))));
            vb = fmaf(gb.x, w0, fmaf(gb.y, wA, fmaf(gb.z, wB, fmaf(gb.w, wC, vb))));
        }
        float* red = (float*)(smc + OFF_RED);
        float sa = va, sb = vb;
        #pragma unroll
        for (int off = 16; off; off >>= 1) {
            sa += __shfl_xor_sync(0xffffffffu, sa, off);
            sb += __shfl_xor_sync(0xffffffffu, sb, off);
        }
        int wi = (tid >> 5) & 3;
        if ((tid & 31) == 0) { red[ua * 8 + wi] = sa; red[ub * 8 + wi] = sb; }
        __syncthreads();
        float mua = (red[ua * 8] + red[ua * 8 + 1] + red[ua * 8 + 2] + red[ua * 8 + 3]) * (1.f / 128.f);
        float mub = (red[ub * 8] + red[ub * 8 + 1] + red[ub * 8 + 2] + red[ub * 8 + 3]) * (1.f / 128.f);
        float da = va - mua, db = vb - mub;
        float qa = da * da, qb = db * db;
        #pragma unroll
        for (int off = 16; off; off >>= 1) {
            qa += __shfl_xor_sync(0xffffffffu, qa, off);
            qb += __shfl_xor_sync(0xffffffffu, qb, off);
        }
        if ((tid & 31) == 0) { red[ua * 8 + 4 + wi] = qa; red[ub * 8 + 4 + wi] = qb; }
        __syncthreads();
        float vara = (red[ua * 8 + 4] + red[ua * 8 + 5] + red[ua * 8 + 6] + red[ua * 8 + 7]) * (1.f / 128.f);
        float varb = (red[ub * 8 + 4] + red[ub * 8 + 5] + red[ub * 8 + 6] + red[ub * 8 + 7]) * (1.f / 128.f);
        float gv = lng[fy], bv = lnb[fy];
        float* yv = (float*)(smc + OFF_Y);
        yv[ua * 132 + fy] = fmaxf(da * rsqrtf(vara + 1e-5f) * gv + bv, 0.f);
        yv[ub * 132 + fy] = fmaxf(db * rsqrtf(varb + 1e-5f) * gv + bv, 0.f);
    }
    __syncthreads();

    // MLP2 (128->256): thread = (pr = tid>>8 -> items 4pr..4pr+3, col = tid&255)
    {
        int col = tid & 255, pr = tid >> 8;
        const float* yv = (const float*)(smc + OFF_Y) + pr * 4 * 132;
        float a0 = b2[col], a1 = a0, a2 = a0, a3 = a0;
        #pragma unroll 4
        for (int f = 0; f < 128; f += 4) {
            float4 y0 = *(const float4*)&yv[0 * 132 + f];
            float4 y1 = *(const float4*)&yv[1 * 132 + f];
            float4 y2 = *(const float4*)&yv[2 * 132 + f];
            float4 y3 = *(const float4*)&yv[3 * 132 + f];
            float w0 = w2[(f + 0) * 256 + col];
            float wA = w2[(f + 1) * 256 + col];
            float wB = w2[(f + 2) * 256 + col];
            float wC = w2[(f + 3) * 256 + col];
            a0 = fmaf(y0.x, w0, fmaf(y0.y, wA, fmaf(y0.z, wB, fmaf(y0.w, wC, a0))));
            a1 = fmaf(y1.x, w0, fmaf(y1.y, wA, fmaf(y1.z, wB, fmaf(y1.w, wC, a1))));
            a2 = fmaf(y2.x, w0, fmaf(y2.y, wA, fmaf(y2.z, wB, fmaf(y2.w, wC, a2))));
            a3 = fmaf(y3.x, w0, fmaf(y3.y, wA, fmaf(y3.z, wB, fmaf(y3.w, wC, a3))));
        }
        out[(item0 + 4 * pr + 0) * 256 + col] = a0;
        out[(item0 + 4 * pr + 1) * 256 + col] = a1;
        out[(item0 + 4 * pr + 2) * 256 + col] = a2;
        out[(item0 + 4 * pr + 3) * 256 + col] = a3;
    }
}

extern "C" void kernel_launch(void* const* d_in, const int* in_sizes, int n_in,
                              void* d_out, int out_size)
{
    const float* x    = (const float*)d_in[0];
    const float* w_in = (const float*)d_in[1];
    const float* b_in = (const float*)d_in[2];
    const float* W0   = (const float*)d_in[3];
    const float* as0  = (const float*)d_in[4];
    const float* ad0  = (const float*)d_in[5];
    const float* bb0  = (const float*)d_in[6];
    const float* W1   = (const float*)d_in[7];
    const float* as1  = (const float*)d_in[8];
    const float* ad1  = (const float*)d_in[9];
    const float* bb1  = (const float*)d_in[10];
    const float* W2   = (const float*)d_in[11];
    const float* as2  = (const float*)d_in[12];
    const float* ad2  = (const float*)d_in[13];
    const float* bb2  = (const float*)d_in[14];
    const float* w1   = (const float*)d_in[15];
    const float* b1   = (const float*)d_in[16];
    const float* lng  = (const float*)d_in[17];
    const float* lnb  = (const float*)d_in[18];
    const float* w2   = (const float*)d_in[19];
    const float* b2   = (const float*)d_in[20];
    float* out = (float*)d_out;

    int B = out_size / 256;        // 16384
    int grid = B / 8;              // 8 graphs per block

    prep_kernel<<<576, 256>>>(W0, W1, W2);

    cudaFuncSetAttribute(gat_mma_kernel,
                         cudaFuncAttributeMaxDynamicSharedMemorySize, SMEM_BYTES);
    gat_mma_kernel<<<grid, 512, SMEM_BYTES>>>(
        x, w_in, b_in,
        as0, ad0, bb0, as1, ad1, bb1, as2, ad2, bb2,
        w1, b1, lng, lnb, w2, b2, out);
}

// round 13
// speedup vs baseline: 1.9263x; 1.1785x over previous
#include <cuda_runtime.h>
#include <cuda_fp16.h>
#include <cstdint>

// Fused GAT network on mma.sync.m16n8k16 (A fp16, B fp16, fp32 accum).
// 8 graphs per 512-thread block: M = 128, N = 256, K = FIN.
// R13: aggregation also on tensor cores (alpha fp16 16x16 per (item, head)).

#define NN 16
#define WSTRH 264         // whbuf stride (halves) == A stride
#define ASTRB 528         // A row stride bytes (264 halves)
#define BSTRB 144         // B chunk row stride bytes (72 halves)

// ---- shared memory byte offsets ----
#define OFF_A     0            // fp16 A tile 128 x 264 (67584 B); whbuf overlays
#define OFF_WHB   0
#define OFF_B0    67584        // fp16 B chunk buffer 0: 256 x 72 (36864 B)
#define OFF_B1    104448       // buffer 1
#define OFF_XS    67584        // x staging (8192 B) overlays B0, pre-layer0
#define OFF_ALPHA 67584        // alpha fp16 planes: 32 x 784 B = 25088 B (overlays B0)
#define OFF_ES    104448       // 2048 B (overlays B1 after GEMM)
#define OFF_ED    106496       // 2048 B
#define OFF_ASRC  141312       // 1024 B
#define OFF_ADST  142336       // 1024 B
#define OFF_G4    143360       // 8192 B
#define OFF_G     151552       // 2048 B
#define OFF_Y     153600       // 4224 B
#define OFF_RED   157824       // 256 B
#define SMEM_BYTES 158080

// transposed fp16 weights WT[n][k]: W0 16384, W1 65536, W2 65536 elems
__device__ __align__(16) __half g_WTh[147456];

__device__ __forceinline__ uint32_t smem_u32(const void* p) {
    uint32_t a;
    asm("{ .reg .u64 t; cvta.to.shared.u64 t, %1; cvt.u32.u64 %0, t; }" : "=r"(a) : "l"(p));
    return a;
}

#define LDSM4(r, a) \
    asm volatile("ldmatrix.sync.aligned.m8n8.x4.shared.b16 {%0,%1,%2,%3}, [%4];" \
        : "=r"((r)[0]), "=r"((r)[1]), "=r"((r)[2]), "=r"((r)[3]) : "r"(a))

#define LDSM4T(r, a) \
    asm volatile("ldmatrix.sync.aligned.m8n8.x4.trans.shared.b16 {%0,%1,%2,%3}, [%4];" \
        : "=r"((r)[0]), "=r"((r)[1]), "=r"((r)[2]), "=r"((r)[3]) : "r"(a))

#define MMA16816F(d, a, b0, b1) \
    asm volatile("mma.sync.aligned.m16n8k16.row.col.f32.f16.f16.f32 " \
        "{%0,%1,%2,%3}, {%4,%5,%6,%7}, {%8,%9}, {%0,%1,%2,%3};" \
        : "+f"((d)[0]), "+f"((d)[1]), "+f"((d)[2]), "+f"((d)[3]) \
        : "r"((a)[0]), "r"((a)[1]), "r"((a)[2]), "r"((a)[3]), "r"(b0), "r"(b1))

#define CP_ASYNC16(dst, src) \
    asm volatile("cp.async.cg.shared.global [%0], [%1], 16;" :: "r"(dst), "l"(src))
#define CP_COMMIT() asm volatile("cp.async.commit_group;" ::: "memory")
#define CP_WAIT0()  asm volatile("cp.async.wait_group 0;" ::: "memory")

__device__ __forceinline__ unsigned adjmask(int i) {
    int r = i >> 2, c = i & 3;
    unsigned m = 1u << i;
    if (c > 0) m |= 1u << (i - 1);
    if (c < 3) m |= 1u << (i + 1);
    if (r > 0) m |= 1u << (i - 4);
    if (r < 3) m |= 1u << (i + 4);
    return m;
}

// ---- weight prep: transpose + fp16 ----
__global__ void prep_kernel(const float* __restrict__ W0,
                            const float* __restrict__ W1,
                            const float* __restrict__ W2) {
    int i = blockIdx.x * 256 + threadIdx.x;
    if (i >= 147456) return;
    float v;
    if (i < 16384) {                       // WT0[n*64+k] = W0[k*256+n]
        int n = i >> 6, k = i & 63;
        v = W0[k * 256 + n];
    } else if (i < 81920) {                // WT1[n*256+k] = W1[k*256+n]
        int j = i - 16384; int n = j >> 8, k = j & 255;
        v = W1[k * 256 + n];
    } else {                               // WT2
        int j = i - 81920; int n = j >> 8, k = j & 255;
        v = W2[k * 256 + n];
    }
    g_WTh[i] = __float2half_rn(v);
}

// ---- one GAT layer ----
template<int FIN, bool FINAL>
__device__ void gat_layer(char* smc, uint32_t smb, int tid,
                          const __half* __restrict__ WTh,
                          const float* __restrict__ asrc,
                          const float* __restrict__ adst,
                          const float* __restrict__ bb)
{
    const int NCH = FIN / 64;
    const int wid = tid >> 5, l = tid & 31;
    const int wr2 = wid & 3;         // row block: rows 32*wr2 .. +31 (items 2wr2, 2wr2+1)
    const int cg4 = wid >> 2;        // head / col group: cols 64*cg4 .. +63
    const int nb0 = cg4 * 64;

    // stage asrc/adst into smem (read post-mainloop; covered by loop syncs)
    if (tid < 256) ((float*)(smc + OFF_ASRC))[tid] = asrc[tid];
    else           ((float*)(smc + OFF_ADST))[tid - 256] = adst[tid - 256];

    // ldmatrix lane addresses for A (two 16-row groups)
    uint32_t aAddr0 = smb + OFF_A + (uint32_t)((wr2 * 32 + (l & 15)) * ASTRB)
                    + (uint32_t)((l >> 4) * 16);
    uint32_t aAddr1 = aAddr0 + 16 * ASTRB;
    // B lane-invariant offset within a chunk buffer
    int bn = (l & 7) + ((l >> 4) << 3);
    uint32_t bLane = (uint32_t)((nb0 + bn) * BSTRB) + (uint32_t)(((l >> 3) & 1) * 16);

    // B staging: thread -> 64 contiguous bytes per chunk (4 x cp.async 16B)
    const int sn = tid >> 1, shf = tid & 1;
    uint32_t sdst0 = smb + OFF_B0 + (uint32_t)(sn * BSTRB + shf * 64);
    uint32_t sdst1 = smb + OFF_B1 + (uint32_t)(sn * BSTRB + shf * 64);
    const char* gbase = (const char*)(WTh + sn * FIN + shf * 32);

    float d[2][8][4];
    #pragma unroll
    for (int rg = 0; rg < 2; rg++)
        #pragma unroll
        for (int nb = 0; nb < 8; nb++)
            #pragma unroll
            for (int q = 0; q < 4; q++) d[rg][nb][q] = 0.f;

    // prologue: stage chunk 0 into B0
    #pragma unroll
    for (int q = 0; q < 4; q++) CP_ASYNC16(sdst0 + q * 16, gbase + q * 16);
    CP_COMMIT();
    CP_WAIT0();
    __syncthreads();

    for (int kc = 0; kc < NCH; kc++) {
        if (kc + 1 < NCH) {
            uint32_t sd = (kc & 1) ? sdst0 : sdst1;
            const char* gs = gbase + (kc + 1) * 128;
            #pragma unroll
            for (int q = 0; q < 4; q++) CP_ASYNC16(sd + q * 16, gs + q * 16);
            CP_COMMIT();
        }
        uint32_t bufBase = smb + ((kc & 1) ? OFF_B1 : OFF_B0) + bLane;
        #pragma unroll
        for (int kk = 0; kk < 4; kk++) {
            int k16 = kc * 4 + kk;
            uint32_t a0[4], a1[4];
            LDSM4(a0, aAddr0 + k16 * 32);
            LDSM4(a1, aAddr1 + k16 * 32);
            #pragma unroll
            for (int nt = 0; nt < 4; nt++) {
                uint32_t ba = bufBase + nt * (16 * BSTRB) + kk * 32;
                uint32_t bh4[4];
                LDSM4(bh4, ba);
                MMA16816F(d[0][2 * nt],     a0, bh4[0], bh4[1]);
                MMA16816F(d[0][2 * nt + 1], a0, bh4[2], bh4[3]);
                MMA16816F(d[1][2 * nt],     a1, bh4[0], bh4[1]);
                MMA16816F(d[1][2 * nt + 1], a1, bh4[2], bh4[3]);
            }
        }
        if (kc + 1 < NCH) CP_WAIT0();
        __syncthreads();
    }

    // ---- in-register logits from D-fragments (head = cg4) ----
    {
        float pS[2][2] = {{0.f,0.f},{0.f,0.f}};   // [row-group][row-half]
        float pD[2][2] = {{0.f,0.f},{0.f,0.f}};
        const float* as_s = (const float*)(smc + OFF_ASRC) + cg4 * 64;
        const float* ad_s = (const float*)(smc + OFF_ADST) + cg4 * 64;
        int cbase = (l & 3) * 2;
        #pragma unroll
        for (int nb = 0; nb < 8; nb++) {
            int c64 = nb * 8 + cbase;
            float2 av = *(const float2*)&as_s[c64];
            float2 dv = *(const float2*)&ad_s[c64];
            #pragma unroll
            for (int rg = 0; rg < 2; rg++) {
                pS[rg][0] = fmaf(d[rg][nb][0], av.x, fmaf(d[rg][nb][1], av.y, pS[rg][0]));
                pS[rg][1] = fmaf(d[rg][nb][2], av.x, fmaf(d[rg][nb][3], av.y, pS[rg][1]));
                pD[rg][0] = fmaf(d[rg][nb][0], dv.x, fmaf(d[rg][nb][1], dv.y, pD[rg][0]));
                pD[rg][1] = fmaf(d[rg][nb][2], dv.x, fmaf(d[rg][nb][3], dv.y, pD[rg][1]));
            }
        }
        #pragma unroll
        for (int off = 1; off <= 2; off <<= 1) {
            #pragma unroll
            for (int rg = 0; rg < 2; rg++) {
                #pragma unroll
                for (int rh = 0; rh < 2; rh++) {
                    pS[rg][rh] += __shfl_xor_sync(0xffffffffu, pS[rg][rh], off);
                    pD[rg][rh] += __shfl_xor_sync(0xffffffffu, pD[rg][rh], off);
                }
            }
        }
        if ((l & 3) == 0) {
            int n1 = l >> 2;
            float* ES = (float*)(smc + OFF_ES);
            float* ED = (float*)(smc + OFF_ED);
            #pragma unroll
            for (int rg = 0; rg < 2; rg++) {
                int u = wr2 * 2 + rg;
                ES[u * 64 + n1 * 4 + cg4]       = pS[rg][0];
                ES[u * 64 + (n1 + 8) * 4 + cg4] = pS[rg][1];
                ED[u * 64 + n1 * 4 + cg4]       = pD[rg][0];
                ED[u * 64 + (n1 + 8) * 4 + cg4] = pD[rg][1];
            }
        }
    }

    // ---- spill D -> whbuf (fp16 half2, stride WSTRH halves) ----
    {
        __half* whb = (__half*)(smc + OFF_WHB);
        int baseRow = wr2 * 32 + (l >> 2);
        int col = nb0 + (l & 3) * 2;
        #pragma unroll
        for (int rg = 0; rg < 2; rg++) {
            int r0 = baseRow + rg * 16;
            #pragma unroll
            for (int nb = 0; nb < 8; nb++) {
                int cc = col + nb * 8;
                *(__half2*)&whb[r0 * WSTRH + cc] =
                    __floats2half2_rn(d[rg][nb][0], d[rg][nb][1]);
                *(__half2*)&whb[(r0 + 8) * WSTRH + cc] =
                    __floats2half2_rn(d[rg][nb][2], d[rg][nb][3]);
            }
        }
    }
    __syncthreads();

    // ---- masked softmax: one thread per (u, i, hh); alpha fp16 planes ----
    {
        int u = tid >> 6, rem = tid & 63, i = rem & 15, hh = rem >> 4;
        const float* es = (const float*)(smc + OFF_ES);
        const float* edp = (const float*)(smc + OFF_ED);
        unsigned m = adjmask(i);
        float ed = edp[u * 64 + i * 4 + hh];
        float eb[NN];
        float mx = -1e30f;
        #pragma unroll
        for (int j = 0; j < NN; j++) {
            eb[j] = -1e30f;
            if ((m >> j) & 1u) {
                float e = ed + es[u * 64 + j * 4 + hh];
                e = e > 0.f ? e : 0.2f * e;
                eb[j] = e;
                mx = fmaxf(mx, e);
            }
        }
        float ssum = 0.f;
        #pragma unroll
        for (int j = 0; j < NN; j++) {
            float a = ((m >> j) & 1u) ? __expf(eb[j] - mx) : 0.f;
            eb[j] = a;
            ssum += a;
        }
        float inv = 1.f / ssum;
        // plane p = u*4 + hh: 16 rows x 48 B (32 B data), plane stride 784 B
        __half2 hp[8];
        #pragma unroll
        for (int j2 = 0; j2 < 8; j2++)
            hp[j2] = __floats2half2_rn(eb[2 * j2] * inv, eb[2 * j2 + 1] * inv);
        char* dst = smc + OFF_ALPHA + (u * 4 + hh) * 784 + i * 48;
        uint4 w0, w1;
        w0.x = *(uint32_t*)&hp[0]; w0.y = *(uint32_t*)&hp[1];
        w0.z = *(uint32_t*)&hp[2]; w0.w = *(uint32_t*)&hp[3];
        w1.x = *(uint32_t*)&hp[4]; w1.y = *(uint32_t*)&hp[5];
        w1.z = *(uint32_t*)&hp[6]; w1.w = *(uint32_t*)&hp[7];
        *(uint4*)dst = w0;
        *(uint4*)(dst + 16) = w1;
    }
    __syncthreads();

    // ---- aggregation on tensor cores: warp handles pairs p = 2*wid, 2*wid+1 ----
    // out[u][i][c] = sum_j alpha[u,h][i][j] * wh[u][j][c]
    #pragma unroll
    for (int t = 0; t < 2; t++) {
        int p = (wid << 1) | t;
        int u = p >> 2, h = p & 3;
        uint32_t aA = smb + OFF_ALPHA
                    + (uint32_t)(p * 784 + (l & 15) * 48 + (l >> 4) * 16);
        uint32_t af[4];
        LDSM4(af, aA);
        uint32_t bbase = smb + OFF_WHB
                       + (uint32_t)((u * 16 + (l & 15)) * ASTRB)
                       + (uint32_t)((h * 64 + (l >> 4) * 8) * 2);
        uint32_t bf[4][4];
        #pragma unroll
        for (int q = 0; q < 4; q++) LDSM4T(bf[q], bbase + q * 32);
        float dd[8][4];
        #pragma unroll
        for (int nt = 0; nt < 8; nt++)
            dd[nt][0] = dd[nt][1] = dd[nt][2] = dd[nt][3] = 0.f;
        #pragma unroll
        for (int q = 0; q < 4; q++) {
            MMA16816F(dd[2 * q],     af, bf[q][0], bf[q][1]);
            MMA16816F(dd[2 * q + 1], af, bf[q][2], bf[q][3]);
        }
        if (FINAL) {
            #pragma unroll
            for (int nt = 0; nt < 8; nt++) {
                float pc0 = dd[nt][0] + dd[nt][2];
                float pc1 = dd[nt][1] + dd[nt][3];
                #pragma unroll
                for (int off = 4; off <= 16; off <<= 1) {
                    pc0 += __shfl_xor_sync(0xffffffffu, pc0, off);
                    pc1 += __shfl_xor_sync(0xffffffffu, pc1, off);
                }
                if (l < 4)
                    *(float2*)((float*)(smc + OFF_G4) + u * 256 + h * 64 + nt * 8 + l * 2)
                        = make_float2(pc0, pc1);
            }
        } else {
            __half* ab = (__half*)(smc + OFF_A);
            int r0 = u * 16 + (l >> 2);
            #pragma unroll
            for (int nt = 0; nt < 8; nt++) {
                int cn = h * 64 + nt * 8 + (l & 3) * 2;
                float2 bv = *(const float2*)&bb[cn];
                float v0 = fmaxf(dd[nt][0] + bv.x, 0.f);
                float v1 = fmaxf(dd[nt][1] + bv.y, 0.f);
                float v2 = fmaxf(dd[nt][2] + bv.x, 0.f);
                float v3 = fmaxf(dd[nt][3] + bv.y, 0.f);
                *(__half2*)&ab[r0 * WSTRH + cn]       = __floats2half2_rn(v0, v1);
                *(__half2*)&ab[(r0 + 8) * WSTRH + cn] = __floats2half2_rn(v2, v3);
            }
        }
    }
    __syncthreads();
}

__global__ void __launch_bounds__(512, 1) gat_mma_kernel(
    const float* __restrict__ x,
    const float* __restrict__ w_in, const float* __restrict__ b_in,
    const float* __restrict__ as0, const float* __restrict__ ad0,
    const float* __restrict__ bb0,
    const float* __restrict__ as1, const float* __restrict__ ad1,
    const float* __restrict__ bb1,
    const float* __restrict__ as2, const float* __restrict__ ad2,
    const float* __restrict__ bb2,
    const float* __restrict__ w1, const float* __restrict__ b1,
    const float* __restrict__ lng, const float* __restrict__ lnb,
    const float* __restrict__ w2, const float* __restrict__ b2,
    float* __restrict__ out)
{
    extern __shared__ char smc[];
    uint32_t smb = smem_u32(smc);
    int tid = threadIdx.x;
    long item0 = (long)blockIdx.x * 8;

    // stage x: 8 items * 256 floats into (pre-layer0-dead) B0 region
    float* xs = (float*)(smc + OFF_XS);
    #pragma unroll
    for (int q = 0; q < 4; q++)
        xs[q * 512 + tid] = x[item0 * 256 + q * 512 + tid];
    __syncthreads();

    // input linear -> A (fp16), thread = (u = tid>>6, f = tid&63)
    {
        int u = tid >> 6, f = tid & 63;
        const float* xu = xs + u * 256;
        float acc[NN];
        #pragma unroll
        for (int nn = 0; nn < NN; nn++) acc[nn] = 0.f;
        #pragma unroll
        for (int c = 0; c < 16; c++) {
            float wv = w_in[c * 64 + f];
            #pragma unroll
            for (int nn = 0; nn < NN; nn++)
                acc[nn] = fmaf(xu[c * 16 + nn], wv, acc[nn]);
        }
        float bv = b_in[f];
        __half* ab = (__half*)(smc + OFF_A);
        #pragma unroll
        for (int nn = 0; nn < NN; nn++) {
            float vv = fmaxf(acc[nn] + bv, 0.f);
            ab[(u * 16 + nn) * WSTRH + f] = __float2half_rn(vv);
        }
    }
    __syncthreads();

    gat_layer<64,  false>(smc, smb, tid, g_WTh,         as0, ad0, bb0);
    gat_layer<256, false>(smc, smb, tid, g_WTh + 16384, as1, ad1, bb1);
    gat_layer<256, true >(smc, smb, tid, g_WTh + 81920, as2, ad2, bb2);

    // pooled g[c] = mean over nodes+heads + bb2
    {
        int u = tid >> 6, cc = tid & 63;
        const float* g4 = (const float*)(smc + OFF_G4) + u * 256;
        float sg = g4[cc] + g4[64 + cc] + g4[128 + cc] + g4[192 + cc];
        ((float*)(smc + OFF_G))[u * 64 + cc] = sg * (1.0f / 64.0f) + bb2[cc];
    }
    __syncthreads();

    // MLP1 (64->128) + LN + relu; thread covers items up, up+4
    {
        int fy = tid & 127, up = tid >> 7;
        int ua = up, ub = up + 4;
        const float* ga_ = (const float*)(smc + OFF_G) + ua * 64;
        const float* gb_ = (const float*)(smc + OFF_G) + ub * 64;
        float va = b1[fy], vb = va;
        #pragma unroll 4
        for (int c = 0; c < 64; c += 4) {
            float4 ga = *(const float4*)&ga_[c];
            float4 gb = *(const float4*)&gb_[c];
            float w0 = w1[(c + 0) * 128 + fy];
            float wA = w1[(c + 1) * 128 + fy];
            float wB = w1[(c + 2) * 128 + fy];
            float wC = w1[(c + 3) * 128 + fy];
            va = fmaf(ga.x, w0, fmaf(ga.y, wA, fmaf(ga.z, wB, fmaf(ga.w, wC, va))));
            vb = fmaf(gb.x, w0, fmaf(gb.y, wA, fmaf(gb.z, wB, fmaf(gb.w, wC, vb))));
        }
        float* red = (float*)(smc + OFF_RED);
        float sa = va, sb = vb;
        #pragma unroll
        for (int off = 16; off; off >>= 1) {
            sa += __shfl_xor_sync(0xffffffffu, sa, off);
            sb += __shfl_xor_sync(0xffffffffu, sb, off);
        }
        int wi = (tid >> 5) & 3;
        if ((tid & 31) == 0) { red[ua * 8 + wi] = sa; red[ub * 8 + wi] = sb; }
        __syncthreads();
        float mua = (red[ua * 8] + red[ua * 8 + 1] + red[ua * 8 + 2] + red[ua * 8 + 3]) * (1.f / 128.f);
        float mub = (red[ub * 8] + red[ub * 8 + 1] + red[ub * 8 + 2] + red[ub * 8 + 3]) * (1.f / 128.f);
        float da = va - mua, db = vb - mub;
        float qa = da * da, qb = db * db;
        #pragma unroll
        for (int off = 16; off; off >>= 1) {
            qa += __shfl_xor_sync(0xffffffffu, qa, off);
            qb += __shfl_xor_sync(0xffffffffu, qb, off);
        }
        if ((tid & 31) == 0) { red[ua * 8 + 4 + wi] = qa; red[ub * 8 + 4 + wi] = qb; }
        __syncthreads();
        float vara = (red[ua * 8 + 4] + red[ua * 8 + 5] + red[ua * 8 + 6] + red[ua * 8 + 7]) * (1.f / 128.f);
        float varb = (red[ub * 8 + 4] + red[ub * 8 + 5] + red[ub * 8 + 6] + red[ub * 8 + 7]) * (1.f / 128.f);
        float gv = lng[fy], bv = lnb[fy];
        float* yv = (float*)(smc + OFF_Y);
        yv[ua * 132 + fy] = fmaxf(da * rsqrtf(vara + 1e-5f) * gv + bv, 0.f);
        yv[ub * 132 + fy] = fmaxf(db * rsqrtf(varb + 1e-5f) * gv + bv, 0.f);
    }
    __syncthreads();

    // MLP2 (128->256): thread = (pr = tid>>8 -> items 4pr..4pr+3, col = tid&255)
    {
        int col = tid & 255, pr = tid >> 8;
        const float* yv = (const float*)(smc + OFF_Y) + pr * 4 * 132;
        float a0 = b2[col], a1 = a0, a2 = a0, a3 = a0;
        #pragma unroll 4
        for (int f = 0; f < 128; f += 4) {
            float4 y0 = *(const float4*)&yv[0 * 132 + f];
            float4 y1 = *(const float4*)&yv[1 * 132 + f];
            float4 y2 = *(const float4*)&yv[2 * 132 + f];
            float4 y3 = *(const float4*)&yv[3 * 132 + f];
            float w0 = w2[(f + 0) * 256 + col];
            float wA = w2[(f + 1) * 256 + col];
            float wB = w2[(f + 2) * 256 + col];
            float wC = w2[(f + 3) * 256 + col];
            a0 = fmaf(y0.x, w0, fmaf(y0.y, wA, fmaf(y0.z, wB, fmaf(y0.w, wC, a0))));
            a1 = fmaf(y1.x, w0, fmaf(y1.y, wA, fmaf(y1.z, wB, fmaf(y1.w, wC, a1))));
            a2 = fmaf(y2.x, w0, fmaf(y2.y, wA, fmaf(y2.z, wB, fmaf(y2.w, wC, a2))));
            a3 = fmaf(y3.x, w0, fmaf(y3.y, wA, fmaf(y3.z, wB, fmaf(y3.w, wC, a3))));
        }
        out[(item0 + 4 * pr + 0) * 256 + col] = a0;
        out[(item0 + 4 * pr + 1) * 256 + col] = a1;
        out[(item0 + 4 * pr + 2) * 256 + col] = a2;
        out[(item0 + 4 * pr + 3) * 256 + col] = a3;
    }
}

extern "C" void kernel_launch(void* const* d_in, const int* in_sizes, int n_in,
                              void* d_out, int out_size)
{
    const float* x    = (const float*)d_in[0];
    const float* w_in = (const float*)d_in[1];
    const float* b_in = (const float*)d_in[2];
    const float* W0   = (const float*)d_in[3];
    const float* as0  = (const float*)d_in[4];
    const float* ad0  = (const float*)d_in[5];
    const float* bb0  = (const float*)d_in[6];
    const float* W1   = (const float*)d_in[7];
    const float* as1  = (const float*)d_in[8];
    const float* ad1  = (const float*)d_in[9];
    const float* bb1  = (const float*)d_in[10];
    const float* W2   = (const float*)d_in[11];
    const float* as2  = (const float*)d_in[12];
    const float* ad2  = (const float*)d_in[13];
    const float* bb2  = (const float*)d_in[14];
    const float* w1   = (const float*)d_in[15];
    const float* b1   = (const float*)d_in[16];
    const float* lng  = (const float*)d_in[17];
    const float* lnb  = (const float*)d_in[18];
    const float* w2   = (const float*)d_in[19];
    const float* b2   = (const float*)d_in[20];
    float* out = (float*)d_out;

    int B = out_size / 256;        // 16384
    int grid = B / 8;              // 8 graphs per block

    prep_kernel<<<576, 256>>>(W0, W1, W2);

    cudaFuncSetAttribute(gat_mma_kernel,
                         cudaFuncAttributeMaxDynamicSharedMemorySize, SMEM_BYTES);
    gat_mma_kernel<<<grid, 512, SMEM_BYTES>>>(
        x, w_in, b_in,
        as0, ad0, bb0, as1, ad1, bb1, as2, ad2, bb2,
        w1, b1, lng, lnb, w2, b2, out);
}

// round 14
// speedup vs baseline: 1.9720x; 1.0237x over previous
#include <cuda_runtime.h>
#include <cuda_fp16.h>
#include <cstdint>

// Fused GAT network on mma.sync.m16n8k16 (A fp16, B fp16, fp32 accum).
// 8 graphs per 512-thread block: M = 128, N = 256, K = FIN.
// R14: warp-local softmax (1 fewer barrier/layer) + cross-layer B chunk-0
// prefetch into the free buffer (hides staging, 1 fewer barrier/layer).

#define NN 16
#define WSTRH 264         // whbuf stride (halves) == A stride
#define ASTRB 528         // A row stride bytes (264 halves)
#define BSTRB 144         // B chunk row stride bytes (72 halves)

// ---- shared memory byte offsets ----
#define OFF_A     0            // fp16 A tile 128 x 264 (67584 B); whbuf overlays
#define OFF_WHB   0
#define OFF_B0    67584        // fp16 B chunk buffer 0: 256 x 72 (36864 B)
#define OFF_B1    104448       // buffer 1 (end 141312)
#define OFF_ALPHA 67584        // alpha fp16 planes: 32 x 784 B = 25088 B (overlays B0)
#define OFF_ASRC  141312       // 1024 B
#define OFF_ADST  142336       // 1024 B
#define OFF_WSCR  143360       // 4096 B: 16 warps x 64 floats warp-local scratch
#define OFF_G4    147456       // 8192 B (FINAL only)
#define OFF_XS    147456       // x staging 8192 B overlays G4 (pre-layer0)
#define OFF_G     155648       // 2048 B
#define OFF_Y     157696       // 4224 B
#define OFF_RED   161920       // 256 B
#define SMEM_BYTES 162176

// transposed fp16 weights WT[n][k]: W0 16384, W1 65536, W2 65536 elems
__device__ __align__(16) __half g_WTh[147456];

__device__ __forceinline__ uint32_t smem_u32(const void* p) {
    uint32_t a;
    asm("{ .reg .u64 t; cvta.to.shared.u64 t, %1; cvt.u32.u64 %0, t; }" : "=r"(a) : "l"(p));
    return a;
}

#define LDSM4(r, a) \
    asm volatile("ldmatrix.sync.aligned.m8n8.x4.shared.b16 {%0,%1,%2,%3}, [%4];" \
        : "=r"((r)[0]), "=r"((r)[1]), "=r"((r)[2]), "=r"((r)[3]) : "r"(a))

#define LDSM4T(r, a) \
    asm volatile("ldmatrix.sync.aligned.m8n8.x4.trans.shared.b16 {%0,%1,%2,%3}, [%4];" \
        : "=r"((r)[0]), "=r"((r)[1]), "=r"((r)[2]), "=r"((r)[3]) : "r"(a))

#define MMA16816F(d, a, b0, b1) \
    asm volatile("mma.sync.aligned.m16n8k16.row.col.f32.f16.f16.f32 " \
        "{%0,%1,%2,%3}, {%4,%5,%6,%7}, {%8,%9}, {%0,%1,%2,%3};" \
        : "+f"((d)[0]), "+f"((d)[1]), "+f"((d)[2]), "+f"((d)[3]) \
        : "r"((a)[0]), "r"((a)[1]), "r"((a)[2]), "r"((a)[3]), "r"(b0), "r"(b1))

#define CP_ASYNC16(dst, src) \
    asm volatile("cp.async.cg.shared.global [%0], [%1], 16;" :: "r"(dst), "l"(src))
#define CP_COMMIT() asm volatile("cp.async.commit_group;" ::: "memory")
#define CP_WAIT0()  asm volatile("cp.async.wait_group 0;" ::: "memory")

__device__ __forceinline__ unsigned adjmask(int i) {
    int r = i >> 2, c = i & 3;
    unsigned m = 1u << i;
    if (c > 0) m |= 1u << (i - 1);
    if (c < 3) m |= 1u << (i + 1);
    if (r > 0) m |= 1u << (i - 4);
    if (r < 3) m |= 1u << (i + 4);
    return m;
}

// ---- weight prep: transpose + fp16 ----
__global__ void prep_kernel(const float* __restrict__ W0,
                            const float* __restrict__ W1,
                            const float* __restrict__ W2) {
    int i = blockIdx.x * 256 + threadIdx.x;
    if (i >= 147456) return;
    float v;
    if (i < 16384) {                       // WT0[n*64+k] = W0[k*256+n]
        int n = i >> 6, k = i & 63;
        v = W0[k * 256 + n];
    } else if (i < 81920) {                // WT1[n*256+k] = W1[k*256+n]
        int j = i - 16384; int n = j >> 8, k = j & 255;
        v = W1[k * 256 + n];
    } else {                               // WT2
        int j = i - 81920; int n = j >> 8, k = j & 255;
        v = W2[k * 256 + n];
    }
    g_WTh[i] = __float2half_rn(v);
}

// stage chunk-0 of a layer's weights into a fixed buffer (64 B per thread)
__device__ __forceinline__ void prefetch_chunk0(char* smc, uint32_t smb, int tid,
                                                const __half* WT, int fin,
                                                uint32_t bufOff) {
    int sn = tid >> 1, shf = tid & 1;
    uint32_t dst = smb + bufOff + (uint32_t)(sn * BSTRB + shf * 64);
    const char* src = (const char*)(WT + sn * fin + shf * 32);
    #pragma unroll
    for (int q = 0; q < 4; q++) CP_ASYNC16(dst + q * 16, src + q * 16);
    CP_COMMIT();
}

// ---- one GAT layer ----
// START = parity of the buffer holding (prefetched) chunk 0.
template<int FIN, int START, bool FINAL>
__device__ void gat_layer(char* smc, uint32_t smb, int tid,
                          const __half* __restrict__ WTh,
                          const float* __restrict__ asrc,
                          const float* __restrict__ adst,
                          const float* __restrict__ bb,
                          const __half* __restrict__ nextWT, int nextFIN)
{
    const int NCH = FIN / 64;
    const int wid = tid >> 5, l = tid & 31;
    const int wr2 = wid & 3;         // row block: rows 32*wr2 .. +31 (items 2wr2, 2wr2+1)
    const int cg4 = wid >> 2;        // head / col group: cols 64*cg4 .. +63
    const int nb0 = cg4 * 64;

    // stage asrc/adst (read post-mainloop; entry sync orders them)
    if (tid < 256) ((float*)(smc + OFF_ASRC))[tid] = asrc[tid];
    else           ((float*)(smc + OFF_ADST))[tid - 256] = adst[tid - 256];

    // ldmatrix lane addresses for A (two 16-row groups)
    uint32_t aAddr0 = smb + OFF_A + (uint32_t)((wr2 * 32 + (l & 15)) * ASTRB)
                    + (uint32_t)((l >> 4) * 16);
    uint32_t aAddr1 = aAddr0 + 16 * ASTRB;
    int bn = (l & 7) + ((l >> 4) << 3);
    uint32_t bLane = (uint32_t)((nb0 + bn) * BSTRB) + (uint32_t)(((l >> 3) & 1) * 16);

    // B staging mapping: thread -> 64 contiguous bytes per chunk
    const int sn = tid >> 1, shf = tid & 1;
    const char* gbase = (const char*)(WTh + sn * FIN + shf * 32);
    uint32_t snoff = (uint32_t)(sn * BSTRB + shf * 64);

    float d[2][8][4];
    #pragma unroll
    for (int rg = 0; rg < 2; rg++)
        #pragma unroll
        for (int nb = 0; nb < 8; nb++)
            #pragma unroll
            for (int q = 0; q < 4; q++) d[rg][nb][q] = 0.f;

    // entry: chunk 0 was prefetched; wait own copies, then block-wide visibility
    CP_WAIT0();
    __syncthreads();

    for (int kc = 0; kc < NCH; kc++) {
        if (kc + 1 < NCH) {
            uint32_t sd = smb + ((((START + kc + 1) & 1)) ? OFF_B1 : OFF_B0) + snoff;
            const char* gs = gbase + (kc + 1) * 128;
            #pragma unroll
            for (int q = 0; q < 4; q++) CP_ASYNC16(sd + q * 16, gs + q * 16);
            CP_COMMIT();
        }
        uint32_t bufBase = smb + ((((START + kc) & 1)) ? OFF_B1 : OFF_B0) + bLane;
        #pragma unroll
        for (int kk = 0; kk < 4; kk++) {
            int k16 = kc * 4 + kk;
            uint32_t a0[4], a1[4];
            LDSM4(a0, aAddr0 + k16 * 32);
            LDSM4(a1, aAddr1 + k16 * 32);
            #pragma unroll
            for (int nt = 0; nt < 4; nt++) {
                uint32_t ba = bufBase + nt * (16 * BSTRB) + kk * 32;
                uint32_t bh4[4];
                LDSM4(bh4, ba);
                MMA16816F(d[0][2 * nt],     a0, bh4[0], bh4[1]);
                MMA16816F(d[0][2 * nt + 1], a0, bh4[2], bh4[3]);
                MMA16816F(d[1][2 * nt],     a1, bh4[0], bh4[1]);
                MMA16816F(d[1][2 * nt + 1], a1, bh4[2], bh4[3]);
            }
        }
        if (kc + 1 < NCH) CP_WAIT0();
        __syncthreads();
    }

    // ---- in-register logits from D-fragments (head = cg4) ----
    float* wsc = (float*)(smc + OFF_WSCR) + wid * 64;
    {
        float pS[2][2] = {{0.f,0.f},{0.f,0.f}};   // [row-group][row-half]
        float pD[2][2] = {{0.f,0.f},{0.f,0.f}};
        const float* as_s = (const float*)(smc + OFF_ASRC) + cg4 * 64;
        const float* ad_s = (const float*)(smc + OFF_ADST) + cg4 * 64;
        int cbase = (l & 3) * 2;
        #pragma unroll
        for (int nb = 0; nb < 8; nb++) {
            int c64 = nb * 8 + cbase;
            float2 av = *(const float2*)&as_s[c64];
            float2 dv = *(const float2*)&ad_s[c64];
            #pragma unroll
            for (int rg = 0; rg < 2; rg++) {
                pS[rg][0] = fmaf(d[rg][nb][0], av.x, fmaf(d[rg][nb][1], av.y, pS[rg][0]));
                pS[rg][1] = fmaf(d[rg][nb][2], av.x, fmaf(d[rg][nb][3], av.y, pS[rg][1]));
                pD[rg][0] = fmaf(d[rg][nb][0], dv.x, fmaf(d[rg][nb][1], dv.y, pD[rg][0]));
                pD[rg][1] = fmaf(d[rg][nb][2], dv.x, fmaf(d[rg][nb][3], dv.y, pD[rg][1]));
            }
        }
        #pragma unroll
        for (int off = 1; off <= 2; off <<= 1) {
            #pragma unroll
            for (int rg = 0; rg < 2; rg++) {
                #pragma unroll
                for (int rh = 0; rh < 2; rh++) {
                    pS[rg][rh] += __shfl_xor_sync(0xffffffffu, pS[rg][rh], off);
                    pD[rg][rh] += __shfl_xor_sync(0xffffffffu, pD[rg][rh], off);
                }
            }
        }
        // warp-private scratch: ES at [rg*32 + n], ED at [rg*32 + 16 + n]
        if ((l & 3) == 0) {
            int n1 = l >> 2;
            #pragma unroll
            for (int rg = 0; rg < 2; rg++) {
                #pragma unroll
                for (int rh = 0; rh < 2; rh++) {
                    wsc[rg * 32 + (n1 + 8 * rh)]      = pS[rg][rh];
                    wsc[rg * 32 + 16 + (n1 + 8 * rh)] = pD[rg][rh];
                }
            }
        }
    }

    // ---- spill D -> whbuf (fp16 half2) while scratch settles ----
    {
        __half* whb = (__half*)(smc + OFF_WHB);
        int baseRow = wr2 * 32 + (l >> 2);
        int col = nb0 + (l & 3) * 2;
        #pragma unroll
        for (int rg = 0; rg < 2; rg++) {
            int r0 = baseRow + rg * 16;
            #pragma unroll
            for (int nb = 0; nb < 8; nb++) {
                int cc = col + nb * 8;
                *(__half2*)&whb[r0 * WSTRH + cc] =
                    __floats2half2_rn(d[rg][nb][0], d[rg][nb][1]);
                *(__half2*)&whb[(r0 + 8) * WSTRH + cc] =
                    __floats2half2_rn(d[rg][nb][2], d[rg][nb][3]);
            }
        }
    }
    __syncwarp();

    // ---- warp-local masked softmax: lane = (uloc = l>>4, i = l&15) ----
    {
        int uloc = l >> 4, i = l & 15;
        int u = wr2 * 2 + uloc;
        float ed = wsc[uloc * 32 + 16 + i];
        unsigned m = adjmask(i);
        float eb[NN];
        float mx = -1e30f;
        #pragma unroll
        for (int j = 0; j < NN; j++) {
            eb[j] = -1e30f;
            if ((m >> j) & 1u) {
                float e = ed + wsc[uloc * 32 + j];
                e = e > 0.f ? e : 0.2f * e;
                eb[j] = e;
                mx = fmaxf(mx, e);
            }
        }
        float ssum = 0.f;
        #pragma unroll
        for (int j = 0; j < NN; j++) {
            float a = ((m >> j) & 1u) ? __expf(eb[j] - mx) : 0.f;
            eb[j] = a;
            ssum += a;
        }
        float inv = 1.f / ssum;
        __half2 hp[8];
        #pragma unroll
        for (int j2 = 0; j2 < 8; j2++)
            hp[j2] = __floats2half2_rn(eb[2 * j2] * inv, eb[2 * j2 + 1] * inv);
        char* dst = smc + OFF_ALPHA + (u * 4 + cg4) * 784 + i * 48;
        uint4 w0, w1;
        w0.x = *(uint32_t*)&hp[0]; w0.y = *(uint32_t*)&hp[1];
        w0.z = *(uint32_t*)&hp[2]; w0.w = *(uint32_t*)&hp[3];
        w1.x = *(uint32_t*)&hp[4]; w1.y = *(uint32_t*)&hp[5];
        w1.z = *(uint32_t*)&hp[6]; w1.w = *(uint32_t*)&hp[7];
        *(uint4*)dst = w0;
        *(uint4*)(dst + 16) = w1;
    }
    __syncthreads();

    // ---- aggregation on tensor cores: warp handles pairs p = 2*wid, 2*wid+1 ----
    #pragma unroll
    for (int t = 0; t < 2; t++) {
        int p = (wid << 1) | t;
        int u = p >> 2, h = p & 3;
        uint32_t aA = smb + OFF_ALPHA
                    + (uint32_t)(p * 784 + (l & 15) * 48 + (l >> 4) * 16);
        uint32_t af[4];
        LDSM4(af, aA);
        uint32_t bbase = smb + OFF_WHB
                       + (uint32_t)((u * 16 + (l & 15)) * ASTRB)
                       + (uint32_t)((h * 64 + (l >> 4) * 8) * 2);
        uint32_t bf[4][4];
        #pragma unroll
        for (int q = 0; q < 4; q++) LDSM4T(bf[q], bbase + q * 32);
        float dd[8][4];
        #pragma unroll
        for (int nt = 0; nt < 8; nt++)
            dd[nt][0] = dd[nt][1] = dd[nt][2] = dd[nt][3] = 0.f;
        #pragma unroll
        for (int q = 0; q < 4; q++) {
            MMA16816F(dd[2 * q],     af, bf[q][0], bf[q][1]);
            MMA16816F(dd[2 * q + 1], af, bf[q][2], bf[q][3]);
        }
        if (FINAL) {
            #pragma unroll
            for (int nt = 0; nt < 8; nt++) {
                float pc0 = dd[nt][0] + dd[nt][2];
                float pc1 = dd[nt][1] + dd[nt][3];
                #pragma unroll
                for (int off = 4; off <= 16; off <<= 1) {
                    pc0 += __shfl_xor_sync(0xffffffffu, pc0, off);
                    pc1 += __shfl_xor_sync(0xffffffffu, pc1, off);
                }
                if (l < 4)
                    *(float2*)((float*)(smc + OFF_G4) + u * 256 + h * 64 + nt * 8 + l * 2)
                        = make_float2(pc0, pc1);
            }
        } else {
            __half* ab = (__half*)(smc + OFF_A);
            int r0 = u * 16 + (l >> 2);
            #pragma unroll
            for (int nt = 0; nt < 8; nt++) {
                int cn = h * 64 + nt * 8 + (l & 3) * 2;
                float2 bv = *(const float2*)&bb[cn];
                float v0 = fmaxf(dd[nt][0] + bv.x, 0.f);
                float v1 = fmaxf(dd[nt][1] + bv.y, 0.f);
                float v2 = fmaxf(dd[nt][2] + bv.x, 0.f);
                float v3 = fmaxf(dd[nt][3] + bv.y, 0.f);
                *(__half2*)&ab[r0 * WSTRH + cn]       = __floats2half2_rn(v0, v1);
                *(__half2*)&ab[(r0 + 8) * WSTRH + cn] = __floats2half2_rn(v2, v3);
            }
        }
    }
    // prefetch next layer's chunk 0 into B1 (free during epilogue)
    if (!FINAL) {
        prefetch_chunk0(smc, smb, tid, nextWT, nextFIN, OFF_B1);
        // no sync: next layer's entry CP_WAIT0 + __syncthreads covers ordering
    } else {
        __syncthreads();
    }
}

__global__ void __launch_bounds__(512, 1) gat_mma_kernel(
    const float* __restrict__ x,
    const float* __restrict__ w_in, const float* __restrict__ b_in,
    const float* __restrict__ as0, const float* __restrict__ ad0,
    const float* __restrict__ bb0,
    const float* __restrict__ as1, const float* __restrict__ ad1,
    const float* __restrict__ bb1,
    const float* __restrict__ as2, const float* __restrict__ ad2,
    const float* __restrict__ bb2,
    const float* __restrict__ w1, const float* __restrict__ b1,
    const float* __restrict__ lng, const float* __restrict__ lnb,
    const float* __restrict__ w2, const float* __restrict__ b2,
    float* __restrict__ out)
{
    extern __shared__ char smc[];
    uint32_t smb = smem_u32(smc);
    int tid = threadIdx.x;
    long item0 = (long)blockIdx.x * 8;

    // prefetch layer 0's single B chunk into B0 (overlaps x load + input linear)
    prefetch_chunk0(smc, smb, tid, g_WTh, 64, OFF_B0);

    // stage x: 8 items * 256 floats into XS (overlays G4 region)
    float* xs = (float*)(smc + OFF_XS);
    #pragma unroll
    for (int q = 0; q < 4; q++)
        xs[q * 512 + tid] = x[item0 * 256 + q * 512 + tid];
    __syncthreads();

    // input linear -> A (fp16), thread = (u = tid>>6, f = tid&63)
    {
        int u = tid >> 6, f = tid & 63;
        const float* xu = xs + u * 256;
        float acc[NN];
        #pragma unroll
        for (int nn = 0; nn < NN; nn++) acc[nn] = 0.f;
        #pragma unroll
        for (int c = 0; c < 16; c++) {
            float wv = w_in[c * 64 + f];
            #pragma unroll
            for (int nn = 0; nn < NN; nn++)
                acc[nn] = fmaf(xu[c * 16 + nn], wv, acc[nn]);
        }
        float bv = b_in[f];
        __half* ab = (__half*)(smc + OFF_A);
        #pragma unroll
        for (int nn = 0; nn < NN; nn++) {
            float vv = fmaxf(acc[nn] + bv, 0.f);
            ab[(u * 16 + nn) * WSTRH + f] = __float2half_rn(vv);
        }
    }
    // no sync here: layer 0's entry CP_WAIT0 + __syncthreads orders A writes

    gat_layer<64,  0, false>(smc, smb, tid, g_WTh,         as0, ad0, bb0,
                             g_WTh + 16384, 256);
    gat_layer<256, 1, false>(smc, smb, tid, g_WTh + 16384, as1, ad1, bb1,
                             g_WTh + 81920, 256);
    gat_layer<256, 1, true >(smc, smb, tid, g_WTh + 81920, as2, ad2, bb2,
                             (const __half*)nullptr, 0);

    // pooled g[c] = mean over nodes+heads + bb2
    {
        int u = tid >> 6, cc = tid & 63;
        const float* g4 = (const float*)(smc + OFF_G4) + u * 256;
        float sg = g4[cc] + g4[64 + cc] + g4[128 + cc] + g4[192 + cc];
        ((float*)(smc + OFF_G))[u * 64 + cc] = sg * (1.0f / 64.0f) + bb2[cc];
    }
    __syncthreads();

    // MLP1 (64->128) + LN + relu; thread covers items up, up+4
    {
        int fy = tid & 127, up = tid >> 7;
        int ua = up, ub = up + 4;
        const float* ga_ = (const float*)(smc + OFF_G) + ua * 64;
        const float* gb_ = (const float*)(smc + OFF_G) + ub * 64;
        float va = b1[fy], vb = va;
        #pragma unroll 4
        for (int c = 0; c < 64; c += 4) {
            float4 ga = *(const float4*)&ga_[c];
            float4 gb = *(const float4*)&gb_[c];
            float w0 = w1[(c + 0) * 128 + fy];
            float wA = w1[(c + 1) * 128 + fy];
            float wB = w1[(c + 2) * 128 + fy];
            float wC = w1[(c + 3) * 128 + fy];
            va = fmaf(ga.x, w0, fmaf(ga.y, wA, fmaf(ga.z, wB, fmaf(ga.w, wC, va))));
            vb = fmaf(gb.x, w0, fmaf(gb.y, wA, fmaf(gb.z, wB, fmaf(gb.w, wC, vb))));
        }
        float* red = (float*)(smc + OFF_RED);
        float sa = va, sb = vb;
        #pragma unroll
        for (int off = 16; off; off >>= 1) {
            sa += __shfl_xor_sync(0xffffffffu, sa, off);
            sb += __shfl_xor_sync(0xffffffffu, sb, off);
        }
        int wi = (tid >> 5) & 3;
        if ((tid & 31) == 0) { red[ua * 8 + wi] = sa; red[ub * 8 + wi] = sb; }
        __syncthreads();
        float mua = (red[ua * 8] + red[ua * 8 + 1] + red[ua * 8 + 2] + red[ua * 8 + 3]) * (1.f / 128.f);
        float mub = (red[ub * 8] + red[ub * 8 + 1] + red[ub * 8 + 2] + red[ub * 8 + 3]) * (1.f / 128.f);
        float da = va - mua, db = vb - mub;
        float qa = da * da, qb = db * db;
        #pragma unroll
        for (int off = 16; off; off >>= 1) {
            qa += __shfl_xor_sync(0xffffffffu, qa, off);
            qb += __shfl_xor_sync(0xffffffffu, qb, off);
        }
        if ((tid & 31) == 0) { red[ua * 8 + 4 + wi] = qa; red[ub * 8 + 4 + wi] = qb; }
        __syncthreads();
        float vara = (red[ua * 8 + 4] + red[ua * 8 + 5] + red[ua * 8 + 6] + red[ua * 8 + 7]) * (1.f / 128.f);
        float varb = (red[ub * 8 + 4] + red[ub * 8 + 5] + red[ub * 8 + 6] + red[ub * 8 + 7]) * (1.f / 128.f);
        float gv = lng[fy], bv = lnb[fy];
        float* yv = (float*)(smc + OFF_Y);
        yv[ua * 132 + fy] = fmaxf(da * rsqrtf(vara + 1e-5f) * gv + bv, 0.f);
        yv[ub * 132 + fy] = fmaxf(db * rsqrtf(varb + 1e-5f) * gv + bv, 0.f);
    }
    __syncthreads();

    // MLP2 (128->256): thread = (pr = tid>>8 -> items 4pr..4pr+3, col = tid&255)
    {
        int col = tid & 255, pr = tid >> 8;
        const float* yv = (const float*)(smc + OFF_Y) + pr * 4 * 132;
        float a0 = b2[col], a1 = a0, a2 = a0, a3 = a0;
        #pragma unroll 4
        for (int f = 0; f < 128; f += 4) {
            float4 y0 = *(const float4*)&yv[0 * 132 + f];
            float4 y1 = *(const float4*)&yv[1 * 132 + f];
            float4 y2 = *(const float4*)&yv[2 * 132 + f];
            float4 y3 = *(const float4*)&yv[3 * 132 + f];
            float w0 = w2[(f + 0) * 256 + col];
            float wA = w2[(f + 1) * 256 + col];
            float wB = w2[(f + 2) * 256 + col];
            float wC = w2[(f + 3) * 256 + col];
            a0 = fmaf(y0.x, w0, fmaf(y0.y, wA, fmaf(y0.z, wB, fmaf(y0.w, wC, a0))));
            a1 = fmaf(y1.x, w0, fmaf(y1.y, wA, fmaf(y1.z, wB, fmaf(y1.w, wC, a1))));
            a2 = fmaf(y2.x, w0, fmaf(y2.y, wA, fmaf(y2.z, wB, fmaf(y2.w, wC, a2))));
            a3 = fmaf(y3.x, w0, fmaf(y3.y, wA, fmaf(y3.z, wB, fmaf(y3.w, wC, a3))));
        }
        out[(item0 + 4 * pr + 0) * 256 + col] = a0;
        out[(item0 + 4 * pr + 1) * 256 + col] = a1;
        out[(item0 + 4 * pr + 2) * 256 + col] = a2;
        out[(item0 + 4 * pr + 3) * 256 + col] = a3;
    }
}

extern "C" void kernel_launch(void* const* d_in, const int* in_sizes, int n_in,
                              void* d_out, int out_size)
{
    const float* x    = (const float*)d_in[0];
    const float* w_in = (const float*)d_in[1];
    const float* b_in = (const float*)d_in[2];
    const float* W0   = (const float*)d_in[3];
    const float* as0  = (const float*)d_in[4];
    const float* ad0  = (const float*)d_in[5];
    const float* bb0  = (const float*)d_in[6];
    const float* W1   = (const float*)d_in[7];
    const float* as1  = (const float*)d_in[8];
    const float* ad1  = (const float*)d_in[9];
    const float* bb1  = (const float*)d_in[10];
    const float* W2   = (const float*)d_in[11];
    const float* as2  = (const float*)d_in[12];
    const float* ad2  = (const float*)d_in[13];
    const float* bb2  = (const float*)d_in[14];
    const float* w1   = (const float*)d_in[15];
    const float* b1   = (const float*)d_in[16];
    const float* lng  = (const float*)d_in[17];
    const float* lnb  = (const float*)d_in[18];
    const float* w2   = (const float*)d_in[19];
    const float* b2   = (const float*)d_in[20];
    float* out = (float*)d_out;

    int B = out_size / 256;        // 16384
    int grid = B / 8;              // 8 graphs per block

    prep_kernel<<<576, 256>>>(W0, W1, W2);

    cudaFuncSetAttribute(gat_mma_kernel,
                         cudaFuncAttributeMaxDynamicSharedMemorySize, SMEM_BYTES);
    gat_mma_kernel<<<grid, 512, SMEM_BYTES>>>(
        x, w_in, b_in,
        as0, ad0, bb0, as1, ad1, bb1, as2, ad2, bb2,
        w1, b1, lng, lnb, w2, b2, out);
}

// round 15
// speedup vs baseline: 2.0327x; 1.0308x over previous
#include <cuda_runtime.h>
#include <cuda_fp16.h>
#include <cstdint>

// Fused GAT network on mma.sync.m16n8k16 (A fp16, B fp16, fp32 accum).
// 8 graphs per 512-thread block: M = 128, N = 256, K = FIN.
// R15: fully warp-local epilogue — aggregation B operand built from the
// warp's own D fragments via movmatrix (no whbuf, one fewer barrier/layer).

#define NN 16
#define ASTRB 528         // A row stride bytes (264 halves)
#define BSTRB 144         // B chunk row stride bytes (72 halves)

// ---- shared memory byte offsets ----
#define OFF_A     0            // fp16 A tile 128 x 264 (67584 B)
#define OFF_B0    67584        // fp16 B chunk buffer 0: 256 x 72 (36864 B)
#define OFF_B1    104448       // buffer 1 (end 141312)
#define OFF_ALPHA 67584        // alpha fp16 planes: 32 x 784 B = 25088 B (overlays B0)
#define OFF_ASRC  141312       // 1024 B
#define OFF_ADST  142336       // 1024 B
#define OFF_WSCR  143360       // 4096 B: 16 warps x 64 floats warp-local scratch
#define OFF_G4    147456       // 8192 B (FINAL only)
#define OFF_XS    147456       // x staging 8192 B overlays G4 (pre-layer0)
#define OFF_G     155648       // 2048 B
#define OFF_Y     157696       // 4224 B
#define OFF_RED   161920       // 256 B
#define SMEM_BYTES 162176

// transposed fp16 weights WT[n][k]: W0 16384, W1 65536, W2 65536 elems
__device__ __align__(16) __half g_WTh[147456];

__device__ __forceinline__ uint32_t smem_u32(const void* p) {
    uint32_t a;
    asm("{ .reg .u64 t; cvta.to.shared.u64 t, %1; cvt.u32.u64 %0, t; }" : "=r"(a) : "l"(p));
    return a;
}

#define LDSM4(r, a) \
    asm volatile("ldmatrix.sync.aligned.m8n8.x4.shared.b16 {%0,%1,%2,%3}, [%4];" \
        : "=r"((r)[0]), "=r"((r)[1]), "=r"((r)[2]), "=r"((r)[3]) : "r"(a))

#define MOVM(dst, src) \
    asm volatile("movmatrix.sync.aligned.m8n8.trans.b16 %0, %1;" \
        : "=r"(dst) : "r"(src))

#define MMA16816F(d, a, b0, b1) \
    asm volatile("mma.sync.aligned.m16n8k16.row.col.f32.f16.f16.f32 " \
        "{%0,%1,%2,%3}, {%4,%5,%6,%7}, {%8,%9}, {%0,%1,%2,%3};" \
        : "+f"((d)[0]), "+f"((d)[1]), "+f"((d)[2]), "+f"((d)[3]) \
        : "r"((a)[0]), "r"((a)[1]), "r"((a)[2]), "r"((a)[3]), "r"(b0), "r"(b1))

#define CP_ASYNC16(dst, src) \
    asm volatile("cp.async.cg.shared.global [%0], [%1], 16;" :: "r"(dst), "l"(src))
#define CP_COMMIT() asm volatile("cp.async.commit_group;" ::: "memory")
#define CP_WAIT0()  asm volatile("cp.async.wait_group 0;" ::: "memory")

__device__ __forceinline__ unsigned adjmask(int i) {
    int r = i >> 2, c = i & 3;
    unsigned m = 1u << i;
    if (c > 0) m |= 1u << (i - 1);
    if (c < 3) m |= 1u << (i + 1);
    if (r > 0) m |= 1u << (i - 4);
    if (r < 3) m |= 1u << (i + 4);
    return m;
}

// ---- weight prep: transpose + fp16 ----
__global__ void prep_kernel(const float* __restrict__ W0,
                            const float* __restrict__ W1,
                            const float* __restrict__ W2) {
    int i = blockIdx.x * 256 + threadIdx.x;
    if (i >= 147456) return;
    float v;
    if (i < 16384) {                       // WT0[n*64+k] = W0[k*256+n]
        int n = i >> 6, k = i & 63;
        v = W0[k * 256 + n];
    } else if (i < 81920) {                // WT1[n*256+k] = W1[k*256+n]
        int j = i - 16384; int n = j >> 8, k = j & 255;
        v = W1[k * 256 + n];
    } else {                               // WT2
        int j = i - 81920; int n = j >> 8, k = j & 255;
        v = W2[k * 256 + n];
    }
    g_WTh[i] = __float2half_rn(v);
}

// stage chunk-0 of a layer's weights into a fixed buffer (64 B per thread)
__device__ __forceinline__ void prefetch_chunk0(uint32_t smb, int tid,
                                                const __half* WT, int fin,
                                                uint32_t bufOff) {
    int sn = tid >> 1, shf = tid & 1;
    uint32_t dst = smb + bufOff + (uint32_t)(sn * BSTRB + shf * 64);
    const char* src = (const char*)(WT + sn * fin + shf * 32);
    #pragma unroll
    for (int q = 0; q < 4; q++) CP_ASYNC16(dst + q * 16, src + q * 16);
    CP_COMMIT();
}

// ---- one GAT layer ----
// START = parity of the buffer holding (prefetched) chunk 0.
template<int FIN, int START, bool FINAL>
__device__ void gat_layer(char* smc, uint32_t smb, int tid,
                          const __half* __restrict__ WTh,
                          const float* __restrict__ asrc,
                          const float* __restrict__ adst,
                          const float* __restrict__ bb,
                          const __half* __restrict__ nextWT, int nextFIN)
{
    const int NCH = FIN / 64;
    const int wid = tid >> 5, l = tid & 31;
    const int wr2 = wid & 3;         // row block: items 2wr2, 2wr2+1
    const int cg4 = wid >> 2;        // head: cols 64*cg4 .. +63
    const int nb0 = cg4 * 64;

    // ldmatrix lane addresses for A (two 16-row groups)
    uint32_t aAddr0 = smb + OFF_A + (uint32_t)((wr2 * 32 + (l & 15)) * ASTRB)
                    + (uint32_t)((l >> 4) * 16);
    uint32_t aAddr1 = aAddr0 + 16 * ASTRB;
    int bn = (l & 7) + ((l >> 4) << 3);
    uint32_t bLane = (uint32_t)((nb0 + bn) * BSTRB) + (uint32_t)(((l >> 3) & 1) * 16);

    // B staging mapping: thread -> 64 contiguous bytes per chunk
    const int sn = tid >> 1, shf = tid & 1;
    const char* gbase = (const char*)(WTh + sn * FIN + shf * 32);
    uint32_t snoff = (uint32_t)(sn * BSTRB + shf * 64);

    float d[2][8][4];
    #pragma unroll
    for (int rg = 0; rg < 2; rg++)
        #pragma unroll
        for (int nb = 0; nb < 8; nb++)
            #pragma unroll
            for (int q = 0; q < 4; q++) d[rg][nb][q] = 0.f;

    // entry: chunk 0 was prefetched; wait own copies, then block-wide visibility.
    // This sync also orders previous layer's A writeback / alpha reads.
    CP_WAIT0();
    __syncthreads();

    // stage asrc/adst AFTER entry sync (previous epilogue readers are done);
    // visibility for this layer's epilogue is ordered by the chunk syncs below.
    if (tid < 256) ((float*)(smc + OFF_ASRC))[tid] = asrc[tid];
    else           ((float*)(smc + OFF_ADST))[tid - 256] = adst[tid - 256];

    for (int kc = 0; kc < NCH; kc++) {
        if (kc + 1 < NCH) {
            uint32_t sd = smb + ((((START + kc + 1) & 1)) ? OFF_B1 : OFF_B0) + snoff;
            const char* gs = gbase + (kc + 1) * 128;
            #pragma unroll
            for (int q = 0; q < 4; q++) CP_ASYNC16(sd + q * 16, gs + q * 16);
            CP_COMMIT();
        }
        uint32_t bufBase = smb + ((((START + kc) & 1)) ? OFF_B1 : OFF_B0) + bLane;
        #pragma unroll
        for (int kk = 0; kk < 4; kk++) {
            int k16 = kc * 4 + kk;
            uint32_t a0[4], a1[4];
            LDSM4(a0, aAddr0 + k16 * 32);
            LDSM4(a1, aAddr1 + k16 * 32);
            #pragma unroll
            for (int nt = 0; nt < 4; nt++) {
                uint32_t ba = bufBase + nt * (16 * BSTRB) + kk * 32;
                uint32_t bh4[4];
                LDSM4(bh4, ba);
                MMA16816F(d[0][2 * nt],     a0, bh4[0], bh4[1]);
                MMA16816F(d[0][2 * nt + 1], a0, bh4[2], bh4[3]);
                MMA16816F(d[1][2 * nt],     a1, bh4[0], bh4[1]);
                MMA16816F(d[1][2 * nt + 1], a1, bh4[2], bh4[3]);
            }
        }
        if (kc + 1 < NCH) CP_WAIT0();
        __syncthreads();
    }

    // ---- in-register logits from D-fragments (head = cg4), warp-local ----
    float* wsc = (float*)(smc + OFF_WSCR) + wid * 64;
    {
        float pS[2][2] = {{0.f,0.f},{0.f,0.f}};   // [row-group][row-half]
        float pD[2][2] = {{0.f,0.f},{0.f,0.f}};
        const float* as_s = (const float*)(smc + OFF_ASRC) + cg4 * 64;
        const float* ad_s = (const float*)(smc + OFF_ADST) + cg4 * 64;
        int cbase = (l & 3) * 2;
        #pragma unroll
        for (int nb = 0; nb < 8; nb++) {
            int c64 = nb * 8 + cbase;
            float2 av = *(const float2*)&as_s[c64];
            float2 dv = *(const float2*)&ad_s[c64];
            #pragma unroll
            for (int rg = 0; rg < 2; rg++) {
                pS[rg][0] = fmaf(d[rg][nb][0], av.x, fmaf(d[rg][nb][1], av.y, pS[rg][0]));
                pS[rg][1] = fmaf(d[rg][nb][2], av.x, fmaf(d[rg][nb][3], av.y, pS[rg][1]));
                pD[rg][0] = fmaf(d[rg][nb][0], dv.x, fmaf(d[rg][nb][1], dv.y, pD[rg][0]));
                pD[rg][1] = fmaf(d[rg][nb][2], dv.x, fmaf(d[rg][nb][3], dv.y, pD[rg][1]));
            }
        }
        #pragma unroll
        for (int off = 1; off <= 2; off <<= 1) {
            #pragma unroll
            for (int rg = 0; rg < 2; rg++) {
                #pragma unroll
                for (int rh = 0; rh < 2; rh++) {
                    pS[rg][rh] += __shfl_xor_sync(0xffffffffu, pS[rg][rh], off);
                    pD[rg][rh] += __shfl_xor_sync(0xffffffffu, pD[rg][rh], off);
                }
            }
        }
        if ((l & 3) == 0) {
            int n1 = l >> 2;
            #pragma unroll
            for (int rg = 0; rg < 2; rg++) {
                #pragma unroll
                for (int rh = 0; rh < 2; rh++) {
                    wsc[rg * 32 + (n1 + 8 * rh)]      = pS[rg][rh];
                    wsc[rg * 32 + 16 + (n1 + 8 * rh)] = pD[rg][rh];
                }
            }
        }
    }
    __syncwarp();

    // ---- warp-local masked softmax: lane = (uloc = l>>4, i = l&15) ----
    {
        int uloc = l >> 4, i = l & 15;
        int u = wr2 * 2 + uloc;
        float ed = wsc[uloc * 32 + 16 + i];
        unsigned m = adjmask(i);
        float eb[NN];
        float mx = -1e30f;
        #pragma unroll
        for (int j = 0; j < NN; j++) {
            eb[j] = -1e30f;
            if ((m >> j) & 1u) {
                float e = ed + wsc[uloc * 32 + j];
                e = e > 0.f ? e : 0.2f * e;
                eb[j] = e;
                mx = fmaxf(mx, e);
            }
        }
        float ssum = 0.f;
        #pragma unroll
        for (int j = 0; j < NN; j++) {
            float a = ((m >> j) & 1u) ? __expf(eb[j] - mx) : 0.f;
            eb[j] = a;
            ssum += a;
        }
        float inv = 1.f / ssum;
        __half2 hp[8];
        #pragma unroll
        for (int j2 = 0; j2 < 8; j2++)
            hp[j2] = __floats2half2_rn(eb[2 * j2] * inv, eb[2 * j2 + 1] * inv);
        char* dst = smc + OFF_ALPHA + (u * 4 + cg4) * 784 + i * 48;
        uint4 w0, w1;
        w0.x = *(uint32_t*)&hp[0]; w0.y = *(uint32_t*)&hp[1];
        w0.z = *(uint32_t*)&hp[2]; w0.w = *(uint32_t*)&hp[3];
        w1.x = *(uint32_t*)&hp[4]; w1.y = *(uint32_t*)&hp[5];
        w1.z = *(uint32_t*)&hp[6]; w1.w = *(uint32_t*)&hp[7];
        *(uint4*)dst = w0;
        *(uint4*)(dst + 16) = w1;
    }
    __syncwarp();

    // ---- aggregation on tensor cores, fully warp-local ----
    // pair (u = 2wr2+rg, h = cg4): A = alpha (LDSM from warp-private plane),
    // B = wh from this warp's own D fragments via movmatrix transpose.
    #pragma unroll
    for (int rg = 0; rg < 2; rg++) {
        int u = wr2 * 2 + rg;
        uint32_t aA = smb + OFF_ALPHA
                    + (uint32_t)((u * 4 + cg4) * 784 + (l & 15) * 48 + (l >> 4) * 16);
        uint32_t af[4];
        LDSM4(af, aA);
        float ddag[8][4];
        #pragma unroll
        for (int nb = 0; nb < 8; nb++) {
            ddag[nb][0] = ddag[nb][1] = ddag[nb][2] = ddag[nb][3] = 0.f;
            __half2 h01 = __floats2half2_rn(d[rg][nb][0], d[rg][nb][1]);
            __half2 h23 = __floats2half2_rn(d[rg][nb][2], d[rg][nb][3]);
            uint32_t b0, b1;
            MOVM(b0, *(uint32_t*)&h01);
            MOVM(b1, *(uint32_t*)&h23);
            MMA16816F(ddag[nb], af, b0, b1);
        }
        if (FINAL) {
            #pragma unroll
            for (int nb = 0; nb < 8; nb++) {
                float pc0 = ddag[nb][0] + ddag[nb][2];
                float pc1 = ddag[nb][1] + ddag[nb][3];
                #pragma unroll
                for (int off = 4; off <= 16; off <<= 1) {
                    pc0 += __shfl_xor_sync(0xffffffffu, pc0, off);
                    pc1 += __shfl_xor_sync(0xffffffffu, pc1, off);
                }
                if (l < 4)
                    *(float2*)((float*)(smc + OFF_G4) + u * 256 + cg4 * 64 + nb * 8 + l * 2)
                        = make_float2(pc0, pc1);
            }
        } else {
            __half* ab = (__half*)(smc + OFF_A);
            int r0 = u * 16 + (l >> 2);
            #pragma unroll
            for (int nb = 0; nb < 8; nb++) {
                int cn = cg4 * 64 + nb * 8 + (l & 3) * 2;
                float2 bv = *(const float2*)&bb[cn];
                float v0 = fmaxf(ddag[nb][0] + bv.x, 0.f);
                float v1 = fmaxf(ddag[nb][1] + bv.y, 0.f);
                float v2 = fmaxf(ddag[nb][2] + bv.x, 0.f);
                float v3 = fmaxf(ddag[nb][3] + bv.y, 0.f);
                *(__half2*)&ab[r0 * 264 + cn]       = __floats2half2_rn(v0, v1);
                *(__half2*)&ab[(r0 + 8) * 264 + cn] = __floats2half2_rn(v2, v3);
            }
        }
    }
    // prefetch next layer's chunk 0 into B1 (free during epilogue)
    if (!FINAL) {
        prefetch_chunk0(smb, tid, nextWT, nextFIN, OFF_B1);
        // no sync: next layer's entry CP_WAIT0 + __syncthreads covers ordering
    } else {
        __syncthreads();
    }
}

__global__ void __launch_bounds__(512, 1) gat_mma_kernel(
    const float* __restrict__ x,
    const float* __restrict__ w_in, const float* __restrict__ b_in,
    const float* __restrict__ as0, const float* __restrict__ ad0,
    const float* __restrict__ bb0,
    const float* __restrict__ as1, const float* __restrict__ ad1,
    const float* __restrict__ bb1,
    const float* __restrict__ as2, const float* __restrict__ ad2,
    const float* __restrict__ bb2,
    const float* __restrict__ w1, const float* __restrict__ b1,
    const float* __restrict__ lng, const float* __restrict__ lnb,
    const float* __restrict__ w2, const float* __restrict__ b2,
    float* __restrict__ out)
{
    extern __shared__ char smc[];
    uint32_t smb = smem_u32(smc);
    int tid = threadIdx.x;
    long item0 = (long)blockIdx.x * 8;

    // prefetch layer 0's single B chunk into B0 (overlaps x load + input linear)
    prefetch_chunk0(smb, tid, g_WTh, 64, OFF_B0);

    // stage x: 8 items * 256 floats into XS (overlays G4 region)
    float* xs = (float*)(smc + OFF_XS);
    #pragma unroll
    for (int q = 0; q < 4; q++)
        xs[q * 512 + tid] = x[item0 * 256 + q * 512 + tid];
    __syncthreads();

    // input linear -> A (fp16), thread = (u = tid>>6, f = tid&63)
    {
        int u = tid >> 6, f = tid & 63;
        const float* xu = xs + u * 256;
        float acc[NN];
        #pragma unroll
        for (int nn = 0; nn < NN; nn++) acc[nn] = 0.f;
        #pragma unroll
        for (int c = 0; c < 16; c++) {
            float wv = w_in[c * 64 + f];
            #pragma unroll
            for (int nn = 0; nn < NN; nn++)
                acc[nn] = fmaf(xu[c * 16 + nn], wv, acc[nn]);
        }
        float bv = b_in[f];
        __half* ab = (__half*)(smc + OFF_A);
        #pragma unroll
        for (int nn = 0; nn < NN; nn++) {
            float vv = fmaxf(acc[nn] + bv, 0.f);
            ab[(u * 16 + nn) * 264 + f] = __float2half_rn(vv);
        }
    }
    // no sync here: layer 0's entry CP_WAIT0 + __syncthreads orders A writes

    gat_layer<64,  0, false>(smc, smb, tid, g_WTh,         as0, ad0, bb0,
                             g_WTh + 16384, 256);
    gat_layer<256, 1, false>(smc, smb, tid, g_WTh + 16384, as1, ad1, bb1,
                             g_WTh + 81920, 256);
    gat_layer<256, 1, true >(smc, smb, tid, g_WTh + 81920, as2, ad2, bb2,
                             (const __half*)nullptr, 0);

    // pooled g[c] = mean over nodes+heads + bb2
    {
        int u = tid >> 6, cc = tid & 63;
        const float* g4 = (const float*)(smc + OFF_G4) + u * 256;
        float sg = g4[cc] + g4[64 + cc] + g4[128 + cc] + g4[192 + cc];
        ((float*)(smc + OFF_G))[u * 64 + cc] = sg * (1.0f / 64.0f) + bb2[cc];
    }
    __syncthreads();

    // MLP1 (64->128) + LN + relu; thread covers items up, up+4
    {
        int fy = tid & 127, up = tid >> 7;
        int ua = up, ub = up + 4;
        const float* ga_ = (const float*)(smc + OFF_G) + ua * 64;
        const float* gb_ = (const float*)(smc + OFF_G) + ub * 64;
        float va = b1[fy], vb = va;
        #pragma unroll 4
        for (int c = 0; c < 64; c += 4) {
            float4 ga = *(const float4*)&ga_[c];
            float4 gb = *(const float4*)&gb_[c];
            float w0 = w1[(c + 0) * 128 + fy];
            float wA = w1[(c + 1) * 128 + fy];
            float wB = w1[(c + 2) * 128 + fy];
            float wC = w1[(c + 3) * 128 + fy];
            va = fmaf(ga.x, w0, fmaf(ga.y, wA, fmaf(ga.z, wB, fmaf(ga.w, wC, va))));
            vb = fmaf(gb.x, w0, fmaf(gb.y, wA, fmaf(gb.z, wB, fmaf(gb.w, wC, vb))));
        }
        float* red = (float*)(smc + OFF_RED);
        float sa = va, sb = vb;
        #pragma unroll
        for (int off = 16; off; off >>= 1) {
            sa += __shfl_xor_sync(0xffffffffu, sa, off);
            sb += __shfl_xor_sync(0xffffffffu, sb, off);
        }
        int wi = (tid >> 5) & 3;
        if ((tid & 31) == 0) { red[ua * 8 + wi] = sa; red[ub * 8 + wi] = sb; }
        __syncthreads();
        float mua = (red[ua * 8] + red[ua * 8 + 1] + red[ua * 8 + 2] + red[ua * 8 + 3]) * (1.f / 128.f);
        float mub = (red[ub * 8] + red[ub * 8 + 1] + red[ub * 8 + 2] + red[ub * 8 + 3]) * (1.f / 128.f);
        float da = va - mua, db = vb - mub;
        float qa = da * da, qb = db * db;
        #pragma unroll
        for (int off = 16; off; off >>= 1) {
            qa += __shfl_xor_sync(0xffffffffu, qa, off);
            qb += __shfl_xor_sync(0xffffffffu, qb, off);
        }
        if ((tid & 31) == 0) { red[ua * 8 + 4 + wi] = qa; red[ub * 8 + 4 + wi] = qb; }
        __syncthreads();
        float vara = (red[ua * 8 + 4] + red[ua * 8 + 5] + red[ua * 8 + 6] + red[ua * 8 + 7]) * (1.f / 128.f);
        float varb = (red[ub * 8 + 4] + red[ub * 8 + 5] + red[ub * 8 + 6] + red[ub * 8 + 7]) * (1.f / 128.f);
        float gv = lng[fy], bv = lnb[fy];
        float* yv = (float*)(smc + OFF_Y);
        yv[ua * 132 + fy] = fmaxf(da * rsqrtf(vara + 1e-5f) * gv + bv, 0.f);
        yv[ub * 132 + fy] = fmaxf(db * rsqrtf(varb + 1e-5f) * gv + bv, 0.f);
    }
    __syncthreads();

    // MLP2 (128->256): thread = (pr = tid>>8 -> items 4pr..4pr+3, col = tid&255)
    {
        int col = tid & 255, pr = tid >> 8;
        const float* yv = (const float*)(smc + OFF_Y) + pr * 4 * 132;
        float a0 = b2[col], a1 = a0, a2 = a0, a3 = a0;
        #pragma unroll 4
        for (int f = 0; f < 128; f += 4) {
            float4 y0 = *(const float4*)&yv[0 * 132 + f];
            float4 y1 = *(const float4*)&yv[1 * 132 + f];
            float4 y2 = *(const float4*)&yv[2 * 132 + f];
            float4 y3 = *(const float4*)&yv[3 * 132 + f];
            float w0 = w2[(f + 0) * 256 + col];
            float wA = w2[(f + 1) * 256 + col];
            float wB = w2[(f + 2) * 256 + col];
            float wC = w2[(f + 3) * 256 + col];
            a0 = fmaf(y0.x, w0, fmaf(y0.y, wA, fmaf(y0.z, wB, fmaf(y0.w, wC, a0))));
            a1 = fmaf(y1.x, w0, fmaf(y1.y, wA, fmaf(y1.z, wB, fmaf(y1.w, wC, a1))));
            a2 = fmaf(y2.x, w0, fmaf(y2.y, wA, fmaf(y2.z, wB, fmaf(y2.w, wC, a2))));
            a3 = fmaf(y3.x, w0, fmaf(y3.y, wA, fmaf(y3.z, wB, fmaf(y3.w, wC, a3))));
        }
        out[(item0 + 4 * pr + 0) * 256 + col] = a0;
        out[(item0 + 4 * pr + 1) * 256 + col] = a1;
        out[(item0 + 4 * pr + 2) * 256 + col] = a2;
        out[(item0 + 4 * pr + 3) * 256 + col] = a3;
    }
}

extern "C" void kernel_launch(void* const* d_in, const int* in_sizes, int n_in,
                              void* d_out, int out_size)
{
    const float* x    = (const float*)d_in[0];
    const float* w_in = (const float*)d_in[1];
    const float* b_in = (const float*)d_in[2];
    const float* W0   = (const float*)d_in[3];
    const float* as0  = (const float*)d_in[4];
    const float* ad0  = (const float*)d_in[5];
    const float* bb0  = (const float*)d_in[6];
    const float* W1   = (const float*)d_in[7];
    const float* as1  = (const float*)d_in[8];
    const float* ad1  = (const float*)d_in[9];
    const float* bb1  = (const float*)d_in[10];
    const float* W2   = (const float*)d_in[11];
    const float* as2  = (const float*)d_in[12];
    const float* ad2  = (const float*)d_in[13];
    const float* bb2  = (const float*)d_in[14];
    const float* w1   = (const float*)d_in[15];
    const float* b1   = (const float*)d_in[16];
    const float* lng  = (const float*)d_in[17];
    const float* lnb  = (const float*)d_in[18];
    const float* w2   = (const float*)d_in[19];
    const float* b2   = (const float*)d_in[20];
    float* out = (float*)d_out;

    int B = out_size / 256;        // 16384
    int grid = B / 8;              // 8 graphs per block

    prep_kernel<<<576, 256>>>(W0, W1, W2);

    cudaFuncSetAttribute(gat_mma_kernel,
                         cudaFuncAttributeMaxDynamicSharedMemorySize, SMEM_BYTES);
    gat_mma_kernel<<<grid, 512, SMEM_BYTES>>>(
        x, w_in, b_in,
        as0, ad0, bb0, as1, ad1, bb1, as2, ad2, bb2,
        w1, b1, lng, lnb, w2, b2, out);
}